// round 2
// baseline (speedup 1.0000x reference)
#include <cuda_runtime.h>
#include <math.h>

#define EMBED 1024
#define HEADS 16
#define HEAD_DIM 64
#define BATCH 4
#define SEQ 2048
#define FFDIM 4096
#define ROWS (BATCH * SEQ) /* 8192 */

// ---------------- scratch (device globals; allocation-free) ----------------
__device__ float g_h[ROWS * EMBED];   // LN1 output
__device__ float g_q[ROWS * EMBED];   // Q  [b,s,h,d]
__device__ float g_k[ROWS * EMBED];   // K
__device__ float g_v[ROWS * EMBED];   // V
__device__ float g_y[ROWS * EMBED];   // attention output (pre-Wo)
__device__ float g_x1[ROWS * EMBED];  // x + attn
__device__ float g_h2[ROWS * EMBED];  // LN2 output
__device__ float g_f[ROWS * FFDIM];   // gelu(h2 @ W1 + b1)

// ---------------- LayerNorm: one block per row ----------------
__global__ void __launch_bounds__(256) ln_kernel(const float* __restrict__ X,
                                                 const float* __restrict__ gam,
                                                 const float* __restrict__ bet,
                                                 float* __restrict__ Y) {
    int row = blockIdx.x;
    int tid = threadIdx.x;
    const float* xr = X + (size_t)row * EMBED;
    float4 v = *reinterpret_cast<const float4*>(&xr[tid * 4]);
    float s  = v.x + v.y + v.z + v.w;
    float sq = v.x * v.x + v.y * v.y + v.z * v.z + v.w * v.w;
#pragma unroll
    for (int o = 16; o; o >>= 1) {
        s  += __shfl_xor_sync(0xffffffffu, s, o);
        sq += __shfl_xor_sync(0xffffffffu, sq, o);
    }
    __shared__ float ss[8], sqs[8];
    int w = tid >> 5;
    if ((tid & 31) == 0) { ss[w] = s; sqs[w] = sq; }
    __syncthreads();
    s = 0.f; sq = 0.f;
#pragma unroll
    for (int i = 0; i < 8; i++) { s += ss[i]; sq += sqs[i]; }
    float mu  = s * (1.0f / EMBED);
    float var = sq * (1.0f / EMBED) - mu * mu;
    float inv = rsqrtf(var + 1e-5f);
    float4 gv = *reinterpret_cast<const float4*>(&gam[tid * 4]);
    float4 bv = *reinterpret_cast<const float4*>(&bet[tid * 4]);
    float4 o;
    o.x = (v.x - mu) * inv * gv.x + bv.x;
    o.y = (v.y - mu) * inv * gv.y + bv.y;
    o.z = (v.z - mu) * inv * gv.z + bv.z;
    o.w = (v.w - mu) * inv * gv.w + bv.w;
    *reinterpret_cast<float4*>(&Y[(size_t)row * EMBED + tid * 4]) = o;
}

// ---------------- GEMM: C[M,N] = A[M,K] @ W[K,N] + bias (+epilogue) --------
// EPI: 0 = bias only, 1 = bias + residual R, 2 = bias + exact GELU
__device__ __forceinline__ float gelu_exact(float x) {
    return 0.5f * x * (1.0f + erff(x * 0.70710678118654752f));
}

template <int EPI>
__global__ void __launch_bounds__(256) gemm_kernel(const float* __restrict__ A,
                                                   const float* __restrict__ W,
                                                   const float* __restrict__ bias,
                                                   const float* __restrict__ R,
                                                   float* __restrict__ C,
                                                   int M, int N, int K) {
    __shared__ float As[16][128];
    __shared__ float Bs[16][128];
    const int tid = threadIdx.x;
    const int tx = tid & 15;   // N micro index
    const int ty = tid >> 4;   // M micro index
    const int row0 = blockIdx.y * 128;
    const int col0 = blockIdx.x * 128;

    float acc[8][8];
#pragma unroll
    for (int i = 0; i < 8; i++)
#pragma unroll
        for (int j = 0; j < 8; j++) acc[i][j] = 0.f;

    for (int k0 = 0; k0 < K; k0 += 16) {
        // load A tile (128 rows x 16 k) transposed into As[k][m]
#pragma unroll
        for (int i = 0; i < 2; i++) {
            int idx = tid + i * 256;          // 0..511 float4
            int r   = idx >> 2;               // 0..127
            int kc  = (idx & 3) * 4;          // 0,4,8,12
            float4 a = *reinterpret_cast<const float4*>(
                &A[(size_t)(row0 + r) * K + k0 + kc]);
            As[kc + 0][r] = a.x;
            As[kc + 1][r] = a.y;
            As[kc + 2][r] = a.z;
            As[kc + 3][r] = a.w;
        }
        // load B tile (16 k x 128 n)
#pragma unroll
        for (int i = 0; i < 2; i++) {
            int idx = tid + i * 256;          // 0..511 float4
            int r   = idx >> 5;               // 0..15
            int c   = (idx & 31) * 4;         // 0..124
            *reinterpret_cast<float4*>(&Bs[r][c]) =
                *reinterpret_cast<const float4*>(&W[(size_t)(k0 + r) * N + col0 + c]);
        }
        __syncthreads();
#pragma unroll
        for (int k = 0; k < 16; k++) {
            float ra[8], rb[8];
            *reinterpret_cast<float4*>(&ra[0]) = *reinterpret_cast<float4*>(&As[k][ty * 8]);
            *reinterpret_cast<float4*>(&ra[4]) = *reinterpret_cast<float4*>(&As[k][ty * 8 + 4]);
            *reinterpret_cast<float4*>(&rb[0]) = *reinterpret_cast<float4*>(&Bs[k][tx * 8]);
            *reinterpret_cast<float4*>(&rb[4]) = *reinterpret_cast<float4*>(&Bs[k][tx * 8 + 4]);
#pragma unroll
            for (int i = 0; i < 8; i++)
#pragma unroll
                for (int j = 0; j < 8; j++) acc[i][j] += ra[i] * rb[j];
        }
        __syncthreads();
    }

    // epilogue
#pragma unroll
    for (int i = 0; i < 8; i++) {
        int r = row0 + ty * 8 + i;
#pragma unroll
        for (int jj = 0; jj < 2; jj++) {
            int c = col0 + tx * 8 + jj * 4;
            float4 bv = *reinterpret_cast<const float4*>(&bias[c]);
            float4 o;
            o.x = acc[i][jj * 4 + 0] + bv.x;
            o.y = acc[i][jj * 4 + 1] + bv.y;
            o.z = acc[i][jj * 4 + 2] + bv.z;
            o.w = acc[i][jj * 4 + 3] + bv.w;
            if (EPI == 1) {
                float4 rv = *reinterpret_cast<const float4*>(&R[(size_t)r * N + c]);
                o.x += rv.x; o.y += rv.y; o.z += rv.z; o.w += rv.w;
            }
            if (EPI == 2) {
                o.x = gelu_exact(o.x);
                o.y = gelu_exact(o.y);
                o.z = gelu_exact(o.z);
                o.w = gelu_exact(o.w);
            }
            *reinterpret_cast<float4*>(&C[(size_t)r * N + c]) = o;
        }
    }
}

// ---------------- causal flash attention (fp32 SIMT) ----------------------
// grid: B * HEADS * (SEQ/64) blocks, 256 threads.
// Per block: 64 q rows of one head. K-loop in tiles of 32 keys.
__global__ void __launch_bounds__(256) attn_kernel() {
    __shared__ float Qs[64][65];
    __shared__ float Ks[32][65];
    __shared__ float Vs[32][65];
    __shared__ float Ps[64][33];

    const int bt = blockIdx.x;
    const int qt = bt & 31;          // SEQ/64 = 32
    const int h  = (bt >> 5) & 15;
    const int b  = bt >> 9;
    const int q0 = qt * 64;

    const int tid = threadIdx.x;
    const int qr  = tid >> 2;        // 0..63 : q row owned
    const int g4  = tid & 3;         // 0..3  : column group
    const int dc0 = g4 * 16;         // this thread's 16 d-columns of O

    // load Q tile [64 x 64]
#pragma unroll
    for (int i = 0; i < 4; i++) {
        int idx = tid + i * 256;     // 0..1023 float4
        int r   = idx >> 4;
        int d   = (idx & 15) * 4;
        float4 qv = *reinterpret_cast<const float4*>(
            &g_q[(size_t)((b * SEQ + q0 + r)) * EMBED + h * 64 + d]);
        Qs[r][d] = qv.x; Qs[r][d + 1] = qv.y; Qs[r][d + 2] = qv.z; Qs[r][d + 3] = qv.w;
    }

    float m = -1e30f, l = 0.f;
    float o[16];
#pragma unroll
    for (int j = 0; j < 16; j++) o[j] = 0.f;

    const int ktiles = (q0 + 64) / 32;
    for (int kt = 0; kt < ktiles; kt++) {
        const int k0 = kt * 32;
        __syncthreads();  // prior-iter reads done (also Q tile visible, iter 0)
#pragma unroll
        for (int i = 0; i < 2; i++) {
            int idx = tid + i * 256;   // 0..511 float4 over 32x64
            int r   = idx >> 4;
            int d   = (idx & 15) * 4;
            size_t gidx = (size_t)((b * SEQ + k0 + r)) * EMBED + h * 64 + d;
            float4 kv = *reinterpret_cast<const float4*>(&g_k[gidx]);
            Ks[r][d] = kv.x; Ks[r][d + 1] = kv.y; Ks[r][d + 2] = kv.z; Ks[r][d + 3] = kv.w;
            float4 vv = *reinterpret_cast<const float4*>(&g_v[gidx]);
            Vs[r][d] = vv.x; Vs[r][d + 1] = vv.y; Vs[r][d + 2] = vv.z; Vs[r][d + 3] = vv.w;
        }
        __syncthreads();

        // scores: this thread computes 8 cols g4*8+j for row qr
        float s[8];
#pragma unroll
        for (int j = 0; j < 8; j++) s[j] = 0.f;
#pragma unroll
        for (int d = 0; d < 64; d++) {
            float qv = Qs[qr][d];
#pragma unroll
            for (int j = 0; j < 8; j++) s[j] += qv * Ks[g4 * 8 + j][d];
        }
        float mx = -1e30f;
#pragma unroll
        for (int j = 0; j < 8; j++) {
            int kg = k0 + g4 * 8 + j;
            s[j] = (kg <= q0 + qr) ? s[j] * 0.125f : -1e30f;
            mx = fmaxf(mx, s[j]);
        }
        // reduce over the 4 lanes owning this q row (consecutive lanes)
        mx = fmaxf(mx, __shfl_xor_sync(0xffffffffu, mx, 1));
        mx = fmaxf(mx, __shfl_xor_sync(0xffffffffu, mx, 2));
        float mnew  = fmaxf(m, mx);
        float alpha = __expf(m - mnew);
        float rl = 0.f;
#pragma unroll
        for (int j = 0; j < 8; j++) {
            float p = __expf(s[j] - mnew);
            rl += p;
            Ps[qr][g4 * 8 + j] = p;
        }
        rl += __shfl_xor_sync(0xffffffffu, rl, 1);
        rl += __shfl_xor_sync(0xffffffffu, rl, 2);
        l = l * alpha + rl;
        m = mnew;
#pragma unroll
        for (int j = 0; j < 16; j++) o[j] *= alpha;
        __syncwarp();  // Ps row written by 4 lanes of this warp
        // O += P @ V
#pragma unroll
        for (int kc = 0; kc < 32; kc++) {
            float p = Ps[qr][kc];
#pragma unroll
            for (int j = 0; j < 16; j++) o[j] += p * Vs[kc][dc0 + j];
        }
    }

    float inv = 1.0f / l;
    size_t base = (size_t)((b * SEQ + q0 + qr)) * EMBED + h * 64 + dc0;
#pragma unroll
    for (int j = 0; j < 16; j++) g_y[base + j] = o[j] * inv;
}

// ---------------- launch ---------------------------------------------------
extern "C" void kernel_launch(void* const* d_in, const int* in_sizes, int n_in,
                              void* d_out, int out_size) {
    const float* x     = (const float*)d_in[0];
    const float* Wq    = (const float*)d_in[1];
    const float* bq    = (const float*)d_in[2];
    const float* Wk    = (const float*)d_in[3];
    const float* bk    = (const float*)d_in[4];
    const float* Wv    = (const float*)d_in[5];
    const float* bv    = (const float*)d_in[6];
    const float* Wo    = (const float*)d_in[7];
    const float* bo    = (const float*)d_in[8];
    const float* g1    = (const float*)d_in[9];
    const float* beta1 = (const float*)d_in[10];
    const float* g2    = (const float*)d_in[11];
    const float* beta2 = (const float*)d_in[12];
    const float* W1    = (const float*)d_in[13];
    const float* b1    = (const float*)d_in[14];
    const float* W2    = (const float*)d_in[15];
    const float* b2    = (const float*)d_in[16];
    float* out = (float*)d_out;

    float *ph, *pq, *pk, *pv, *py, *px1, *ph2, *pf;
    cudaGetSymbolAddress((void**)&ph,  g_h);
    cudaGetSymbolAddress((void**)&pq,  g_q);
    cudaGetSymbolAddress((void**)&pk,  g_k);
    cudaGetSymbolAddress((void**)&pv,  g_v);
    cudaGetSymbolAddress((void**)&py,  g_y);
    cudaGetSymbolAddress((void**)&px1, g_x1);
    cudaGetSymbolAddress((void**)&ph2, g_h2);
    cudaGetSymbolAddress((void**)&pf,  g_f);

    dim3 blk(256);

    // LN1
    ln_kernel<<<ROWS, blk>>>(x, g1, beta1, ph);
    // QKV projections
    dim3 g1024(EMBED / 128, ROWS / 128);
    gemm_kernel<0><<<g1024, blk>>>(ph, Wq, bq, nullptr, pq, ROWS, EMBED, EMBED);
    gemm_kernel<0><<<g1024, blk>>>(ph, Wk, bk, nullptr, pk, ROWS, EMBED, EMBED);
    gemm_kernel<0><<<g1024, blk>>>(ph, Wv, bv, nullptr, pv, ROWS, EMBED, EMBED);
    // causal attention
    attn_kernel<<<BATCH * HEADS * (SEQ / 64), blk>>>();
    // x1 = x + y @ Wo + bo
    gemm_kernel<1><<<g1024, blk>>>(py, Wo, bo, x, px1, ROWS, EMBED, EMBED);
    // LN2
    ln_kernel<<<ROWS, blk>>>(px1, g2, beta2, ph2);
    // f = gelu(h2 @ W1 + b1)
    dim3 gff(FFDIM / 128, ROWS / 128);
    gemm_kernel<2><<<gff, blk>>>(ph2, W1, b1, nullptr, pf, ROWS, FFDIM, EMBED);
    // out = x1 + f @ W2 + b2
    gemm_kernel<1><<<g1024, blk>>>(pf, W2, b2, px1, out, ROWS, EMBED, FFDIM);
}

// round 7
// speedup vs baseline: 2.4022x; 2.4022x over previous
#include <cuda_runtime.h>
#include <cuda_bf16.h>
#include <math.h>
#include <stdint.h>

#define EMBED 1024
#define HEADS 16
#define HEAD_DIM 64
#define BATCH 4
#define SEQ 2048
#define FFDIM 4096
#define ROWS (BATCH * SEQ) /* 8192 */

// ---------------- scratch (device globals; allocation-free) ----------------
__device__ float g_q[ROWS * EMBED];
__device__ float g_k[ROWS * EMBED];
__device__ float g_v[ROWS * EMBED];
__device__ float g_x1[ROWS * EMBED];
__device__ __nv_bfloat16 g_h_hi[ROWS * EMBED],  g_h_lo[ROWS * EMBED];
__device__ __nv_bfloat16 g_y_hi[ROWS * EMBED],  g_y_lo[ROWS * EMBED];
__device__ __nv_bfloat16 g_h2_hi[ROWS * EMBED], g_h2_lo[ROWS * EMBED];
__device__ __nv_bfloat16 g_f_hi[ROWS * FFDIM],  g_f_lo[ROWS * FFDIM];
// pre-transposed weights [N,K] bf16 hi/lo
__device__ __nv_bfloat16 g_wq_hi[EMBED * EMBED], g_wq_lo[EMBED * EMBED];
__device__ __nv_bfloat16 g_wk_hi[EMBED * EMBED], g_wk_lo[EMBED * EMBED];
__device__ __nv_bfloat16 g_wv_hi[EMBED * EMBED], g_wv_lo[EMBED * EMBED];
__device__ __nv_bfloat16 g_wo_hi[EMBED * EMBED], g_wo_lo[EMBED * EMBED];
__device__ __nv_bfloat16 g_w1_hi[EMBED * FFDIM], g_w1_lo[EMBED * FFDIM];
__device__ __nv_bfloat16 g_w2_hi[FFDIM * EMBED], g_w2_lo[FFDIM * EMBED];

// ---------------- helpers ----------------
__device__ __forceinline__ uint32_t smem_u32(const void* p) {
    uint32_t a;
    asm("{ .reg .u64 t; cvta.to.shared.u64 t, %1; cvt.u32.u64 %0, t; }" : "=r"(a) : "l"(p));
    return a;
}
__device__ __forceinline__ void split_bf16(float x, __nv_bfloat16& h, __nv_bfloat16& l) {
    h = __float2bfloat16(x);
    l = __float2bfloat16(x - __bfloat162float(h));
}
__device__ __forceinline__ float gelu_exact(float x) {
    return 0.5f * x * (1.0f + erff(x * 0.70710678118654752f));
}

#define CP_ASYNC16(dst, src) \
    asm volatile("cp.async.cg.shared.global [%0], [%1], 16;" :: "r"(dst), "l"(src))
#define CP_COMMIT()  asm volatile("cp.async.commit_group;" ::: "memory")
#define CP_WAIT(n)   asm volatile("cp.async.wait_group %0;" :: "n"(n) : "memory")

__device__ __forceinline__ void mma_bf16(float* c, const uint32_t* a, const uint32_t* b) {
    asm volatile(
        "mma.sync.aligned.m16n8k16.row.col.f32.bf16.bf16.f32 "
        "{%0,%1,%2,%3},{%4,%5,%6,%7},{%8,%9},{%0,%1,%2,%3};"
        : "+f"(c[0]), "+f"(c[1]), "+f"(c[2]), "+f"(c[3])
        : "r"(a[0]), "r"(a[1]), "r"(a[2]), "r"(a[3]), "r"(b[0]), "r"(b[1]));
}
#define LDSM_X4(r, addr) \
    asm volatile("ldmatrix.sync.aligned.m8n8.x4.shared.b16 {%0,%1,%2,%3}, [%4];" \
                 : "=r"((r)[0]), "=r"((r)[1]), "=r"((r)[2]), "=r"((r)[3]) : "r"(addr))
#define LDSM_X2(r, addr) \
    asm volatile("ldmatrix.sync.aligned.m8n8.x2.shared.b16 {%0,%1}, [%2];" \
                 : "=r"((r)[0]), "=r"((r)[1]) : "r"(addr))

// ---------------- weight transpose + split: W[K,N] fp32 -> T[N,K] bf16 hi/lo
__global__ void __launch_bounds__(256) transpose_split(const float* __restrict__ W,
                                                       __nv_bfloat16* __restrict__ Th,
                                                       __nv_bfloat16* __restrict__ Tl,
                                                       int K, int N) {
    __shared__ float t[32][33];
    int n0 = blockIdx.x * 32, k0 = blockIdx.y * 32;
    int tx = threadIdx.x & 31, ty = threadIdx.x >> 5;
#pragma unroll
    for (int i = 0; i < 4; i++) {
        int k = ty + i * 8;
        t[k][tx] = W[(size_t)(k0 + k) * N + n0 + tx];
    }
    __syncthreads();
#pragma unroll
    for (int i = 0; i < 4; i++) {
        int r = ty + i * 8;  // n-index
        float v = t[tx][r];
        __nv_bfloat16 h, l;
        split_bf16(v, h, l);
        Th[(size_t)(n0 + r) * K + k0 + tx] = h;
        Tl[(size_t)(n0 + r) * K + k0 + tx] = l;
    }
}

// ---------------- LayerNorm: one block per row, bf16 hi/lo output ----------
__global__ void __launch_bounds__(256) ln_kernel(const float* __restrict__ X,
                                                 const float* __restrict__ gam,
                                                 const float* __restrict__ bet,
                                                 __nv_bfloat16* __restrict__ Yh,
                                                 __nv_bfloat16* __restrict__ Yl) {
    int row = blockIdx.x;
    int tid = threadIdx.x;
    const float* xr = X + (size_t)row * EMBED;
    float4 v = *reinterpret_cast<const float4*>(&xr[tid * 4]);
    float s  = v.x + v.y + v.z + v.w;
    float sq = v.x * v.x + v.y * v.y + v.z * v.z + v.w * v.w;
#pragma unroll
    for (int o = 16; o; o >>= 1) {
        s  += __shfl_xor_sync(0xffffffffu, s, o);
        sq += __shfl_xor_sync(0xffffffffu, sq, o);
    }
    __shared__ float ss[8], sqs[8];
    int w = tid >> 5;
    if ((tid & 31) == 0) { ss[w] = s; sqs[w] = sq; }
    __syncthreads();
    s = 0.f; sq = 0.f;
#pragma unroll
    for (int i = 0; i < 8; i++) { s += ss[i]; sq += sqs[i]; }
    float mu  = s * (1.0f / EMBED);
    float var = sq * (1.0f / EMBED) - mu * mu;
    float inv = rsqrtf(var + 1e-5f);
    float4 gv = *reinterpret_cast<const float4*>(&gam[tid * 4]);
    float4 bv = *reinterpret_cast<const float4*>(&bet[tid * 4]);
    float o0 = (v.x - mu) * inv * gv.x + bv.x;
    float o1 = (v.y - mu) * inv * gv.y + bv.y;
    float o2 = (v.z - mu) * inv * gv.z + bv.z;
    float o3 = (v.w - mu) * inv * gv.w + bv.w;
    size_t base = (size_t)row * EMBED + tid * 4;
    __nv_bfloat16 h0, l0, h1, l1, h2, l2, h3, l3;
    split_bf16(o0, h0, l0); split_bf16(o1, h1, l1);
    split_bf16(o2, h2, l2); split_bf16(o3, h3, l3);
    __nv_bfloat162 ph0; ph0.x = h0; ph0.y = h1;
    __nv_bfloat162 ph1; ph1.x = h2; ph1.y = h3;
    __nv_bfloat162 pl0; pl0.x = l0; pl0.y = l1;
    __nv_bfloat162 pl1; pl1.x = l2; pl1.y = l3;
    *reinterpret_cast<__nv_bfloat162*>(&Yh[base])     = ph0;
    *reinterpret_cast<__nv_bfloat162*>(&Yh[base + 2]) = ph1;
    *reinterpret_cast<__nv_bfloat162*>(&Yl[base])     = pl0;
    *reinterpret_cast<__nv_bfloat162*>(&Yl[base + 2]) = pl1;
}

// ---------------- mma.sync GEMM: C[M,N] = A@B^T, split-bf16 fp32 emulation -
// A: [M,K] bf16 hi/lo row-major.  B: [N,K] bf16 hi/lo row-major.
// CTA tile 128x128, K-chunk 32, 8 warps (2M x 4N), warp tile 64x32.
// smem per stage: Ah(0) Al(10240) Bh(20480) Bl(30720), row stride 40 halves (80B).
// EPI: 0=bias  1=bias+residual  2=bias+GELU.  WB: bf16 hi/lo out.  WF: fp32 out.
static constexpr int GEMM_SMEM = 81920;  // 2 stages x 40960B

template <int EPI, int WB, int WF>
__device__ __forceinline__ void epi_store(float v0, float v1, int r, int c,
                                          const float* R, float* C,
                                          __nv_bfloat16* Ch, __nv_bfloat16* Cl, int N) {
    size_t off = (size_t)r * N + c;
    if (EPI == 1) { float2 rr = *reinterpret_cast<const float2*>(&R[off]); v0 += rr.x; v1 += rr.y; }
    if (EPI == 2) { v0 = gelu_exact(v0); v1 = gelu_exact(v1); }
    if (WF) { float2 o; o.x = v0; o.y = v1; *reinterpret_cast<float2*>(&C[off]) = o; }
    if (WB) {
        __nv_bfloat16 h0, l0, h1, l1;
        split_bf16(v0, h0, l0); split_bf16(v1, h1, l1);
        __nv_bfloat162 ph; ph.x = h0; ph.y = h1;
        __nv_bfloat162 pl; pl.x = l0; pl.y = l1;
        *reinterpret_cast<__nv_bfloat162*>(&Ch[off]) = ph;
        *reinterpret_cast<__nv_bfloat162*>(&Cl[off]) = pl;
    }
}

__device__ __forceinline__ void gemm_load_stage(
    uint32_t smem_base, int stage,
    const __nv_bfloat16* Ah, const __nv_bfloat16* Al,
    const __nv_bfloat16* Bh, const __nv_bfloat16* Bl,
    int row0, int col0, int K, int k0, int tid) {
    uint32_t sb = smem_base + (uint32_t)stage * 40960u;
#pragma unroll
    for (int i = 0; i < 8; i++) {
        int idx = i * 256 + tid;        // 0..2047
        int arr = idx >> 9;             // 0..3
        int pos = idx & 511;
        int r   = pos >> 2;             // 0..127
        int c8  = pos & 3;              // 16B chunk (8 halves)
        uint32_t dst = sb + (uint32_t)(arr * 10240 + r * 80 + c8 * 16);
        const __nv_bfloat16* src;
        if (arr == 0)      src = &Ah[(size_t)(row0 + r) * K + k0 + c8 * 8];
        else if (arr == 1) src = &Al[(size_t)(row0 + r) * K + k0 + c8 * 8];
        else if (arr == 2) src = &Bh[(size_t)(col0 + r) * K + k0 + c8 * 8];
        else               src = &Bl[(size_t)(col0 + r) * K + k0 + c8 * 8];
        CP_ASYNC16(dst, src);
    }
}

template <int EPI, int WB, int WF>
__global__ void __launch_bounds__(256) gemm_mma(
    const __nv_bfloat16* __restrict__ Ah, const __nv_bfloat16* __restrict__ Al,
    const __nv_bfloat16* __restrict__ Bh, const __nv_bfloat16* __restrict__ Bl,
    const float* __restrict__ bias, const float* __restrict__ R,
    float* __restrict__ C, __nv_bfloat16* __restrict__ Ch, __nv_bfloat16* __restrict__ Cl,
    int M, int N, int K) {
    extern __shared__ char dsm[];
    const int tid  = threadIdx.x;
    const int lane = tid & 31;
    const int wid  = tid >> 5;
    const int wm   = wid & 1;       // 0..1 -> M offset 0/64
    const int wn   = wid >> 1;      // 0..3 -> N offset 0/32/64/96
    const int row0 = blockIdx.y * 128;
    const int col0 = blockIdx.x * 128;
    const uint32_t smem_base = smem_u32(dsm);

    float acc[4][4][4];
#pragma unroll
    for (int i = 0; i < 4; i++)
#pragma unroll
        for (int j = 0; j < 4; j++)
#pragma unroll
            for (int k = 0; k < 4; k++) acc[i][j][k] = 0.f;

    const int nchunks = K >> 5;
    // prologue: stage 0
    gemm_load_stage(smem_base, 0, Ah, Al, Bh, Bl, row0, col0, K, 0, tid);
    CP_COMMIT();

    for (int c = 0; c < nchunks; c++) {
        if (c + 1 < nchunks) {
            gemm_load_stage(smem_base, (c + 1) & 1, Ah, Al, Bh, Bl, row0, col0, K, (c + 1) << 5, tid);
            CP_COMMIT();
            CP_WAIT(1);
        } else {
            CP_WAIT(0);
        }
        __syncthreads();

        uint32_t sb = smem_base + (uint32_t)(c & 1) * 40960u;
#pragma unroll
        for (int ks = 0; ks < 32; ks += 16) {
            // B fragments (4 n8 tiles), hi & lo
            uint32_t bh[4][2], bl[4][2];
            int l2 = lane & 15;
            int rb_off = l2 & 7;
            int kb_off = ks + ((l2 >> 3) << 3);
#pragma unroll
            for (int nt = 0; nt < 4; nt++) {
                int rowb = wn * 32 + nt * 8 + rb_off;
                uint32_t ab = sb + 20480u + (uint32_t)(rowb * 80 + kb_off * 2);
                LDSM_X2(bh[nt], ab);
                LDSM_X2(bl[nt], ab + 10240u);
            }
            int ra_off = (lane & 7) + ((lane >> 3) & 1) * 8;
            int ka_off = ks + ((lane >> 4) << 3);
#pragma unroll
            for (int mt = 0; mt < 4; mt++) {
                int rowa = wm * 64 + mt * 16 + ra_off;
                uint32_t aa = sb + (uint32_t)(rowa * 80 + ka_off * 2);
                uint32_t ah[4], al[4];
                LDSM_X4(ah, aa);
                LDSM_X4(al, aa + 10240u);
#pragma unroll
                for (int nt = 0; nt < 4; nt++) {
                    mma_bf16(acc[mt][nt], ah, bh[nt]);
                    mma_bf16(acc[mt][nt], ah, bl[nt]);
                    mma_bf16(acc[mt][nt], al, bh[nt]);
                }
            }
        }
        __syncthreads();
    }

    // epilogue: direct fragment stores
#pragma unroll
    for (int mt = 0; mt < 4; mt++) {
#pragma unroll
        for (int nt = 0; nt < 4; nt++) {
            int rg = row0 + wm * 64 + mt * 16 + (lane >> 2);
            int cg = col0 + wn * 32 + nt * 8 + (lane & 3) * 2;
            float2 b2 = *reinterpret_cast<const float2*>(&bias[cg]);
            epi_store<EPI, WB, WF>(acc[mt][nt][0] + b2.x, acc[mt][nt][1] + b2.y,
                                   rg, cg, R, C, Ch, Cl, N);
            epi_store<EPI, WB, WF>(acc[mt][nt][2] + b2.x, acc[mt][nt][3] + b2.y,
                                   rg + 8, cg, R, C, Ch, Cl, N);
        }
    }
}

// ---------------- causal flash attention (fp32 SIMT) ----------------------
__global__ void __launch_bounds__(256) attn_kernel() {
    __shared__ float Qs[64][65];
    __shared__ float Ks[32][65];
    __shared__ float Vs[32][65];
    __shared__ float Ps[64][33];

    const int bt = blockIdx.x;
    const int qt = bt & 31;
    const int h  = (bt >> 5) & 15;
    const int b  = bt >> 9;
    const int q0 = qt * 64;

    const int tid = threadIdx.x;
    const int qr  = tid >> 2;
    const int g4  = tid & 3;
    const int dc0 = g4 * 16;

#pragma unroll
    for (int i = 0; i < 4; i++) {
        int idx = tid + i * 256;
        int r   = idx >> 4;
        int d   = (idx & 15) * 4;
        float4 qv = *reinterpret_cast<const float4*>(
            &g_q[(size_t)((b * SEQ + q0 + r)) * EMBED + h * 64 + d]);
        Qs[r][d] = qv.x; Qs[r][d + 1] = qv.y; Qs[r][d + 2] = qv.z; Qs[r][d + 3] = qv.w;
    }

    float m = -1e30f, l = 0.f;
    float o[16];
#pragma unroll
    for (int j = 0; j < 16; j++) o[j] = 0.f;

    const int ktiles = (q0 + 64) / 32;
    for (int kt = 0; kt < ktiles; kt++) {
        const int k0 = kt * 32;
        __syncthreads();
#pragma unroll
        for (int i = 0; i < 2; i++) {
            int idx = tid + i * 256;
            int r   = idx >> 4;
            int d   = (idx & 15) * 4;
            size_t gidx = (size_t)((b * SEQ + k0 + r)) * EMBED + h * 64 + d;
            float4 kv = *reinterpret_cast<const float4*>(&g_k[gidx]);
            Ks[r][d] = kv.x; Ks[r][d + 1] = kv.y; Ks[r][d + 2] = kv.z; Ks[r][d + 3] = kv.w;
            float4 vv = *reinterpret_cast<const float4*>(&g_v[gidx]);
            Vs[r][d] = vv.x; Vs[r][d + 1] = vv.y; Vs[r][d + 2] = vv.z; Vs[r][d + 3] = vv.w;
        }
        __syncthreads();

        float s[8];
#pragma unroll
        for (int j = 0; j < 8; j++) s[j] = 0.f;
#pragma unroll
        for (int d = 0; d < 64; d++) {
            float qv = Qs[qr][d];
#pragma unroll
            for (int j = 0; j < 8; j++) s[j] += qv * Ks[g4 * 8 + j][d];
        }
        float mx = -1e30f;
#pragma unroll
        for (int j = 0; j < 8; j++) {
            int kg = k0 + g4 * 8 + j;
            s[j] = (kg <= q0 + qr) ? s[j] * 0.125f : -1e30f;
            mx = fmaxf(mx, s[j]);
        }
        mx = fmaxf(mx, __shfl_xor_sync(0xffffffffu, mx, 1));
        mx = fmaxf(mx, __shfl_xor_sync(0xffffffffu, mx, 2));
        float mnew  = fmaxf(m, mx);
        float alpha = __expf(m - mnew);
        float rl = 0.f;
#pragma unroll
        for (int j = 0; j < 8; j++) {
            float p = __expf(s[j] - mnew);
            rl += p;
            Ps[qr][g4 * 8 + j] = p;
        }
        rl += __shfl_xor_sync(0xffffffffu, rl, 1);
        rl += __shfl_xor_sync(0xffffffffu, rl, 2);
        l = l * alpha + rl;
        m = mnew;
#pragma unroll
        for (int j = 0; j < 16; j++) o[j] *= alpha;
        __syncwarp();
#pragma unroll
        for (int kc = 0; kc < 32; kc++) {
            float p = Ps[qr][kc];
#pragma unroll
            for (int j = 0; j < 16; j++) o[j] += p * Vs[kc][dc0 + j];
        }
    }

    float inv = 1.0f / l;
    size_t base = (size_t)((b * SEQ + q0 + qr)) * EMBED + h * 64 + dc0;
#pragma unroll
    for (int j = 0; j < 16; j++) {
        float val = o[j] * inv;
        __nv_bfloat16 hh, ll;
        split_bf16(val, hh, ll);
        g_y_hi[base + j] = hh;
        g_y_lo[base + j] = ll;
    }
}

// ---------------- launch ---------------------------------------------------
extern "C" void kernel_launch(void* const* d_in, const int* in_sizes, int n_in,
                              void* d_out, int out_size) {
    const float* x     = (const float*)d_in[0];
    const float* Wq    = (const float*)d_in[1];
    const float* bq    = (const float*)d_in[2];
    const float* Wk    = (const float*)d_in[3];
    const float* bk    = (const float*)d_in[4];
    const float* Wv    = (const float*)d_in[5];
    const float* bv    = (const float*)d_in[6];
    const float* Wo    = (const float*)d_in[7];
    const float* bo    = (const float*)d_in[8];
    const float* g1    = (const float*)d_in[9];
    const float* beta1 = (const float*)d_in[10];
    const float* g2    = (const float*)d_in[11];
    const float* beta2 = (const float*)d_in[12];
    const float* W1    = (const float*)d_in[13];
    const float* b1    = (const float*)d_in[14];
    const float* W2    = (const float*)d_in[15];
    const float* b2    = (const float*)d_in[16];
    float* out = (float*)d_out;

    float *pq, *pk, *pv, *px1;
    cudaGetSymbolAddress((void**)&pq,  g_q);
    cudaGetSymbolAddress((void**)&pk,  g_k);
    cudaGetSymbolAddress((void**)&pv,  g_v);
    cudaGetSymbolAddress((void**)&px1, g_x1);
    __nv_bfloat16 *phh, *phl, *pyh, *pyl, *ph2h, *ph2l, *pfh, *pfl;
    cudaGetSymbolAddress((void**)&phh,  g_h_hi);  cudaGetSymbolAddress((void**)&phl,  g_h_lo);
    cudaGetSymbolAddress((void**)&pyh,  g_y_hi);  cudaGetSymbolAddress((void**)&pyl,  g_y_lo);
    cudaGetSymbolAddress((void**)&ph2h, g_h2_hi); cudaGetSymbolAddress((void**)&ph2l, g_h2_lo);
    cudaGetSymbolAddress((void**)&pfh,  g_f_hi);  cudaGetSymbolAddress((void**)&pfl,  g_f_lo);
    __nv_bfloat16 *wqh, *wql, *wkh, *wkl, *wvh, *wvl, *woh, *wol, *w1h, *w1l, *w2h, *w2l;
    cudaGetSymbolAddress((void**)&wqh, g_wq_hi); cudaGetSymbolAddress((void**)&wql, g_wq_lo);
    cudaGetSymbolAddress((void**)&wkh, g_wk_hi); cudaGetSymbolAddress((void**)&wkl, g_wk_lo);
    cudaGetSymbolAddress((void**)&wvh, g_wv_hi); cudaGetSymbolAddress((void**)&wvl, g_wv_lo);
    cudaGetSymbolAddress((void**)&woh, g_wo_hi); cudaGetSymbolAddress((void**)&wol, g_wo_lo);
    cudaGetSymbolAddress((void**)&w1h, g_w1_hi); cudaGetSymbolAddress((void**)&w1l, g_w1_lo);
    cudaGetSymbolAddress((void**)&w2h, g_w2_hi); cudaGetSymbolAddress((void**)&w2l, g_w2_lo);

    cudaFuncSetAttribute(gemm_mma<0, 0, 1>, cudaFuncAttributeMaxDynamicSharedMemorySize, GEMM_SMEM);
    cudaFuncSetAttribute(gemm_mma<1, 0, 1>, cudaFuncAttributeMaxDynamicSharedMemorySize, GEMM_SMEM);
    cudaFuncSetAttribute(gemm_mma<2, 1, 0>, cudaFuncAttributeMaxDynamicSharedMemorySize, GEMM_SMEM);

    dim3 t256(256);
    // weight prep (transpose + bf16 split)
    transpose_split<<<dim3(EMBED / 32, EMBED / 32), t256>>>(Wq, wqh, wql, EMBED, EMBED);
    transpose_split<<<dim3(EMBED / 32, EMBED / 32), t256>>>(Wk, wkh, wkl, EMBED, EMBED);
    transpose_split<<<dim3(EMBED / 32, EMBED / 32), t256>>>(Wv, wvh, wvl, EMBED, EMBED);
    transpose_split<<<dim3(EMBED / 32, EMBED / 32), t256>>>(Wo, woh, wol, EMBED, EMBED);
    transpose_split<<<dim3(FFDIM / 32, EMBED / 32), t256>>>(W1, w1h, w1l, EMBED, FFDIM);
    transpose_split<<<dim3(EMBED / 32, FFDIM / 32), t256>>>(W2, w2h, w2l, FFDIM, EMBED);

    // LN1 -> h (bf16 split)
    ln_kernel<<<ROWS, t256>>>(x, g1, beta1, phh, phl);

    dim3 g1024(EMBED / 128, ROWS / 128);
    gemm_mma<0, 0, 1><<<g1024, t256, GEMM_SMEM>>>(phh, phl, wqh, wql, bq, nullptr, pq, nullptr, nullptr, ROWS, EMBED, EMBED);
    gemm_mma<0, 0, 1><<<g1024, t256, GEMM_SMEM>>>(phh, phl, wkh, wkl, bk, nullptr, pk, nullptr, nullptr, ROWS, EMBED, EMBED);
    gemm_mma<0, 0, 1><<<g1024, t256, GEMM_SMEM>>>(phh, phl, wvh, wvl, bv, nullptr, pv, nullptr, nullptr, ROWS, EMBED, EMBED);

    attn_kernel<<<BATCH * HEADS * (SEQ / 64), t256>>>();

    // x1 = x + y @ Wo + bo
    gemm_mma<1, 0, 1><<<g1024, t256, GEMM_SMEM>>>(pyh, pyl, woh, wol, bo, x, px1, nullptr, nullptr, ROWS, EMBED, EMBED);
    // LN2 -> h2 (bf16 split)
    ln_kernel<<<ROWS, t256>>>(px1, g2, beta2, ph2h, ph2l);
    // f = gelu(h2 @ W1 + b1), bf16 split only
    dim3 gff(FFDIM / 128, ROWS / 128);
    gemm_mma<2, 1, 0><<<gff, t256, GEMM_SMEM>>>(ph2h, ph2l, w1h, w1l, b1, nullptr, nullptr, pfh, pfl, ROWS, FFDIM, EMBED);
    // out = x1 + f @ W2 + b2
    gemm_mma<1, 0, 1><<<g1024, t256, GEMM_SMEM>>>(pfh, pfl, w2h, w2l, b2, px1, out, nullptr, nullptr, ROWS, EMBED, FFDIM);
}

// round 8
// speedup vs baseline: 5.2364x; 2.1798x over previous
#include <cuda_runtime.h>
#include <cuda_bf16.h>
#include <math.h>
#include <stdint.h>

#define EMBED 1024
#define HEADS 16
#define HEAD_DIM 64
#define BATCH 4
#define SEQ 2048
#define FFDIM 4096
#define ROWS (BATCH * SEQ) /* 8192 */

// ---------------- scratch (device globals; allocation-free) ----------------
__device__ float g_x1[ROWS * EMBED];
__device__ __nv_bfloat16 g_h_hi[ROWS * EMBED],  g_h_lo[ROWS * EMBED];
__device__ __nv_bfloat16 g_y_hi[ROWS * EMBED],  g_y_lo[ROWS * EMBED];
__device__ __nv_bfloat16 g_h2_hi[ROWS * EMBED], g_h2_lo[ROWS * EMBED];
__device__ __nv_bfloat16 g_f_hi[ROWS * FFDIM],  g_f_lo[ROWS * FFDIM];
// attention operands: Q,K head-major [b,h,s,d]; V transposed [b,h,d,s]
__device__ __nv_bfloat16 g_att_qh[ROWS * EMBED], g_att_ql[ROWS * EMBED];
__device__ __nv_bfloat16 g_att_kh[ROWS * EMBED], g_att_kl[ROWS * EMBED];
__device__ __nv_bfloat16 g_att_vh[ROWS * EMBED], g_att_vl[ROWS * EMBED];
// pre-transposed weights [N,K] bf16 hi/lo
__device__ __nv_bfloat16 g_wq_hi[EMBED * EMBED], g_wq_lo[EMBED * EMBED];
__device__ __nv_bfloat16 g_wk_hi[EMBED * EMBED], g_wk_lo[EMBED * EMBED];
__device__ __nv_bfloat16 g_wv_hi[EMBED * EMBED], g_wv_lo[EMBED * EMBED];
__device__ __nv_bfloat16 g_wo_hi[EMBED * EMBED], g_wo_lo[EMBED * EMBED];
__device__ __nv_bfloat16 g_w1_hi[EMBED * FFDIM], g_w1_lo[EMBED * FFDIM];
__device__ __nv_bfloat16 g_w2_hi[FFDIM * EMBED], g_w2_lo[FFDIM * EMBED];

// ---------------- helpers ----------------
__device__ __forceinline__ uint32_t smem_u32(const void* p) {
    uint32_t a;
    asm("{ .reg .u64 t; cvta.to.shared.u64 t, %1; cvt.u32.u64 %0, t; }" : "=r"(a) : "l"(p));
    return a;
}
__device__ __forceinline__ void split_bf16(float x, __nv_bfloat16& h, __nv_bfloat16& l) {
    h = __float2bfloat16(x);
    l = __float2bfloat16(x - __bfloat162float(h));
}
__device__ __forceinline__ void split2_pack(float a, float b, uint32_t& hi, uint32_t& lo) {
    __nv_bfloat16 ah, al, bh, bl;
    split_bf16(a, ah, al); split_bf16(b, bh, bl);
    __nv_bfloat162 H; H.x = ah; H.y = bh;
    __nv_bfloat162 L; L.x = al; L.y = bl;
    hi = *reinterpret_cast<uint32_t*>(&H);
    lo = *reinterpret_cast<uint32_t*>(&L);
}
__device__ __forceinline__ float gelu_exact(float x) {
    return 0.5f * x * (1.0f + erff(x * 0.70710678118654752f));
}

#define CP_ASYNC16(dst, src) \
    asm volatile("cp.async.cg.shared.global [%0], [%1], 16;" :: "r"(dst), "l"(src))
#define CP_COMMIT()  asm volatile("cp.async.commit_group;" ::: "memory")
#define CP_WAIT(n)   asm volatile("cp.async.wait_group %0;" :: "n"(n) : "memory")

__device__ __forceinline__ void mma_bf16(float* c, const uint32_t* a, const uint32_t* b) {
    asm volatile(
        "mma.sync.aligned.m16n8k16.row.col.f32.bf16.bf16.f32 "
        "{%0,%1,%2,%3},{%4,%5,%6,%7},{%8,%9},{%0,%1,%2,%3};"
        : "+f"(c[0]), "+f"(c[1]), "+f"(c[2]), "+f"(c[3])
        : "r"(a[0]), "r"(a[1]), "r"(a[2]), "r"(a[3]), "r"(b[0]), "r"(b[1]));
}
#define LDSM_X4(r, addr) \
    asm volatile("ldmatrix.sync.aligned.m8n8.x4.shared.b16 {%0,%1,%2,%3}, [%4];" \
                 : "=r"((r)[0]), "=r"((r)[1]), "=r"((r)[2]), "=r"((r)[3]) : "r"(addr))
#define LDSM_X2(r, addr) \
    asm volatile("ldmatrix.sync.aligned.m8n8.x2.shared.b16 {%0,%1}, [%2];" \
                 : "=r"((r)[0]), "=r"((r)[1]) : "r"(addr))

// ---------------- weight transpose + split ----------------
__global__ void __launch_bounds__(256) transpose_split(const float* __restrict__ W,
                                                       __nv_bfloat16* __restrict__ Th,
                                                       __nv_bfloat16* __restrict__ Tl,
                                                       int K, int N) {
    __shared__ float t[32][33];
    int n0 = blockIdx.x * 32, k0 = blockIdx.y * 32;
    int tx = threadIdx.x & 31, ty = threadIdx.x >> 5;
#pragma unroll
    for (int i = 0; i < 4; i++) {
        int k = ty + i * 8;
        t[k][tx] = W[(size_t)(k0 + k) * N + n0 + tx];
    }
    __syncthreads();
#pragma unroll
    for (int i = 0; i < 4; i++) {
        int r = ty + i * 8;
        float v = t[tx][r];
        __nv_bfloat16 h, l;
        split_bf16(v, h, l);
        Th[(size_t)(n0 + r) * K + k0 + tx] = h;
        Tl[(size_t)(n0 + r) * K + k0 + tx] = l;
    }
}

// ---------------- LayerNorm ----------------
__global__ void __launch_bounds__(256) ln_kernel(const float* __restrict__ X,
                                                 const float* __restrict__ gam,
                                                 const float* __restrict__ bet,
                                                 __nv_bfloat16* __restrict__ Yh,
                                                 __nv_bfloat16* __restrict__ Yl) {
    int row = blockIdx.x;
    int tid = threadIdx.x;
    const float* xr = X + (size_t)row * EMBED;
    float4 v = *reinterpret_cast<const float4*>(&xr[tid * 4]);
    float s  = v.x + v.y + v.z + v.w;
    float sq = v.x * v.x + v.y * v.y + v.z * v.z + v.w * v.w;
#pragma unroll
    for (int o = 16; o; o >>= 1) {
        s  += __shfl_xor_sync(0xffffffffu, s, o);
        sq += __shfl_xor_sync(0xffffffffu, sq, o);
    }
    __shared__ float ss[8], sqs[8];
    int w = tid >> 5;
    if ((tid & 31) == 0) { ss[w] = s; sqs[w] = sq; }
    __syncthreads();
    s = 0.f; sq = 0.f;
#pragma unroll
    for (int i = 0; i < 8; i++) { s += ss[i]; sq += sqs[i]; }
    float mu  = s * (1.0f / EMBED);
    float var = sq * (1.0f / EMBED) - mu * mu;
    float inv = rsqrtf(var + 1e-5f);
    float4 gv = *reinterpret_cast<const float4*>(&gam[tid * 4]);
    float4 bv = *reinterpret_cast<const float4*>(&bet[tid * 4]);
    float o0 = (v.x - mu) * inv * gv.x + bv.x;
    float o1 = (v.y - mu) * inv * gv.y + bv.y;
    float o2 = (v.z - mu) * inv * gv.z + bv.z;
    float o3 = (v.w - mu) * inv * gv.w + bv.w;
    size_t base = (size_t)row * EMBED + tid * 4;
    uint32_t h0, l0, h1, l1;
    split2_pack(o0, o1, h0, l0);
    split2_pack(o2, o3, h1, l1);
    *reinterpret_cast<uint32_t*>(&Yh[base])     = h0;
    *reinterpret_cast<uint32_t*>(&Yh[base + 2]) = h1;
    *reinterpret_cast<uint32_t*>(&Yl[base])     = l0;
    *reinterpret_cast<uint32_t*>(&Yl[base + 2]) = l1;
}

// ---------------- mma.sync GEMM (split-bf16 fp32 emulation) ----------------
// EPI: 0=bias  1=bias+residual  2=bias+GELU
// OUT: 0=fp32 row-major  1=bf16 hi/lo row-major  2=bf16 hi/lo [b,h,s,d]  3=bf16 hi/lo [b,h,d,s]
static constexpr int GEMM_SMEM = 81920;

template <int EPI, int OUT>
__device__ __forceinline__ void epi_store(float v0, float v1, int r, int c,
                                          const float* R, float* C,
                                          __nv_bfloat16* Ch, __nv_bfloat16* Cl, int N) {
    size_t off = (size_t)r * N + c;
    if (EPI == 1) { float2 rr = *reinterpret_cast<const float2*>(&R[off]); v0 += rr.x; v1 += rr.y; }
    if (EPI == 2) { v0 = gelu_exact(v0); v1 = gelu_exact(v1); }
    if (OUT == 0) {
        float2 o; o.x = v0; o.y = v1;
        *reinterpret_cast<float2*>(&C[off]) = o;
    } else if (OUT == 1) {
        uint32_t hi, lo;
        split2_pack(v0, v1, hi, lo);
        *reinterpret_cast<uint32_t*>(&Ch[off]) = hi;
        *reinterpret_cast<uint32_t*>(&Cl[off]) = lo;
    } else if (OUT == 2) {
        // [b,h,s,d]: b=r>>11, h=c>>6, s=r&2047, d=c&63 (pair contiguous in d)
        size_t o2 = (((size_t)(r >> 11) * HEADS + (c >> 6)) * SEQ + (r & 2047)) * 64 + (c & 63);
        uint32_t hi, lo;
        split2_pack(v0, v1, hi, lo);
        *reinterpret_cast<uint32_t*>(&Ch[o2]) = hi;
        *reinterpret_cast<uint32_t*>(&Cl[o2]) = lo;
    } else {
        // [b,h,d,s]: stride SEQ between d and d+1
        size_t o3 = (((size_t)(r >> 11) * HEADS + (c >> 6)) * 64 + (c & 63)) * SEQ + (r & 2047);
        __nv_bfloat16 h0, l0, h1, l1;
        split_bf16(v0, h0, l0); split_bf16(v1, h1, l1);
        Ch[o3] = h0; Cl[o3] = l0;
        Ch[o3 + SEQ] = h1; Cl[o3 + SEQ] = l1;
    }
}

__device__ __forceinline__ void gemm_load_stage(
    uint32_t smem_base, int stage,
    const __nv_bfloat16* Ah, const __nv_bfloat16* Al,
    const __nv_bfloat16* Bh, const __nv_bfloat16* Bl,
    int row0, int col0, int K, int k0, int tid) {
    uint32_t sb = smem_base + (uint32_t)stage * 40960u;
#pragma unroll
    for (int i = 0; i < 8; i++) {
        int idx = i * 256 + tid;
        int arr = idx >> 9;
        int pos = idx & 511;
        int r   = pos >> 2;
        int c8  = pos & 3;
        uint32_t dst = sb + (uint32_t)(arr * 10240 + r * 80 + c8 * 16);
        const __nv_bfloat16* src;
        if (arr == 0)      src = &Ah[(size_t)(row0 + r) * K + k0 + c8 * 8];
        else if (arr == 1) src = &Al[(size_t)(row0 + r) * K + k0 + c8 * 8];
        else if (arr == 2) src = &Bh[(size_t)(col0 + r) * K + k0 + c8 * 8];
        else               src = &Bl[(size_t)(col0 + r) * K + k0 + c8 * 8];
        CP_ASYNC16(dst, src);
    }
}

template <int EPI, int OUT>
__global__ void __launch_bounds__(256) gemm_mma(
    const __nv_bfloat16* __restrict__ Ah, const __nv_bfloat16* __restrict__ Al,
    const __nv_bfloat16* __restrict__ Bh, const __nv_bfloat16* __restrict__ Bl,
    const float* __restrict__ bias, const float* __restrict__ R,
    float* __restrict__ C, __nv_bfloat16* __restrict__ Ch, __nv_bfloat16* __restrict__ Cl,
    int M, int N, int K) {
    extern __shared__ char dsm[];
    const int tid  = threadIdx.x;
    const int lane = tid & 31;
    const int wid  = tid >> 5;
    const int wm   = wid & 1;
    const int wn   = wid >> 1;
    const int row0 = blockIdx.y * 128;
    const int col0 = blockIdx.x * 128;
    const uint32_t smem_base = smem_u32(dsm);

    float acc[4][4][4];
#pragma unroll
    for (int i = 0; i < 4; i++)
#pragma unroll
        for (int j = 0; j < 4; j++)
#pragma unroll
            for (int k = 0; k < 4; k++) acc[i][j][k] = 0.f;

    const int nchunks = K >> 5;
    gemm_load_stage(smem_base, 0, Ah, Al, Bh, Bl, row0, col0, K, 0, tid);
    CP_COMMIT();

    for (int c = 0; c < nchunks; c++) {
        if (c + 1 < nchunks) {
            gemm_load_stage(smem_base, (c + 1) & 1, Ah, Al, Bh, Bl, row0, col0, K, (c + 1) << 5, tid);
            CP_COMMIT();
            CP_WAIT(1);
        } else {
            CP_WAIT(0);
        }
        __syncthreads();

        uint32_t sb = smem_base + (uint32_t)(c & 1) * 40960u;
#pragma unroll
        for (int ks = 0; ks < 32; ks += 16) {
            uint32_t bh[4][2], bl[4][2];
            int l2 = lane & 15;
            int rb_off = l2 & 7;
            int kb_off = ks + ((l2 >> 3) << 3);
#pragma unroll
            for (int nt = 0; nt < 4; nt++) {
                int rowb = wn * 32 + nt * 8 + rb_off;
                uint32_t ab = sb + 20480u + (uint32_t)(rowb * 80 + kb_off * 2);
                LDSM_X2(bh[nt], ab);
                LDSM_X2(bl[nt], ab + 10240u);
            }
            int ra_off = (lane & 7) + ((lane >> 3) & 1) * 8;
            int ka_off = ks + ((lane >> 4) << 3);
#pragma unroll
            for (int mt = 0; mt < 4; mt++) {
                int rowa = wm * 64 + mt * 16 + ra_off;
                uint32_t aa = sb + (uint32_t)(rowa * 80 + ka_off * 2);
                uint32_t ah[4], al[4];
                LDSM_X4(ah, aa);
                LDSM_X4(al, aa + 10240u);
#pragma unroll
                for (int nt = 0; nt < 4; nt++) {
                    mma_bf16(acc[mt][nt], ah, bh[nt]);
                    mma_bf16(acc[mt][nt], ah, bl[nt]);
                    mma_bf16(acc[mt][nt], al, bh[nt]);
                }
            }
        }
        __syncthreads();
    }

#pragma unroll
    for (int mt = 0; mt < 4; mt++) {
#pragma unroll
        for (int nt = 0; nt < 4; nt++) {
            int rg = row0 + wm * 64 + mt * 16 + (lane >> 2);
            int cg = col0 + wn * 32 + nt * 8 + (lane & 3) * 2;
            float2 b2 = *reinterpret_cast<const float2*>(&bias[cg]);
            epi_store<EPI, OUT>(acc[mt][nt][0] + b2.x, acc[mt][nt][1] + b2.y,
                                rg, cg, R, C, Ch, Cl, N);
            epi_store<EPI, OUT>(acc[mt][nt][2] + b2.x, acc[mt][nt][3] + b2.y,
                                rg + 8, cg, R, C, Ch, Cl, N);
        }
    }
}

// ---------------- tensor-core causal flash attention -----------------------
// CTA: one (b,h) x one 128-row q tile. 8 warps x 16 q rows. K-tiles of 64 keys.
// K smem: [64 keys][64 d] hi/lo, row stride 144B. Vt smem: [64 d][64 keys] hi/lo.
static constexpr int AT_KLO   = 18432;   // 128*144 region reserved (Q staging reuse)
static constexpr int AT_VHI   = 36864;
static constexpr int AT_VLO   = 46080;   // 36864 + 9216
static constexpr int AT_STAGE = 55296;
static constexpr int ATTN_SMEM = 110592; // 2 stages

__device__ __forceinline__ void attn_load_kv(uint32_t sb, int stage, int bh, int k0, int tid) {
    uint32_t st = sb + (uint32_t)stage * AT_STAGE;
    // K tile: 64 rows x 64 halves, hi+lo -> 1024 chunks of 16B
#pragma unroll
    for (int i = 0; i < 4; i++) {
        int idx = i * 256 + tid;          // 0..1023
        int arr = idx >> 9;               // 0 hi, 1 lo
        int pos = idx & 511;
        int r   = pos >> 3;               // 0..63
        int c8  = pos & 7;
        uint32_t dst = st + (uint32_t)(arr * AT_KLO + r * 144 + c8 * 16);
        const __nv_bfloat16* src = (arr ? g_att_kl : g_att_kh)
            + ((size_t)bh * SEQ + k0 + r) * 64 + c8 * 8;
        CP_ASYNC16(dst, src);
    }
    // Vt tile: 64 d-rows x 64 keys, hi+lo -> 1024 chunks
#pragma unroll
    for (int i = 0; i < 4; i++) {
        int idx = i * 256 + tid;
        int arr = idx >> 9;
        int pos = idx & 511;
        int r   = pos >> 3;               // d 0..63
        int c8  = pos & 7;
        uint32_t dst = st + (uint32_t)(AT_VHI + arr * 9216 + r * 144 + c8 * 16);
        const __nv_bfloat16* src = (arr ? g_att_vl : g_att_vh)
            + ((size_t)bh * 64 + r) * SEQ + k0 + c8 * 8;
        CP_ASYNC16(dst, src);
    }
}

__global__ void __launch_bounds__(256) attn_mma() {
    extern __shared__ char smbuf[];
    const int qt  = blockIdx.x;
    const int bh  = blockIdx.y;
    const int q0  = qt * 128;
    const int tid = threadIdx.x;
    const int lane = tid & 31;
    const int w    = tid >> 5;
    const uint32_t sb = smem_u32(smbuf);

    // ---- stage Q tile [128 x 64] hi/lo into stage-0 K region, extract frags
#pragma unroll
    for (int i = 0; i < 8; i++) {
        int idx = i * 256 + tid;          // 0..2047
        int arr = idx >> 10;
        int pos = idx & 1023;
        int r   = pos >> 3;               // 0..127
        int c8  = pos & 7;
        uint32_t dst = sb + (uint32_t)(arr * AT_KLO + r * 144 + c8 * 16);
        const __nv_bfloat16* src = (arr ? g_att_ql : g_att_qh)
            + ((size_t)bh * SEQ + q0 + r) * 64 + c8 * 8;
        CP_ASYNC16(dst, src);
    }
    CP_COMMIT(); CP_WAIT(0); __syncthreads();

    uint32_t qh[4][4], ql[4][4];
    {
        int ra = (lane & 7) + ((lane >> 3) & 1) * 8;
#pragma unroll
        for (int kc = 0; kc < 4; kc++) {
            int ka = kc * 16 + ((lane >> 4) << 3);
            uint32_t addr = sb + (uint32_t)((w * 16 + ra) * 144 + ka * 2);
            LDSM_X4(qh[kc], addr);
            LDSM_X4(ql[kc], addr + AT_KLO);
        }
    }
    __syncthreads();

    float m0 = -1e30f, m1 = -1e30f, l0 = 0.f, l1 = 0.f;
    float o[8][4];
#pragma unroll
    for (int nt = 0; nt < 8; nt++)
#pragma unroll
        for (int j = 0; j < 4; j++) o[nt][j] = 0.f;

    const int nkt = 2 * qt + 2;
    attn_load_kv(sb, 0, bh, 0, tid);
    CP_COMMIT();

    const int l2 = lane & 15;
    const int rb = l2 & 7;
    const int kb = (l2 >> 3) << 3;

    for (int kt = 0; kt < nkt; kt++) {
        if (kt + 1 < nkt) {
            attn_load_kv(sb, (kt + 1) & 1, bh, (kt + 1) * 64, tid);
            CP_COMMIT();
            CP_WAIT(1);
        } else {
            CP_WAIT(0);
        }
        __syncthreads();

        uint32_t st = sb + (uint32_t)(kt & 1) * AT_STAGE;
        const int k0 = kt * 64;

        // ---- scores S = Q K^T (3-term split)
        float s[8][4];
#pragma unroll
        for (int nt = 0; nt < 8; nt++)
#pragma unroll
            for (int j = 0; j < 4; j++) s[nt][j] = 0.f;
#pragma unroll
        for (int kc = 0; kc < 4; kc++) {
#pragma unroll
            for (int nt = 0; nt < 8; nt++) {
                uint32_t kaddr = st + (uint32_t)((nt * 8 + rb) * 144 + (kc * 16 + kb) * 2);
                uint32_t kfh[2], kfl[2];
                LDSM_X2(kfh, kaddr);
                LDSM_X2(kfl, kaddr + AT_KLO);
                mma_bf16(s[nt], qh[kc], kfh);
                mma_bf16(s[nt], ql[kc], kfh);
                mma_bf16(s[nt], qh[kc], kfl);
            }
        }

        // ---- scale + causal mask
        const int r0 = q0 + w * 16 + (lane >> 2);
#pragma unroll
        for (int nt = 0; nt < 8; nt++)
#pragma unroll
            for (int j = 0; j < 4; j++) s[nt][j] *= 0.125f;
        if (k0 + 63 > q0 + w * 16) {
#pragma unroll
            for (int nt = 0; nt < 8; nt++)
#pragma unroll
                for (int j = 0; j < 4; j++) {
                    int col = k0 + nt * 8 + (lane & 3) * 2 + (j & 1);
                    int row = r0 + ((j >> 1) << 3);
                    if (col > row) s[nt][j] = -1e30f;
                }
        }

        // ---- online softmax (rows r0 and r0+8)
        float mx0 = -1e30f, mx1 = -1e30f;
#pragma unroll
        for (int nt = 0; nt < 8; nt++) {
            mx0 = fmaxf(mx0, fmaxf(s[nt][0], s[nt][1]));
            mx1 = fmaxf(mx1, fmaxf(s[nt][2], s[nt][3]));
        }
        mx0 = fmaxf(mx0, __shfl_xor_sync(0xffffffffu, mx0, 1));
        mx0 = fmaxf(mx0, __shfl_xor_sync(0xffffffffu, mx0, 2));
        mx1 = fmaxf(mx1, __shfl_xor_sync(0xffffffffu, mx1, 1));
        mx1 = fmaxf(mx1, __shfl_xor_sync(0xffffffffu, mx1, 2));
        float mn0 = fmaxf(m0, mx0), mn1 = fmaxf(m1, mx1);
        float a0 = __expf(m0 - mn0), a1 = __expf(m1 - mn1);
        float rl0 = 0.f, rl1 = 0.f;
#pragma unroll
        for (int nt = 0; nt < 8; nt++) {
            s[nt][0] = __expf(s[nt][0] - mn0); rl0 += s[nt][0];
            s[nt][1] = __expf(s[nt][1] - mn0); rl0 += s[nt][1];
            s[nt][2] = __expf(s[nt][2] - mn1); rl1 += s[nt][2];
            s[nt][3] = __expf(s[nt][3] - mn1); rl1 += s[nt][3];
        }
        rl0 += __shfl_xor_sync(0xffffffffu, rl0, 1);
        rl0 += __shfl_xor_sync(0xffffffffu, rl0, 2);
        rl1 += __shfl_xor_sync(0xffffffffu, rl1, 1);
        rl1 += __shfl_xor_sync(0xffffffffu, rl1, 2);
        l0 = l0 * a0 + rl0;
        l1 = l1 * a1 + rl1;
        m0 = mn0; m1 = mn1;
#pragma unroll
        for (int nt = 0; nt < 8; nt++) {
            o[nt][0] *= a0; o[nt][1] *= a0;
            o[nt][2] *= a1; o[nt][3] *= a1;
        }

        // ---- O += P V (3-term split; P frags from acc via register remap)
#pragma unroll
        for (int kc = 0; kc < 4; kc++) {
            uint32_t pah[4], pal[4];
            split2_pack(s[2 * kc][0],     s[2 * kc][1],     pah[0], pal[0]);
            split2_pack(s[2 * kc][2],     s[2 * kc][3],     pah[1], pal[1]);
            split2_pack(s[2 * kc + 1][0], s[2 * kc + 1][1], pah[2], pal[2]);
            split2_pack(s[2 * kc + 1][2], s[2 * kc + 1][3], pah[3], pal[3]);
#pragma unroll
            for (int nt = 0; nt < 8; nt++) {
                uint32_t vaddr = st + (uint32_t)(AT_VHI + (nt * 8 + rb) * 144 + (kc * 16 + kb) * 2);
                uint32_t vfh[2], vfl[2];
                LDSM_X2(vfh, vaddr);
                LDSM_X2(vfl, vaddr + 9216);
                mma_bf16(o[nt], pah, vfh);
                mma_bf16(o[nt], pal, vfh);
                mma_bf16(o[nt], pah, vfl);
            }
        }
        __syncthreads();
    }

    // ---- write y (row-major [ROWS][EMBED] bf16 hi/lo)
    const float i0 = 1.f / l0, i1 = 1.f / l1;
    const int b = bh >> 4, h = bh & 15;
    const int rowg = b * SEQ + q0 + w * 16 + (lane >> 2);
#pragma unroll
    for (int nt = 0; nt < 8; nt++) {
        int colg = h * 64 + nt * 8 + (lane & 3) * 2;
        size_t off0 = (size_t)rowg * EMBED + colg;
        size_t off1 = off0 + (size_t)8 * EMBED;
        uint32_t hi, lo;
        split2_pack(o[nt][0] * i0, o[nt][1] * i0, hi, lo);
        *reinterpret_cast<uint32_t*>(&g_y_hi[off0]) = hi;
        *reinterpret_cast<uint32_t*>(&g_y_lo[off0]) = lo;
        split2_pack(o[nt][2] * i1, o[nt][3] * i1, hi, lo);
        *reinterpret_cast<uint32_t*>(&g_y_hi[off1]) = hi;
        *reinterpret_cast<uint32_t*>(&g_y_lo[off1]) = lo;
    }
}

// ---------------- launch ---------------------------------------------------
extern "C" void kernel_launch(void* const* d_in, const int* in_sizes, int n_in,
                              void* d_out, int out_size) {
    const float* x     = (const float*)d_in[0];
    const float* Wq    = (const float*)d_in[1];
    const float* bq    = (const float*)d_in[2];
    const float* Wk    = (const float*)d_in[3];
    const float* bk    = (const float*)d_in[4];
    const float* Wv    = (const float*)d_in[5];
    const float* bv    = (const float*)d_in[6];
    const float* Wo    = (const float*)d_in[7];
    const float* bo    = (const float*)d_in[8];
    const float* g1    = (const float*)d_in[9];
    const float* beta1 = (const float*)d_in[10];
    const float* g2    = (const float*)d_in[11];
    const float* beta2 = (const float*)d_in[12];
    const float* W1    = (const float*)d_in[13];
    const float* b1    = (const float*)d_in[14];
    const float* W2    = (const float*)d_in[15];
    const float* b2    = (const float*)d_in[16];
    float* out = (float*)d_out;

    float* px1;
    cudaGetSymbolAddress((void**)&px1, g_x1);
    __nv_bfloat16 *phh, *phl, *pyh, *pyl, *ph2h, *ph2l, *pfh, *pfl;
    cudaGetSymbolAddress((void**)&phh,  g_h_hi);  cudaGetSymbolAddress((void**)&phl,  g_h_lo);
    cudaGetSymbolAddress((void**)&pyh,  g_y_hi);  cudaGetSymbolAddress((void**)&pyl,  g_y_lo);
    cudaGetSymbolAddress((void**)&ph2h, g_h2_hi); cudaGetSymbolAddress((void**)&ph2l, g_h2_lo);
    cudaGetSymbolAddress((void**)&pfh,  g_f_hi);  cudaGetSymbolAddress((void**)&pfl,  g_f_lo);
    __nv_bfloat16 *aqh, *aql, *akh, *akl, *avh, *avl;
    cudaGetSymbolAddress((void**)&aqh, g_att_qh); cudaGetSymbolAddress((void**)&aql, g_att_ql);
    cudaGetSymbolAddress((void**)&akh, g_att_kh); cudaGetSymbolAddress((void**)&akl, g_att_kl);
    cudaGetSymbolAddress((void**)&avh, g_att_vh); cudaGetSymbolAddress((void**)&avl, g_att_vl);
    __nv_bfloat16 *wqh, *wql, *wkh, *wkl, *wvh, *wvl, *woh, *wol, *w1h, *w1l, *w2h, *w2l;
    cudaGetSymbolAddress((void**)&wqh, g_wq_hi); cudaGetSymbolAddress((void**)&wql, g_wq_lo);
    cudaGetSymbolAddress((void**)&wkh, g_wk_hi); cudaGetSymbolAddress((void**)&wkl, g_wk_lo);
    cudaGetSymbolAddress((void**)&wvh, g_wv_hi); cudaGetSymbolAddress((void**)&wvl, g_wv_lo);
    cudaGetSymbolAddress((void**)&woh, g_wo_hi); cudaGetSymbolAddress((void**)&wol, g_wo_lo);
    cudaGetSymbolAddress((void**)&w1h, g_w1_hi); cudaGetSymbolAddress((void**)&w1l, g_w1_lo);
    cudaGetSymbolAddress((void**)&w2h, g_w2_hi); cudaGetSymbolAddress((void**)&w2l, g_w2_lo);

    cudaFuncSetAttribute(gemm_mma<0, 2>, cudaFuncAttributeMaxDynamicSharedMemorySize, GEMM_SMEM);
    cudaFuncSetAttribute(gemm_mma<0, 3>, cudaFuncAttributeMaxDynamicSharedMemorySize, GEMM_SMEM);
    cudaFuncSetAttribute(gemm_mma<1, 0>, cudaFuncAttributeMaxDynamicSharedMemorySize, GEMM_SMEM);
    cudaFuncSetAttribute(gemm_mma<2, 1>, cudaFuncAttributeMaxDynamicSharedMemorySize, GEMM_SMEM);
    cudaFuncSetAttribute(attn_mma, cudaFuncAttributeMaxDynamicSharedMemorySize, ATTN_SMEM);

    dim3 t256(256);
    transpose_split<<<dim3(EMBED / 32, EMBED / 32), t256>>>(Wq, wqh, wql, EMBED, EMBED);
    transpose_split<<<dim3(EMBED / 32, EMBED / 32), t256>>>(Wk, wkh, wkl, EMBED, EMBED);
    transpose_split<<<dim3(EMBED / 32, EMBED / 32), t256>>>(Wv, wvh, wvl, EMBED, EMBED);
    transpose_split<<<dim3(EMBED / 32, EMBED / 32), t256>>>(Wo, woh, wol, EMBED, EMBED);
    transpose_split<<<dim3(FFDIM / 32, EMBED / 32), t256>>>(W1, w1h, w1l, EMBED, FFDIM);
    transpose_split<<<dim3(EMBED / 32, FFDIM / 32), t256>>>(W2, w2h, w2l, FFDIM, EMBED);

    // LN1
    ln_kernel<<<ROWS, t256>>>(x, g1, beta1, phh, phl);

    // QKV into attention layouts
    dim3 g1024(EMBED / 128, ROWS / 128);
    gemm_mma<0, 2><<<g1024, t256, GEMM_SMEM>>>(phh, phl, wqh, wql, bq, nullptr, nullptr, aqh, aql, ROWS, EMBED, EMBED);
    gemm_mma<0, 2><<<g1024, t256, GEMM_SMEM>>>(phh, phl, wkh, wkl, bk, nullptr, nullptr, akh, akl, ROWS, EMBED, EMBED);
    gemm_mma<0, 3><<<g1024, t256, GEMM_SMEM>>>(phh, phl, wvh, wvl, bv, nullptr, nullptr, avh, avl, ROWS, EMBED, EMBED);

    // tensor-core flash attention
    attn_mma<<<dim3(SEQ / 128, BATCH * HEADS), t256, ATTN_SMEM>>>();

    // x1 = x + y @ Wo + bo
    gemm_mma<1, 0><<<g1024, t256, GEMM_SMEM>>>(pyh, pyl, woh, wol, bo, x, px1, nullptr, nullptr, ROWS, EMBED, EMBED);
    // LN2
    ln_kernel<<<ROWS, t256>>>(px1, g2, beta2, ph2h, ph2l);
    // f = gelu(h2 @ W1 + b1)
    dim3 gff(FFDIM / 128, ROWS / 128);
    gemm_mma<2, 1><<<gff, t256, GEMM_SMEM>>>(ph2h, ph2l, w1h, w1l, b1, nullptr, nullptr, pfh, pfl, ROWS, FFDIM, EMBED);
    // out = x1 + f @ W2 + b2
    gemm_mma<1, 0><<<g1024, t256, GEMM_SMEM>>>(pfh, pfl, w2h, w2l, b2, px1, out, nullptr, nullptr, ROWS, EMBED, FFDIM);
}

// round 10
// speedup vs baseline: 5.5613x; 1.0620x over previous
#include <cuda_runtime.h>
#include <cuda_bf16.h>
#include <math.h>
#include <stdint.h>

#define EMBED 1024
#define HEADS 16
#define HEAD_DIM 64
#define BATCH 4
#define SEQ 2048
#define FFDIM 4096
#define ROWS (BATCH * SEQ) /* 8192 */

// ---------------- scratch (device globals; allocation-free) ----------------
__device__ float g_x1[ROWS * EMBED];
__device__ __nv_bfloat16 g_h_hi[ROWS * EMBED],  g_h_lo[ROWS * EMBED];
__device__ __nv_bfloat16 g_y_hi[ROWS * EMBED],  g_y_lo[ROWS * EMBED];
__device__ __nv_bfloat16 g_h2_hi[ROWS * EMBED], g_h2_lo[ROWS * EMBED];
__device__ __nv_bfloat16 g_f_hi[ROWS * FFDIM],  g_f_lo[ROWS * FFDIM];
// attention operands: Q,K head-major [b,h,s,d]; V transposed [b,h,d,s]
__device__ __nv_bfloat16 g_att_qh[ROWS * EMBED], g_att_ql[ROWS * EMBED];
__device__ __nv_bfloat16 g_att_kh[ROWS * EMBED], g_att_kl[ROWS * EMBED];
__device__ __nv_bfloat16 g_att_vh[ROWS * EMBED], g_att_vl[ROWS * EMBED];
// pre-transposed weights [N,K] bf16 hi/lo
__device__ __nv_bfloat16 g_wqkv_hi[3 * EMBED * EMBED], g_wqkv_lo[3 * EMBED * EMBED];
__device__ float         g_bqkv[3 * EMBED];
__device__ __nv_bfloat16 g_wo_hi[EMBED * EMBED], g_wo_lo[EMBED * EMBED];
__device__ __nv_bfloat16 g_w1_hi[EMBED * FFDIM], g_w1_lo[EMBED * FFDIM];
__device__ __nv_bfloat16 g_w2_hi[FFDIM * EMBED], g_w2_lo[FFDIM * EMBED];

// ---------------- helpers ----------------
__device__ __forceinline__ uint32_t smem_u32(const void* p) {
    uint32_t a;
    asm("{ .reg .u64 t; cvta.to.shared.u64 t, %1; cvt.u32.u64 %0, t; }" : "=r"(a) : "l"(p));
    return a;
}
__device__ __forceinline__ void split_bf16(float x, __nv_bfloat16& h, __nv_bfloat16& l) {
    h = __float2bfloat16(x);
    l = __float2bfloat16(x - __bfloat162float(h));
}
__device__ __forceinline__ void split2_pack(float a, float b, uint32_t& hi, uint32_t& lo) {
    __nv_bfloat16 ah, al, bh, bl;
    split_bf16(a, ah, al); split_bf16(b, bh, bl);
    __nv_bfloat162 H; H.x = ah; H.y = bh;
    __nv_bfloat162 L; L.x = al; L.y = bl;
    hi = *reinterpret_cast<uint32_t*>(&H);
    lo = *reinterpret_cast<uint32_t*>(&L);
}
__device__ __forceinline__ float gelu_exact(float x) {
    return 0.5f * x * (1.0f + erff(x * 0.70710678118654752f));
}

#define CP_ASYNC16(dst, src) \
    asm volatile("cp.async.cg.shared.global [%0], [%1], 16;" :: "r"(dst), "l"(src))
#define CP_COMMIT()  asm volatile("cp.async.commit_group;" ::: "memory")
#define CP_WAIT(n)   asm volatile("cp.async.wait_group %0;" :: "n"(n) : "memory")

__device__ __forceinline__ void mma_bf16(float* c, const uint32_t* a, const uint32_t* b) {
    asm volatile(
        "mma.sync.aligned.m16n8k16.row.col.f32.bf16.bf16.f32 "
        "{%0,%1,%2,%3},{%4,%5,%6,%7},{%8,%9},{%0,%1,%2,%3};"
        : "+f"(c[0]), "+f"(c[1]), "+f"(c[2]), "+f"(c[3])
        : "r"(a[0]), "r"(a[1]), "r"(a[2]), "r"(a[3]), "r"(b[0]), "r"(b[1]));
}
#define LDSM_X4(r, addr) \
    asm volatile("ldmatrix.sync.aligned.m8n8.x4.shared.b16 {%0,%1,%2,%3}, [%4];" \
                 : "=r"((r)[0]), "=r"((r)[1]), "=r"((r)[2]), "=r"((r)[3]) : "r"(addr))
#define LDSM_X2(r, addr) \
    asm volatile("ldmatrix.sync.aligned.m8n8.x2.shared.b16 {%0,%1}, [%2];" \
                 : "=r"((r)[0]), "=r"((r)[1]) : "r"(addr))

// ---------------- weight transpose + split ----------------
__global__ void __launch_bounds__(256) transpose_split(const float* __restrict__ W,
                                                       __nv_bfloat16* __restrict__ Th,
                                                       __nv_bfloat16* __restrict__ Tl,
                                                       int K, int N) {
    __shared__ float t[32][33];
    int n0 = blockIdx.x * 32, k0 = blockIdx.y * 32;
    int tx = threadIdx.x & 31, ty = threadIdx.x >> 5;
#pragma unroll
    for (int i = 0; i < 4; i++) {
        int k = ty + i * 8;
        t[k][tx] = W[(size_t)(k0 + k) * N + n0 + tx];
    }
    __syncthreads();
#pragma unroll
    for (int i = 0; i < 4; i++) {
        int r = ty + i * 8;
        float v = t[tx][r];
        __nv_bfloat16 h, l;
        split_bf16(v, h, l);
        Th[(size_t)(n0 + r) * K + k0 + tx] = h;
        Tl[(size_t)(n0 + r) * K + k0 + tx] = l;
    }
}

__global__ void __launch_bounds__(256) concat_bias(const float* __restrict__ bq,
                                                   const float* __restrict__ bk,
                                                   const float* __restrict__ bv) {
    int i = blockIdx.x * 256 + threadIdx.x;  // 0..1023
    g_bqkv[i]        = bq[i];
    g_bqkv[i + 1024] = bk[i];
    g_bqkv[i + 2048] = bv[i];
}

// ---------------- LayerNorm ----------------
__global__ void __launch_bounds__(256) ln_kernel(const float* __restrict__ X,
                                                 const float* __restrict__ gam,
                                                 const float* __restrict__ bet,
                                                 __nv_bfloat16* __restrict__ Yh,
                                                 __nv_bfloat16* __restrict__ Yl) {
    int row = blockIdx.x;
    int tid = threadIdx.x;
    const float* xr = X + (size_t)row * EMBED;
    float4 v = *reinterpret_cast<const float4*>(&xr[tid * 4]);
    float s  = v.x + v.y + v.z + v.w;
    float sq = v.x * v.x + v.y * v.y + v.z * v.z + v.w * v.w;
#pragma unroll
    for (int o = 16; o; o >>= 1) {
        s  += __shfl_xor_sync(0xffffffffu, s, o);
        sq += __shfl_xor_sync(0xffffffffu, sq, o);
    }
    __shared__ float ss[8], sqs[8];
    int w = tid >> 5;
    if ((tid & 31) == 0) { ss[w] = s; sqs[w] = sq; }
    __syncthreads();
    s = 0.f; sq = 0.f;
#pragma unroll
    for (int i = 0; i < 8; i++) { s += ss[i]; sq += sqs[i]; }
    float mu  = s * (1.0f / EMBED);
    float var = sq * (1.0f / EMBED) - mu * mu;
    float inv = rsqrtf(var + 1e-5f);
    float4 gv = *reinterpret_cast<const float4*>(&gam[tid * 4]);
    float4 bv = *reinterpret_cast<const float4*>(&bet[tid * 4]);
    float o0 = (v.x - mu) * inv * gv.x + bv.x;
    float o1 = (v.y - mu) * inv * gv.y + bv.y;
    float o2 = (v.z - mu) * inv * gv.z + bv.z;
    float o3 = (v.w - mu) * inv * gv.w + bv.w;
    size_t base = (size_t)row * EMBED + tid * 4;
    uint32_t h0, l0, h1, l1;
    split2_pack(o0, o1, h0, l0);
    split2_pack(o2, o3, h1, l1);
    *reinterpret_cast<uint32_t*>(&Yh[base])     = h0;
    *reinterpret_cast<uint32_t*>(&Yh[base + 2]) = h1;
    *reinterpret_cast<uint32_t*>(&Yl[base])     = l0;
    *reinterpret_cast<uint32_t*>(&Yl[base + 2]) = l1;
}

// ---------------- mma.sync GEMM (split-bf16 fp32 emulation) ----------------
// EPI: 0=bias  1=bias+residual  2=bias+GELU
// OUT: 0=fp32 row-major  1=bf16 hi/lo row-major  4=fused QKV (c<1024 Q[b,h,s,d],
//      <2048 K[b,h,s,d], else V[b,h,d,s]) via device globals.
static constexpr int GEMM_SMEM = 81920;

template <int EPI, int OUT>
__device__ __forceinline__ void epi_store(float v0, float v1, int r, int c,
                                          const float* R, float* C,
                                          __nv_bfloat16* Ch, __nv_bfloat16* Cl, int N) {
    if (OUT == 4) {
        int kind = c >> 10;
        int c1   = c & 1023;
        if (kind < 2) {
            size_t o2 = (((size_t)(r >> 11) * HEADS + (c1 >> 6)) * SEQ + (r & 2047)) * 64 + (c1 & 63);
            uint32_t hi, lo;
            split2_pack(v0, v1, hi, lo);
            if (kind == 0) {
                *reinterpret_cast<uint32_t*>(&g_att_qh[o2]) = hi;
                *reinterpret_cast<uint32_t*>(&g_att_ql[o2]) = lo;
            } else {
                *reinterpret_cast<uint32_t*>(&g_att_kh[o2]) = hi;
                *reinterpret_cast<uint32_t*>(&g_att_kl[o2]) = lo;
            }
        } else {
            size_t o3 = (((size_t)(r >> 11) * HEADS + (c1 >> 6)) * 64 + (c1 & 63)) * SEQ + (r & 2047);
            __nv_bfloat16 h0, l0, h1, l1;
            split_bf16(v0, h0, l0); split_bf16(v1, h1, l1);
            g_att_vh[o3] = h0; g_att_vl[o3] = l0;
            g_att_vh[o3 + SEQ] = h1; g_att_vl[o3 + SEQ] = l1;
        }
        return;
    }
    size_t off = (size_t)r * N + c;
    if (EPI == 1) { float2 rr = *reinterpret_cast<const float2*>(&R[off]); v0 += rr.x; v1 += rr.y; }
    if (EPI == 2) { v0 = gelu_exact(v0); v1 = gelu_exact(v1); }
    if (OUT == 0) {
        float2 o; o.x = v0; o.y = v1;
        *reinterpret_cast<float2*>(&C[off]) = o;
    } else {
        uint32_t hi, lo;
        split2_pack(v0, v1, hi, lo);
        *reinterpret_cast<uint32_t*>(&Ch[off]) = hi;
        *reinterpret_cast<uint32_t*>(&Cl[off]) = lo;
    }
}

__device__ __forceinline__ void gemm_load_stage(
    uint32_t smem_base, int stage,
    const __nv_bfloat16* Ah, const __nv_bfloat16* Al,
    const __nv_bfloat16* Bh, const __nv_bfloat16* Bl,
    int row0, int col0, int K, int k0, int tid) {
    uint32_t sb = smem_base + (uint32_t)stage * 40960u;
#pragma unroll
    for (int i = 0; i < 8; i++) {
        int idx = i * 256 + tid;
        int arr = idx >> 9;
        int pos = idx & 511;
        int r   = pos >> 2;
        int c8  = pos & 3;
        uint32_t dst = sb + (uint32_t)(arr * 10240 + r * 80 + c8 * 16);
        const __nv_bfloat16* src;
        if (arr == 0)      src = &Ah[(size_t)(row0 + r) * K + k0 + c8 * 8];
        else if (arr == 1) src = &Al[(size_t)(row0 + r) * K + k0 + c8 * 8];
        else if (arr == 2) src = &Bh[(size_t)(col0 + r) * K + k0 + c8 * 8];
        else               src = &Bl[(size_t)(col0 + r) * K + k0 + c8 * 8];
        CP_ASYNC16(dst, src);
    }
}

template <int EPI, int OUT>
__global__ void __launch_bounds__(256) gemm_mma(
    const __nv_bfloat16* __restrict__ Ah, const __nv_bfloat16* __restrict__ Al,
    const __nv_bfloat16* __restrict__ Bh, const __nv_bfloat16* __restrict__ Bl,
    const float* __restrict__ bias, const float* __restrict__ R,
    float* __restrict__ C, __nv_bfloat16* __restrict__ Ch, __nv_bfloat16* __restrict__ Cl,
    int M, int N, int K) {
    extern __shared__ char dsm[];
    const int tid  = threadIdx.x;
    const int lane = tid & 31;
    const int wid  = tid >> 5;
    const int wm   = wid & 1;
    const int wn   = wid >> 1;
    const int row0 = blockIdx.y * 128;
    const int col0 = blockIdx.x * 128;
    const uint32_t smem_base = smem_u32(dsm);

    float acc[4][4][4];
#pragma unroll
    for (int i = 0; i < 4; i++)
#pragma unroll
        for (int j = 0; j < 4; j++)
#pragma unroll
            for (int k = 0; k < 4; k++) acc[i][j][k] = 0.f;

    const int nchunks = K >> 5;
    gemm_load_stage(smem_base, 0, Ah, Al, Bh, Bl, row0, col0, K, 0, tid);
    CP_COMMIT();

    for (int c = 0; c < nchunks; c++) {
        if (c + 1 < nchunks) {
            gemm_load_stage(smem_base, (c + 1) & 1, Ah, Al, Bh, Bl, row0, col0, K, (c + 1) << 5, tid);
            CP_COMMIT();
            CP_WAIT(1);
        } else {
            CP_WAIT(0);
        }
        __syncthreads();

        uint32_t sb = smem_base + (uint32_t)(c & 1) * 40960u;
#pragma unroll
        for (int ks = 0; ks < 32; ks += 16) {
            uint32_t bh[4][2], bl[4][2];
            int l2 = lane & 15;
            int rb_off = l2 & 7;
            int kb_off = ks + ((l2 >> 3) << 3);
#pragma unroll
            for (int nt = 0; nt < 4; nt++) {
                int rowb = wn * 32 + nt * 8 + rb_off;
                uint32_t ab = sb + 20480u + (uint32_t)(rowb * 80 + kb_off * 2);
                LDSM_X2(bh[nt], ab);
                LDSM_X2(bl[nt], ab + 10240u);
            }
            int ra_off = (lane & 7) + ((lane >> 3) & 1) * 8;
            int ka_off = ks + ((lane >> 4) << 3);
#pragma unroll
            for (int mt = 0; mt < 4; mt++) {
                int rowa = wm * 64 + mt * 16 + ra_off;
                uint32_t aa = sb + (uint32_t)(rowa * 80 + ka_off * 2);
                uint32_t ah[4], al[4];
                LDSM_X4(ah, aa);
                LDSM_X4(al, aa + 10240u);
#pragma unroll
                for (int nt = 0; nt < 4; nt++) {
                    mma_bf16(acc[mt][nt], ah, bh[nt]);
                    mma_bf16(acc[mt][nt], ah, bl[nt]);
                    mma_bf16(acc[mt][nt], al, bh[nt]);
                }
            }
        }
        __syncthreads();
    }

#pragma unroll
    for (int mt = 0; mt < 4; mt++) {
#pragma unroll
        for (int nt = 0; nt < 4; nt++) {
            int rg = row0 + wm * 64 + mt * 16 + (lane >> 2);
            int cg = col0 + wn * 32 + nt * 8 + (lane & 3) * 2;
            float2 b2 = *reinterpret_cast<const float2*>(&bias[cg]);
            epi_store<EPI, OUT>(acc[mt][nt][0] + b2.x, acc[mt][nt][1] + b2.y,
                                rg, cg, R, C, Ch, Cl, N);
            epi_store<EPI, OUT>(acc[mt][nt][2] + b2.x, acc[mt][nt][3] + b2.y,
                                rg + 8, cg, R, C, Ch, Cl, N);
        }
    }
}

// ---------------- tensor-core causal flash attention -----------------------
// CTA: one (b,h) x one 128-row q tile (descending order). 8 warps x 16 q rows.
// K-tiles of 64 keys. K smem: [64 keys][64 d] hi/lo, row stride 144B.
// Vt smem: [64 d][64 keys] hi/lo.
static constexpr int AT_KLO   = 18432;
static constexpr int AT_VHI   = 36864;
static constexpr int AT_STAGE = 55296;
static constexpr int ATTN_SMEM = 110592;

__device__ __forceinline__ void attn_load_kv(uint32_t sb, int stage, int bh, int k0, int tid) {
    uint32_t st = sb + (uint32_t)stage * AT_STAGE;
#pragma unroll
    for (int i = 0; i < 4; i++) {
        int idx = i * 256 + tid;
        int arr = idx >> 9;
        int pos = idx & 511;
        int r   = pos >> 3;
        int c8  = pos & 7;
        uint32_t dst = st + (uint32_t)(arr * AT_KLO + r * 144 + c8 * 16);
        const __nv_bfloat16* src = (arr ? g_att_kl : g_att_kh)
            + ((size_t)bh * SEQ + k0 + r) * 64 + c8 * 8;
        CP_ASYNC16(dst, src);
    }
#pragma unroll
    for (int i = 0; i < 4; i++) {
        int idx = i * 256 + tid;
        int arr = idx >> 9;
        int pos = idx & 511;
        int r   = pos >> 3;
        int c8  = pos & 7;
        uint32_t dst = st + (uint32_t)(AT_VHI + arr * 9216 + r * 144 + c8 * 16);
        const __nv_bfloat16* src = (arr ? g_att_vl : g_att_vh)
            + ((size_t)bh * 64 + r) * SEQ + k0 + c8 * 8;
        CP_ASYNC16(dst, src);
    }
}

__global__ void __launch_bounds__(256) attn_mma() {
    extern __shared__ char smbuf[];
    const int qt  = gridDim.x - 1 - blockIdx.x;   // descending work size first
    const int bh  = blockIdx.y;
    const int q0  = qt * 128;
    const int tid = threadIdx.x;
    const int lane = tid & 31;
    const int w    = tid >> 5;
    const uint32_t sb = smem_u32(smbuf);

    // ---- stage Q tile [128 x 64] hi/lo into stage-0 K region, extract frags
#pragma unroll
    for (int i = 0; i < 8; i++) {
        int idx = i * 256 + tid;
        int arr = idx >> 10;
        int pos = idx & 1023;
        int r   = pos >> 3;
        int c8  = pos & 7;
        uint32_t dst = sb + (uint32_t)(arr * AT_KLO + r * 144 + c8 * 16);
        const __nv_bfloat16* src = (arr ? g_att_ql : g_att_qh)
            + ((size_t)bh * SEQ + q0 + r) * 64 + c8 * 8;
        CP_ASYNC16(dst, src);
    }
    CP_COMMIT(); CP_WAIT(0); __syncthreads();

    uint32_t qh[4][4], ql[4][4];
    {
        int ra = (lane & 7) + ((lane >> 3) & 1) * 8;
#pragma unroll
        for (int kc = 0; kc < 4; kc++) {
            int ka = kc * 16 + ((lane >> 4) << 3);
            uint32_t addr = sb + (uint32_t)((w * 16 + ra) * 144 + ka * 2);
            LDSM_X4(qh[kc], addr);
            LDSM_X4(ql[kc], addr + AT_KLO);
        }
    }
    __syncthreads();

    float m0 = -1e30f, m1 = -1e30f, l0 = 0.f, l1 = 0.f;
    float o[8][4];
#pragma unroll
    for (int nt = 0; nt < 8; nt++)
#pragma unroll
        for (int j = 0; j < 4; j++) o[nt][j] = 0.f;

    const int nkt = 2 * qt + 2;
    attn_load_kv(sb, 0, bh, 0, tid);
    CP_COMMIT();

    const int l2 = lane & 15;
    const int rb = l2 & 7;
    const int kb = (l2 >> 3) << 3;

    for (int kt = 0; kt < nkt; kt++) {
        if (kt + 1 < nkt) {
            attn_load_kv(sb, (kt + 1) & 1, bh, (kt + 1) * 64, tid);
            CP_COMMIT();
            CP_WAIT(1);
        } else {
            CP_WAIT(0);
        }
        __syncthreads();

        uint32_t st = sb + (uint32_t)(kt & 1) * AT_STAGE;
        const int k0 = kt * 64;

        // warp fully above the causal boundary for this tile -> exact no-op
        if (k0 <= q0 + w * 16 + 15) {
            // ---- scores S = Q K^T (3-term split)
            float s[8][4];
#pragma unroll
            for (int nt = 0; nt < 8; nt++)
#pragma unroll
                for (int j = 0; j < 4; j++) s[nt][j] = 0.f;
#pragma unroll
            for (int kc = 0; kc < 4; kc++) {
#pragma unroll
                for (int nt = 0; nt < 8; nt++) {
                    uint32_t kaddr = st + (uint32_t)((nt * 8 + rb) * 144 + (kc * 16 + kb) * 2);
                    uint32_t kfh[2], kfl[2];
                    LDSM_X2(kfh, kaddr);
                    LDSM_X2(kfl, kaddr + AT_KLO);
                    mma_bf16(s[nt], qh[kc], kfh);
                    mma_bf16(s[nt], ql[kc], kfh);
                    mma_bf16(s[nt], qh[kc], kfl);
                }
            }

            // ---- scale + causal mask
            const int r0 = q0 + w * 16 + (lane >> 2);
#pragma unroll
            for (int nt = 0; nt < 8; nt++)
#pragma unroll
                for (int j = 0; j < 4; j++) s[nt][j] *= 0.125f;
            if (k0 + 63 > q0 + w * 16) {
#pragma unroll
                for (int nt = 0; nt < 8; nt++)
#pragma unroll
                    for (int j = 0; j < 4; j++) {
                        int col = k0 + nt * 8 + (lane & 3) * 2 + (j & 1);
                        int row = r0 + ((j >> 1) << 3);
                        if (col > row) s[nt][j] = -1e30f;
                    }
            }

            // ---- online softmax (rows r0 and r0+8)
            float mx0 = -1e30f, mx1 = -1e30f;
#pragma unroll
            for (int nt = 0; nt < 8; nt++) {
                mx0 = fmaxf(mx0, fmaxf(s[nt][0], s[nt][1]));
                mx1 = fmaxf(mx1, fmaxf(s[nt][2], s[nt][3]));
            }
            mx0 = fmaxf(mx0, __shfl_xor_sync(0xffffffffu, mx0, 1));
            mx0 = fmaxf(mx0, __shfl_xor_sync(0xffffffffu, mx0, 2));
            mx1 = fmaxf(mx1, __shfl_xor_sync(0xffffffffu, mx1, 1));
            mx1 = fmaxf(mx1, __shfl_xor_sync(0xffffffffu, mx1, 2));
            float mn0 = fmaxf(m0, mx0), mn1 = fmaxf(m1, mx1);
            float a0 = __expf(m0 - mn0), a1 = __expf(m1 - mn1);
            float rl0 = 0.f, rl1 = 0.f;
#pragma unroll
            for (int nt = 0; nt < 8; nt++) {
                s[nt][0] = __expf(s[nt][0] - mn0); rl0 += s[nt][0];
                s[nt][1] = __expf(s[nt][1] - mn0); rl0 += s[nt][1];
                s[nt][2] = __expf(s[nt][2] - mn1); rl1 += s[nt][2];
                s[nt][3] = __expf(s[nt][3] - mn1); rl1 += s[nt][3];
            }
            rl0 += __shfl_xor_sync(0xffffffffu, rl0, 1);
            rl0 += __shfl_xor_sync(0xffffffffu, rl0, 2);
            rl1 += __shfl_xor_sync(0xffffffffu, rl1, 1);
            rl1 += __shfl_xor_sync(0xffffffffu, rl1, 2);
            l0 = l0 * a0 + rl0;
            l1 = l1 * a1 + rl1;
            m0 = mn0; m1 = mn1;
#pragma unroll
            for (int nt = 0; nt < 8; nt++) {
                o[nt][0] *= a0; o[nt][1] *= a0;
                o[nt][2] *= a1; o[nt][3] *= a1;
            }

            // ---- O += P V (3-term split; P frags from acc via register remap)
#pragma unroll
            for (int kc = 0; kc < 4; kc++) {
                uint32_t pah[4], pal[4];
                split2_pack(s[2 * kc][0],     s[2 * kc][1],     pah[0], pal[0]);
                split2_pack(s[2 * kc][2],     s[2 * kc][3],     pah[1], pal[1]);
                split2_pack(s[2 * kc + 1][0], s[2 * kc + 1][1], pah[2], pal[2]);
                split2_pack(s[2 * kc + 1][2], s[2 * kc + 1][3], pah[3], pal[3]);
#pragma unroll
                for (int nt = 0; nt < 8; nt++) {
                    uint32_t vaddr = st + (uint32_t)(AT_VHI + (nt * 8 + rb) * 144 + (kc * 16 + kb) * 2);
                    uint32_t vfh[2], vfl[2];
                    LDSM_X2(vfh, vaddr);
                    LDSM_X2(vfl, vaddr + 9216);
                    mma_bf16(o[nt], pah, vfh);
                    mma_bf16(o[nt], pal, vfh);
                    mma_bf16(o[nt], pah, vfl);
                }
            }
        }
        __syncthreads();
    }

    // ---- write y (row-major [ROWS][EMBED] bf16 hi/lo)
    const float i0 = 1.f / l0, i1 = 1.f / l1;
    const int b = bh >> 4, h = bh & 15;
    const int rowg = b * SEQ + q0 + w * 16 + (lane >> 2);
#pragma unroll
    for (int nt = 0; nt < 8; nt++) {
        int colg = h * 64 + nt * 8 + (lane & 3) * 2;
        size_t off0 = (size_t)rowg * EMBED + colg;
        size_t off1 = off0 + (size_t)8 * EMBED;
        uint32_t hi, lo;
        split2_pack(o[nt][0] * i0, o[nt][1] * i0, hi, lo);
        *reinterpret_cast<uint32_t*>(&g_y_hi[off0]) = hi;
        *reinterpret_cast<uint32_t*>(&g_y_lo[off0]) = lo;
        split2_pack(o[nt][2] * i1, o[nt][3] * i1, hi, lo);
        *reinterpret_cast<uint32_t*>(&g_y_hi[off1]) = hi;
        *reinterpret_cast<uint32_t*>(&g_y_lo[off1]) = lo;
    }
}

// ---------------- launch ---------------------------------------------------
extern "C" void kernel_launch(void* const* d_in, const int* in_sizes, int n_in,
                              void* d_out, int out_size) {
    const float* x     = (const float*)d_in[0];
    const float* Wq    = (const float*)d_in[1];
    const float* bq    = (const float*)d_in[2];
    const float* Wk    = (const float*)d_in[3];
    const float* bk    = (const float*)d_in[4];
    const float* Wv    = (const float*)d_in[5];
    const float* bv    = (const float*)d_in[6];
    const float* Wo    = (const float*)d_in[7];
    const float* bo    = (const float*)d_in[8];
    const float* g1    = (const float*)d_in[9];
    const float* beta1 = (const float*)d_in[10];
    const float* g2    = (const float*)d_in[11];
    const float* beta2 = (const float*)d_in[12];
    const float* W1    = (const float*)d_in[13];
    const float* b1    = (const float*)d_in[14];
    const float* W2    = (const float*)d_in[15];
    const float* b2    = (const float*)d_in[16];
    float* out = (float*)d_out;

    float* px1;
    cudaGetSymbolAddress((void**)&px1, g_x1);
    __nv_bfloat16 *phh, *phl, *pyh, *pyl, *ph2h, *ph2l, *pfh, *pfl;
    cudaGetSymbolAddress((void**)&phh,  g_h_hi);  cudaGetSymbolAddress((void**)&phl,  g_h_lo);
    cudaGetSymbolAddress((void**)&pyh,  g_y_hi);  cudaGetSymbolAddress((void**)&pyl,  g_y_lo);
    cudaGetSymbolAddress((void**)&ph2h, g_h2_hi); cudaGetSymbolAddress((void**)&ph2l, g_h2_lo);
    cudaGetSymbolAddress((void**)&pfh,  g_f_hi);  cudaGetSymbolAddress((void**)&pfl,  g_f_lo);
    __nv_bfloat16 *wqkvh, *wqkvl, *woh, *wol, *w1h, *w1l, *w2h, *w2l;
    float* pbqkv;
    cudaGetSymbolAddress((void**)&wqkvh, g_wqkv_hi); cudaGetSymbolAddress((void**)&wqkvl, g_wqkv_lo);
    cudaGetSymbolAddress((void**)&pbqkv, g_bqkv);
    cudaGetSymbolAddress((void**)&woh, g_wo_hi); cudaGetSymbolAddress((void**)&wol, g_wo_lo);
    cudaGetSymbolAddress((void**)&w1h, g_w1_hi); cudaGetSymbolAddress((void**)&w1l, g_w1_lo);
    cudaGetSymbolAddress((void**)&w2h, g_w2_hi); cudaGetSymbolAddress((void**)&w2l, g_w2_lo);

    cudaFuncSetAttribute(gemm_mma<0, 4>, cudaFuncAttributeMaxDynamicSharedMemorySize, GEMM_SMEM);
    cudaFuncSetAttribute(gemm_mma<1, 0>, cudaFuncAttributeMaxDynamicSharedMemorySize, GEMM_SMEM);
    cudaFuncSetAttribute(gemm_mma<2, 1>, cudaFuncAttributeMaxDynamicSharedMemorySize, GEMM_SMEM);
    cudaFuncSetAttribute(attn_mma, cudaFuncAttributeMaxDynamicSharedMemorySize, ATTN_SMEM);

    dim3 t256(256);
    // weight prep: QKV into combined [3072,1024] buffer, then Wo, W1, W2
    transpose_split<<<dim3(EMBED / 32, EMBED / 32), t256>>>(Wq, wqkvh, wqkvl, EMBED, EMBED);
    transpose_split<<<dim3(EMBED / 32, EMBED / 32), t256>>>(Wk, wqkvh + EMBED * EMBED, wqkvl + EMBED * EMBED, EMBED, EMBED);
    transpose_split<<<dim3(EMBED / 32, EMBED / 32), t256>>>(Wv, wqkvh + 2 * EMBED * EMBED, wqkvl + 2 * EMBED * EMBED, EMBED, EMBED);
    transpose_split<<<dim3(EMBED / 32, EMBED / 32), t256>>>(Wo, woh, wol, EMBED, EMBED);
    transpose_split<<<dim3(FFDIM / 32, EMBED / 32), t256>>>(W1, w1h, w1l, EMBED, FFDIM);
    transpose_split<<<dim3(EMBED / 32, FFDIM / 32), t256>>>(W2, w2h, w2l, FFDIM, EMBED);
    concat_bias<<<4, t256>>>(bq, bk, bv);

    // LN1
    ln_kernel<<<ROWS, t256>>>(x, g1, beta1, phh, phl);

    // fused QKV projection (N=3072) straight into attention layouts
    dim3 gqkv(3 * EMBED / 128, ROWS / 128);
    gemm_mma<0, 4><<<gqkv, t256, GEMM_SMEM>>>(phh, phl, wqkvh, wqkvl, pbqkv, nullptr,
                                              nullptr, nullptr, nullptr, ROWS, 3 * EMBED, EMBED);

    // tensor-core flash attention
    attn_mma<<<dim3(SEQ / 128, BATCH * HEADS), t256, ATTN_SMEM>>>();

    // x1 = x + y @ Wo + bo
    dim3 g1024(EMBED / 128, ROWS / 128);
    gemm_mma<1, 0><<<g1024, t256, GEMM_SMEM>>>(pyh, pyl, woh, wol, bo, x, px1, nullptr, nullptr, ROWS, EMBED, EMBED);
    // LN2
    ln_kernel<<<ROWS, t256>>>(px1, g2, beta2, ph2h, ph2l);
    // f = gelu(h2 @ W1 + b1)
    dim3 gff(FFDIM / 128, ROWS / 128);
    gemm_mma<2, 1><<<gff, t256, GEMM_SMEM>>>(ph2h, ph2l, w1h, w1l, b1, nullptr, nullptr, pfh, pfl, ROWS, FFDIM, EMBED);
    // out = x1 + f @ W2 + b2
    gemm_mma<1, 0><<<g1024, t256, GEMM_SMEM>>>(pfh, pfl, w2h, w2l, b2, px1, out, nullptr, nullptr, ROWS, EMBED, FFDIM);
}

// round 11
// speedup vs baseline: 6.3112x; 1.1349x over previous
#include <cuda_runtime.h>
#include <cuda_bf16.h>
#include <math.h>
#include <stdint.h>

#define EMBED 1024
#define HEADS 16
#define HEAD_DIM 64
#define BATCH 4
#define SEQ 2048
#define FFDIM 4096
#define ROWS (BATCH * SEQ) /* 8192 */

// ---------------- scratch (device globals; allocation-free) ----------------
__device__ float g_x1[ROWS * EMBED];
__device__ __nv_bfloat16 g_h_hi[ROWS * EMBED],  g_h_lo[ROWS * EMBED];
__device__ __nv_bfloat16 g_y_hi[ROWS * EMBED],  g_y_lo[ROWS * EMBED];
__device__ __nv_bfloat16 g_h2_hi[ROWS * EMBED], g_h2_lo[ROWS * EMBED];
__device__ __nv_bfloat16 g_f_hi[ROWS * FFDIM],  g_f_lo[ROWS * FFDIM];
// attention operands: Q,K head-major [b,h,s,d]; V transposed [b,h,d,s]
__device__ __nv_bfloat16 g_att_qh[ROWS * EMBED], g_att_ql[ROWS * EMBED];
__device__ __nv_bfloat16 g_att_kh[ROWS * EMBED], g_att_kl[ROWS * EMBED];
__device__ __nv_bfloat16 g_att_vh[ROWS * EMBED], g_att_vl[ROWS * EMBED];
// pre-transposed weights [N,K] bf16 hi/lo
__device__ __nv_bfloat16 g_wqkv_hi[3 * EMBED * EMBED], g_wqkv_lo[3 * EMBED * EMBED];
__device__ float         g_bqkv[3 * EMBED];
__device__ __nv_bfloat16 g_wo_hi[EMBED * EMBED], g_wo_lo[EMBED * EMBED];
__device__ __nv_bfloat16 g_w1_hi[EMBED * FFDIM], g_w1_lo[EMBED * FFDIM];
__device__ __nv_bfloat16 g_w2_hi[FFDIM * EMBED], g_w2_lo[FFDIM * EMBED];

// ---------------- helpers ----------------
__device__ __forceinline__ uint32_t smem_u32(const void* p) {
    uint32_t a;
    asm("{ .reg .u64 t; cvta.to.shared.u64 t, %1; cvt.u32.u64 %0, t; }" : "=r"(a) : "l"(p));
    return a;
}
__device__ __forceinline__ void split_bf16(float x, __nv_bfloat16& h, __nv_bfloat16& l) {
    h = __float2bfloat16(x);
    l = __float2bfloat16(x - __bfloat162float(h));
}
__device__ __forceinline__ void split2_pack(float a, float b, uint32_t& hi, uint32_t& lo) {
    __nv_bfloat16 ah, al, bh, bl;
    split_bf16(a, ah, al); split_bf16(b, bh, bl);
    __nv_bfloat162 H; H.x = ah; H.y = bh;
    __nv_bfloat162 L; L.x = al; L.y = bl;
    hi = *reinterpret_cast<uint32_t*>(&H);
    lo = *reinterpret_cast<uint32_t*>(&L);
}
__device__ __forceinline__ float gelu_exact(float x) {
    return 0.5f * x * (1.0f + erff(x * 0.70710678118654752f));
}

#define CP_ASYNC16(dst, src) \
    asm volatile("cp.async.cg.shared.global [%0], [%1], 16;" :: "r"(dst), "l"(src))
#define CP_COMMIT()  asm volatile("cp.async.commit_group;" ::: "memory")
#define CP_WAIT(n)   asm volatile("cp.async.wait_group %0;" :: "n"(n) : "memory")

__device__ __forceinline__ void mma_bf16(float* c, const uint32_t* a, const uint32_t* b) {
    asm volatile(
        "mma.sync.aligned.m16n8k16.row.col.f32.bf16.bf16.f32 "
        "{%0,%1,%2,%3},{%4,%5,%6,%7},{%8,%9},{%0,%1,%2,%3};"
        : "+f"(c[0]), "+f"(c[1]), "+f"(c[2]), "+f"(c[3])
        : "r"(a[0]), "r"(a[1]), "r"(a[2]), "r"(a[3]), "r"(b[0]), "r"(b[1]));
}
#define LDSM_X4(r, addr) \
    asm volatile("ldmatrix.sync.aligned.m8n8.x4.shared.b16 {%0,%1,%2,%3}, [%4];" \
                 : "=r"((r)[0]), "=r"((r)[1]), "=r"((r)[2]), "=r"((r)[3]) : "r"(addr))

// ---------------- weight transpose + split ----------------
__global__ void __launch_bounds__(256) transpose_split(const float* __restrict__ W,
                                                       __nv_bfloat16* __restrict__ Th,
                                                       __nv_bfloat16* __restrict__ Tl,
                                                       int K, int N) {
    __shared__ float t[32][33];
    int n0 = blockIdx.x * 32, k0 = blockIdx.y * 32;
    int tx = threadIdx.x & 31, ty = threadIdx.x >> 5;
#pragma unroll
    for (int i = 0; i < 4; i++) {
        int k = ty + i * 8;
        t[k][tx] = W[(size_t)(k0 + k) * N + n0 + tx];
    }
    __syncthreads();
#pragma unroll
    for (int i = 0; i < 4; i++) {
        int r = ty + i * 8;
        float v = t[tx][r];
        __nv_bfloat16 h, l;
        split_bf16(v, h, l);
        Th[(size_t)(n0 + r) * K + k0 + tx] = h;
        Tl[(size_t)(n0 + r) * K + k0 + tx] = l;
    }
}

__global__ void __launch_bounds__(256) concat_bias(const float* __restrict__ bq,
                                                   const float* __restrict__ bk,
                                                   const float* __restrict__ bv) {
    int i = blockIdx.x * 256 + threadIdx.x;  // 0..1023
    g_bqkv[i]        = bq[i];
    g_bqkv[i + 1024] = bk[i];
    g_bqkv[i + 2048] = bv[i];
}

// ---------------- LayerNorm ----------------
__global__ void __launch_bounds__(256) ln_kernel(const float* __restrict__ X,
                                                 const float* __restrict__ gam,
                                                 const float* __restrict__ bet,
                                                 __nv_bfloat16* __restrict__ Yh,
                                                 __nv_bfloat16* __restrict__ Yl) {
    int row = blockIdx.x;
    int tid = threadIdx.x;
    const float* xr = X + (size_t)row * EMBED;
    float4 v = *reinterpret_cast<const float4*>(&xr[tid * 4]);
    float s  = v.x + v.y + v.z + v.w;
    float sq = v.x * v.x + v.y * v.y + v.z * v.z + v.w * v.w;
#pragma unroll
    for (int o = 16; o; o >>= 1) {
        s  += __shfl_xor_sync(0xffffffffu, s, o);
        sq += __shfl_xor_sync(0xffffffffu, sq, o);
    }
    __shared__ float ss[8], sqs[8];
    int w = tid >> 5;
    if ((tid & 31) == 0) { ss[w] = s; sqs[w] = sq; }
    __syncthreads();
    s = 0.f; sq = 0.f;
#pragma unroll
    for (int i = 0; i < 8; i++) { s += ss[i]; sq += sqs[i]; }
    float mu  = s * (1.0f / EMBED);
    float var = sq * (1.0f / EMBED) - mu * mu;
    float inv = rsqrtf(var + 1e-5f);
    float4 gv = *reinterpret_cast<const float4*>(&gam[tid * 4]);
    float4 bv = *reinterpret_cast<const float4*>(&bet[tid * 4]);
    float o0 = (v.x - mu) * inv * gv.x + bv.x;
    float o1 = (v.y - mu) * inv * gv.y + bv.y;
    float o2 = (v.z - mu) * inv * gv.z + bv.z;
    float o3 = (v.w - mu) * inv * gv.w + bv.w;
    size_t base = (size_t)row * EMBED + tid * 4;
    uint32_t h0, l0, h1, l1;
    split2_pack(o0, o1, h0, l0);
    split2_pack(o2, o3, h1, l1);
    *reinterpret_cast<uint32_t*>(&Yh[base])     = h0;
    *reinterpret_cast<uint32_t*>(&Yh[base + 2]) = h1;
    *reinterpret_cast<uint32_t*>(&Yl[base])     = l0;
    *reinterpret_cast<uint32_t*>(&Yl[base + 2]) = l1;
}

// ---------------- mma.sync GEMM (split-bf16 fp32 emulation) ----------------
// EPI: 0=bias  1=bias+residual  2=bias+GELU
// OUT: 0=fp32 row-major  1=bf16 hi/lo row-major  4=fused QKV (c<1024 Q[b,h,s,d],
//      <2048 K[b,h,s,d], else V[b,h,d,s]) via device globals.
static constexpr int GEMM_SMEM = 81920;

template <int EPI, int OUT>
__device__ __forceinline__ void epi_store(float v0, float v1, int r, int c,
                                          const float* R, float* C,
                                          __nv_bfloat16* Ch, __nv_bfloat16* Cl, int N) {
    if (OUT == 4) {
        int kind = c >> 10;
        int c1   = c & 1023;
        if (kind < 2) {
            size_t o2 = (((size_t)(r >> 11) * HEADS + (c1 >> 6)) * SEQ + (r & 2047)) * 64 + (c1 & 63);
            uint32_t hi, lo;
            split2_pack(v0, v1, hi, lo);
            if (kind == 0) {
                *reinterpret_cast<uint32_t*>(&g_att_qh[o2]) = hi;
                *reinterpret_cast<uint32_t*>(&g_att_ql[o2]) = lo;
            } else {
                *reinterpret_cast<uint32_t*>(&g_att_kh[o2]) = hi;
                *reinterpret_cast<uint32_t*>(&g_att_kl[o2]) = lo;
            }
        } else {
            size_t o3 = (((size_t)(r >> 11) * HEADS + (c1 >> 6)) * 64 + (c1 & 63)) * SEQ + (r & 2047);
            __nv_bfloat16 h0, l0, h1, l1;
            split_bf16(v0, h0, l0); split_bf16(v1, h1, l1);
            g_att_vh[o3] = h0; g_att_vl[o3] = l0;
            g_att_vh[o3 + SEQ] = h1; g_att_vl[o3 + SEQ] = l1;
        }
        return;
    }
    size_t off = (size_t)r * N + c;
    if (EPI == 1) { float2 rr = *reinterpret_cast<const float2*>(&R[off]); v0 += rr.x; v1 += rr.y; }
    if (EPI == 2) { v0 = gelu_exact(v0); v1 = gelu_exact(v1); }
    if (OUT == 0) {
        float2 o; o.x = v0; o.y = v1;
        *reinterpret_cast<float2*>(&C[off]) = o;
    } else {
        uint32_t hi, lo;
        split2_pack(v0, v1, hi, lo);
        *reinterpret_cast<uint32_t*>(&Ch[off]) = hi;
        *reinterpret_cast<uint32_t*>(&Cl[off]) = lo;
    }
}

__device__ __forceinline__ void gemm_load_stage(
    uint32_t smem_base, int stage,
    const __nv_bfloat16* Ah, const __nv_bfloat16* Al,
    const __nv_bfloat16* Bh, const __nv_bfloat16* Bl,
    int row0, int col0, int K, int k0, int tid) {
    uint32_t sb = smem_base + (uint32_t)stage * 40960u;
#pragma unroll
    for (int i = 0; i < 8; i++) {
        int idx = i * 256 + tid;
        int arr = idx >> 9;
        int pos = idx & 511;
        int r   = pos >> 2;
        int c8  = pos & 3;
        uint32_t dst = sb + (uint32_t)(arr * 10240 + r * 80 + c8 * 16);
        const __nv_bfloat16* src;
        if (arr == 0)      src = &Ah[(size_t)(row0 + r) * K + k0 + c8 * 8];
        else if (arr == 1) src = &Al[(size_t)(row0 + r) * K + k0 + c8 * 8];
        else if (arr == 2) src = &Bh[(size_t)(col0 + r) * K + k0 + c8 * 8];
        else               src = &Bl[(size_t)(col0 + r) * K + k0 + c8 * 8];
        CP_ASYNC16(dst, src);
    }
}

template <int EPI, int OUT>
__global__ void __launch_bounds__(256, 2) gemm_mma(
    const __nv_bfloat16* __restrict__ Ah, const __nv_bfloat16* __restrict__ Al,
    const __nv_bfloat16* __restrict__ Bh, const __nv_bfloat16* __restrict__ Bl,
    const float* __restrict__ bias, const float* __restrict__ R,
    float* __restrict__ C, __nv_bfloat16* __restrict__ Ch, __nv_bfloat16* __restrict__ Cl,
    int M, int N, int K) {
    extern __shared__ char dsm[];
    const int tid  = threadIdx.x;
    const int lane = tid & 31;
    const int wid  = tid >> 5;
    const int wm   = wid & 1;
    const int wn   = wid >> 1;
    const int row0 = blockIdx.y * 128;
    const int col0 = blockIdx.x * 128;
    const uint32_t smem_base = smem_u32(dsm);

    float acc[4][4][4];
#pragma unroll
    for (int i = 0; i < 4; i++)
#pragma unroll
        for (int j = 0; j < 4; j++)
#pragma unroll
            for (int k = 0; k < 4; k++) acc[i][j][k] = 0.f;

    const int nchunks = K >> 5;
    gemm_load_stage(smem_base, 0, Ah, Al, Bh, Bl, row0, col0, K, 0, tid);
    CP_COMMIT();

    // x4 B-fragment addressing: tile t = lane>>3; rows (t>>1)*8 + lane&7, k (t&1)*8
    const int tb      = lane >> 3;
    const int rb4_off = ((tb >> 1) << 3) + (lane & 7);
    const int kb4_off = (tb & 1) << 3;
    const int ra_off  = (lane & 7) + ((lane >> 3) & 1) * 8;

    for (int c = 0; c < nchunks; c++) {
        if (c + 1 < nchunks) {
            gemm_load_stage(smem_base, (c + 1) & 1, Ah, Al, Bh, Bl, row0, col0, K, (c + 1) << 5, tid);
            CP_COMMIT();
            CP_WAIT(1);
        } else {
            CP_WAIT(0);
        }
        __syncthreads();

        uint32_t sb = smem_base + (uint32_t)(c & 1) * 40960u;
#pragma unroll
        for (int ks = 0; ks < 32; ks += 16) {
            uint32_t bh[4][2], bl[4][2];
#pragma unroll
            for (int np = 0; np < 2; np++) {   // nt pair (2np, 2np+1)
                int rowb = wn * 32 + np * 16 + rb4_off;
                uint32_t ab = sb + 20480u + (uint32_t)(rowb * 80 + (ks + kb4_off) * 2);
                uint32_t r4[4];
                LDSM_X4(r4, ab);
                bh[np * 2][0] = r4[0]; bh[np * 2][1] = r4[1];
                bh[np * 2 + 1][0] = r4[2]; bh[np * 2 + 1][1] = r4[3];
                LDSM_X4(r4, ab + 10240u);
                bl[np * 2][0] = r4[0]; bl[np * 2][1] = r4[1];
                bl[np * 2 + 1][0] = r4[2]; bl[np * 2 + 1][1] = r4[3];
            }
            int ka_off = ks + ((lane >> 4) << 3);
#pragma unroll
            for (int mt = 0; mt < 4; mt++) {
                int rowa = wm * 64 + mt * 16 + ra_off;
                uint32_t aa = sb + (uint32_t)(rowa * 80 + ka_off * 2);
                uint32_t ah[4], al[4];
                LDSM_X4(ah, aa);
                LDSM_X4(al, aa + 10240u);
#pragma unroll
                for (int nt = 0; nt < 4; nt++) {
                    mma_bf16(acc[mt][nt], ah, bh[nt]);
                    mma_bf16(acc[mt][nt], ah, bl[nt]);
                    mma_bf16(acc[mt][nt], al, bh[nt]);
                }
            }
        }
        __syncthreads();
    }

#pragma unroll
    for (int mt = 0; mt < 4; mt++) {
#pragma unroll
        for (int nt = 0; nt < 4; nt++) {
            int rg = row0 + wm * 64 + mt * 16 + (lane >> 2);
            int cg = col0 + wn * 32 + nt * 8 + (lane & 3) * 2;
            float2 b2 = *reinterpret_cast<const float2*>(&bias[cg]);
            epi_store<EPI, OUT>(acc[mt][nt][0] + b2.x, acc[mt][nt][1] + b2.y,
                                rg, cg, R, C, Ch, Cl, N);
            epi_store<EPI, OUT>(acc[mt][nt][2] + b2.x, acc[mt][nt][3] + b2.y,
                                rg + 8, cg, R, C, Ch, Cl, N);
        }
    }
}

// ---------------- tensor-core causal flash attention -----------------------
// CTA: one (b,h) x one 128-row q tile (descending order). 8 warps x 16 q rows.
// K-tiles of 64 keys. K smem: [64 keys][64 d] hi/lo, row stride 144B.
// Vt smem: [64 d][64 keys] hi/lo.
static constexpr int AT_KLO   = 18432;
static constexpr int AT_VHI   = 36864;
static constexpr int AT_STAGE = 55296;
static constexpr int ATTN_SMEM = 110592;

__device__ __forceinline__ void attn_load_kv(uint32_t sb, int stage, int bh, int k0, int tid) {
    uint32_t st = sb + (uint32_t)stage * AT_STAGE;
#pragma unroll
    for (int i = 0; i < 4; i++) {
        int idx = i * 256 + tid;
        int arr = idx >> 9;
        int pos = idx & 511;
        int r   = pos >> 3;
        int c8  = pos & 7;
        uint32_t dst = st + (uint32_t)(arr * AT_KLO + r * 144 + c8 * 16);
        const __nv_bfloat16* src = (arr ? g_att_kl : g_att_kh)
            + ((size_t)bh * SEQ + k0 + r) * 64 + c8 * 8;
        CP_ASYNC16(dst, src);
    }
#pragma unroll
    for (int i = 0; i < 4; i++) {
        int idx = i * 256 + tid;
        int arr = idx >> 9;
        int pos = idx & 511;
        int r   = pos >> 3;
        int c8  = pos & 7;
        uint32_t dst = st + (uint32_t)(AT_VHI + arr * 9216 + r * 144 + c8 * 16);
        const __nv_bfloat16* src = (arr ? g_att_vl : g_att_vh)
            + ((size_t)bh * 64 + r) * SEQ + k0 + c8 * 8;
        CP_ASYNC16(dst, src);
    }
}

__global__ void __launch_bounds__(256, 2) attn_mma() {
    extern __shared__ char smbuf[];
    const int qt  = gridDim.x - 1 - blockIdx.x;   // descending work size first
    const int bh  = blockIdx.y;
    const int q0  = qt * 128;
    const int tid = threadIdx.x;
    const int lane = tid & 31;
    const int w    = tid >> 5;
    const uint32_t sb = smem_u32(smbuf);

    // ---- stage Q tile [128 x 64] hi/lo into stage-0 K region, extract frags
#pragma unroll
    for (int i = 0; i < 8; i++) {
        int idx = i * 256 + tid;
        int arr = idx >> 10;
        int pos = idx & 1023;
        int r   = pos >> 3;
        int c8  = pos & 7;
        uint32_t dst = sb + (uint32_t)(arr * AT_KLO + r * 144 + c8 * 16);
        const __nv_bfloat16* src = (arr ? g_att_ql : g_att_qh)
            + ((size_t)bh * SEQ + q0 + r) * 64 + c8 * 8;
        CP_ASYNC16(dst, src);
    }
    CP_COMMIT(); CP_WAIT(0); __syncthreads();

    uint32_t qh[4][4], ql[4][4];
    {
        int ra = (lane & 7) + ((lane >> 3) & 1) * 8;
#pragma unroll
        for (int kc = 0; kc < 4; kc++) {
            int ka = kc * 16 + ((lane >> 4) << 3);
            uint32_t addr = sb + (uint32_t)((w * 16 + ra) * 144 + ka * 2);
            LDSM_X4(qh[kc], addr);
            LDSM_X4(ql[kc], addr + AT_KLO);
        }
    }
    __syncthreads();

    float m0 = -1e30f, m1 = -1e30f, l0 = 0.f, l1 = 0.f;
    float o[8][4];
#pragma unroll
    for (int nt = 0; nt < 8; nt++)
#pragma unroll
        for (int j = 0; j < 4; j++) o[nt][j] = 0.f;

    const int nkt = 2 * qt + 2;
    attn_load_kv(sb, 0, bh, 0, tid);
    CP_COMMIT();

    // x4 fragment addressing for K/V (row-pair tiles)
    const int tb      = lane >> 3;
    const int rk4_off = ((tb >> 1) << 3) + (lane & 7);
    const int kk4_off = (tb & 1) << 3;

    for (int kt = 0; kt < nkt; kt++) {
        if (kt + 1 < nkt) {
            attn_load_kv(sb, (kt + 1) & 1, bh, (kt + 1) * 64, tid);
            CP_COMMIT();
            CP_WAIT(1);
        } else {
            CP_WAIT(0);
        }
        __syncthreads();

        uint32_t st = sb + (uint32_t)(kt & 1) * AT_STAGE;
        const int k0 = kt * 64;

        // warp fully above the causal boundary for this tile -> exact no-op
        if (k0 <= q0 + w * 16 + 15) {
            // ---- scores S = Q K^T (3-term split)
            float s[8][4];
#pragma unroll
            for (int nt = 0; nt < 8; nt++)
#pragma unroll
                for (int j = 0; j < 4; j++) s[nt][j] = 0.f;
#pragma unroll
            for (int kc = 0; kc < 4; kc++) {
#pragma unroll
                for (int np = 0; np < 4; np++) {  // key-tile pair (2np, 2np+1)
                    uint32_t kaddr = st + (uint32_t)((np * 16 + rk4_off) * 144 + (kc * 16 + kk4_off) * 2);
                    uint32_t kfh[4], kfl[4];
                    LDSM_X4(kfh, kaddr);
                    LDSM_X4(kfl, kaddr + AT_KLO);
                    mma_bf16(s[np * 2],     qh[kc], kfh);
                    mma_bf16(s[np * 2],     ql[kc], kfh);
                    mma_bf16(s[np * 2],     qh[kc], kfl);
                    mma_bf16(s[np * 2 + 1], qh[kc], kfh + 2);
                    mma_bf16(s[np * 2 + 1], ql[kc], kfh + 2);
                    mma_bf16(s[np * 2 + 1], qh[kc], kfl + 2);
                }
            }

            // ---- scale + causal mask
            const int r0 = q0 + w * 16 + (lane >> 2);
#pragma unroll
            for (int nt = 0; nt < 8; nt++)
#pragma unroll
                for (int j = 0; j < 4; j++) s[nt][j] *= 0.125f;
            if (k0 + 63 > q0 + w * 16) {
#pragma unroll
                for (int nt = 0; nt < 8; nt++)
#pragma unroll
                    for (int j = 0; j < 4; j++) {
                        int col = k0 + nt * 8 + (lane & 3) * 2 + (j & 1);
                        int row = r0 + ((j >> 1) << 3);
                        if (col > row) s[nt][j] = -1e30f;
                    }
            }

            // ---- online softmax (rows r0 and r0+8)
            float mx0 = -1e30f, mx1 = -1e30f;
#pragma unroll
            for (int nt = 0; nt < 8; nt++) {
                mx0 = fmaxf(mx0, fmaxf(s[nt][0], s[nt][1]));
                mx1 = fmaxf(mx1, fmaxf(s[nt][2], s[nt][3]));
            }
            mx0 = fmaxf(mx0, __shfl_xor_sync(0xffffffffu, mx0, 1));
            mx0 = fmaxf(mx0, __shfl_xor_sync(0xffffffffu, mx0, 2));
            mx1 = fmaxf(mx1, __shfl_xor_sync(0xffffffffu, mx1, 1));
            mx1 = fmaxf(mx1, __shfl_xor_sync(0xffffffffu, mx1, 2));
            float mn0 = fmaxf(m0, mx0), mn1 = fmaxf(m1, mx1);
            float a0 = __expf(m0 - mn0), a1 = __expf(m1 - mn1);
            float rl0 = 0.f, rl1 = 0.f;
#pragma unroll
            for (int nt = 0; nt < 8; nt++) {
                s[nt][0] = __expf(s[nt][0] - mn0); rl0 += s[nt][0];
                s[nt][1] = __expf(s[nt][1] - mn0); rl0 += s[nt][1];
                s[nt][2] = __expf(s[nt][2] - mn1); rl1 += s[nt][2];
                s[nt][3] = __expf(s[nt][3] - mn1); rl1 += s[nt][3];
            }
            rl0 += __shfl_xor_sync(0xffffffffu, rl0, 1);
            rl0 += __shfl_xor_sync(0xffffffffu, rl0, 2);
            rl1 += __shfl_xor_sync(0xffffffffu, rl1, 1);
            rl1 += __shfl_xor_sync(0xffffffffu, rl1, 2);
            l0 = l0 * a0 + rl0;
            l1 = l1 * a1 + rl1;
            m0 = mn0; m1 = mn1;
#pragma unroll
            for (int nt = 0; nt < 8; nt++) {
                o[nt][0] *= a0; o[nt][1] *= a0;
                o[nt][2] *= a1; o[nt][3] *= a1;
            }

            // ---- O += P V (3-term split; P frags from acc via register remap)
#pragma unroll
            for (int kc = 0; kc < 4; kc++) {
                uint32_t pah[4], pal[4];
                split2_pack(s[2 * kc][0],     s[2 * kc][1],     pah[0], pal[0]);
                split2_pack(s[2 * kc][2],     s[2 * kc][3],     pah[1], pal[1]);
                split2_pack(s[2 * kc + 1][0], s[2 * kc + 1][1], pah[2], pal[2]);
                split2_pack(s[2 * kc + 1][2], s[2 * kc + 1][3], pah[3], pal[3]);
#pragma unroll
                for (int np = 0; np < 4; np++) {  // d-tile pair (2np, 2np+1)
                    uint32_t vaddr = st + (uint32_t)(AT_VHI + (np * 16 + rk4_off) * 144 + (kc * 16 + kk4_off) * 2);
                    uint32_t vfh[4], vfl[4];
                    LDSM_X4(vfh, vaddr);
                    LDSM_X4(vfl, vaddr + 9216);
                    mma_bf16(o[np * 2],     pah, vfh);
                    mma_bf16(o[np * 2],     pal, vfh);
                    mma_bf16(o[np * 2],     pah, vfl);
                    mma_bf16(o[np * 2 + 1], pah, vfh + 2);
                    mma_bf16(o[np * 2 + 1], pal, vfh + 2);
                    mma_bf16(o[np * 2 + 1], pah, vfl + 2);
                }
            }
        }
        __syncthreads();
    }

    // ---- write y (row-major [ROWS][EMBED] bf16 hi/lo)
    const float i0 = 1.f / l0, i1 = 1.f / l1;
    const int b = bh >> 4, h = bh & 15;
    const int rowg = b * SEQ + q0 + w * 16 + (lane >> 2);
#pragma unroll
    for (int nt = 0; nt < 8; nt++) {
        int colg = h * 64 + nt * 8 + (lane & 3) * 2;
        size_t off0 = (size_t)rowg * EMBED + colg;
        size_t off1 = off0 + (size_t)8 * EMBED;
        uint32_t hi, lo;
        split2_pack(o[nt][0] * i0, o[nt][1] * i0, hi, lo);
        *reinterpret_cast<uint32_t*>(&g_y_hi[off0]) = hi;
        *reinterpret_cast<uint32_t*>(&g_y_lo[off0]) = lo;
        split2_pack(o[nt][2] * i1, o[nt][3] * i1, hi, lo);
        *reinterpret_cast<uint32_t*>(&g_y_hi[off1]) = hi;
        *reinterpret_cast<uint32_t*>(&g_y_lo[off1]) = lo;
    }
}

// ---------------- launch ---------------------------------------------------
extern "C" void kernel_launch(void* const* d_in, const int* in_sizes, int n_in,
                              void* d_out, int out_size) {
    const float* x     = (const float*)d_in[0];
    const float* Wq    = (const float*)d_in[1];
    const float* bq    = (const float*)d_in[2];
    const float* Wk    = (const float*)d_in[3];
    const float* bk    = (const float*)d_in[4];
    const float* Wv    = (const float*)d_in[5];
    const float* bv    = (const float*)d_in[6];
    const float* Wo    = (const float*)d_in[7];
    const float* bo    = (const float*)d_in[8];
    const float* g1    = (const float*)d_in[9];
    const float* beta1 = (const float*)d_in[10];
    const float* g2    = (const float*)d_in[11];
    const float* beta2 = (const float*)d_in[12];
    const float* W1    = (const float*)d_in[13];
    const float* b1    = (const float*)d_in[14];
    const float* W2    = (const float*)d_in[15];
    const float* b2    = (const float*)d_in[16];
    float* out = (float*)d_out;

    float* px1;
    cudaGetSymbolAddress((void**)&px1, g_x1);
    __nv_bfloat16 *phh, *phl, *pyh, *pyl, *ph2h, *ph2l, *pfh, *pfl;
    cudaGetSymbolAddress((void**)&phh,  g_h_hi);  cudaGetSymbolAddress((void**)&phl,  g_h_lo);
    cudaGetSymbolAddress((void**)&pyh,  g_y_hi);  cudaGetSymbolAddress((void**)&pyl,  g_y_lo);
    cudaGetSymbolAddress((void**)&ph2h, g_h2_hi); cudaGetSymbolAddress((void**)&ph2l, g_h2_lo);
    cudaGetSymbolAddress((void**)&pfh,  g_f_hi);  cudaGetSymbolAddress((void**)&pfl,  g_f_lo);
    __nv_bfloat16 *wqkvh, *wqkvl, *woh, *wol, *w1h, *w1l, *w2h, *w2l;
    float* pbqkv;
    cudaGetSymbolAddress((void**)&wqkvh, g_wqkv_hi); cudaGetSymbolAddress((void**)&wqkvl, g_wqkv_lo);
    cudaGetSymbolAddress((void**)&pbqkv, g_bqkv);
    cudaGetSymbolAddress((void**)&woh, g_wo_hi); cudaGetSymbolAddress((void**)&wol, g_wo_lo);
    cudaGetSymbolAddress((void**)&w1h, g_w1_hi); cudaGetSymbolAddress((void**)&w1l, g_w1_lo);
    cudaGetSymbolAddress((void**)&w2h, g_w2_hi); cudaGetSymbolAddress((void**)&w2l, g_w2_lo);

    cudaFuncSetAttribute(gemm_mma<0, 4>, cudaFuncAttributeMaxDynamicSharedMemorySize, GEMM_SMEM);
    cudaFuncSetAttribute(gemm_mma<1, 0>, cudaFuncAttributeMaxDynamicSharedMemorySize, GEMM_SMEM);
    cudaFuncSetAttribute(gemm_mma<2, 1>, cudaFuncAttributeMaxDynamicSharedMemorySize, GEMM_SMEM);
    cudaFuncSetAttribute(attn_mma, cudaFuncAttributeMaxDynamicSharedMemorySize, ATTN_SMEM);

    dim3 t256(256);
    // weight prep: QKV into combined [3072,1024] buffer, then Wo, W1, W2
    transpose_split<<<dim3(EMBED / 32, EMBED / 32), t256>>>(Wq, wqkvh, wqkvl, EMBED, EMBED);
    transpose_split<<<dim3(EMBED / 32, EMBED / 32), t256>>>(Wk, wqkvh + EMBED * EMBED, wqkvl + EMBED * EMBED, EMBED, EMBED);
    transpose_split<<<dim3(EMBED / 32, EMBED / 32), t256>>>(Wv, wqkvh + 2 * EMBED * EMBED, wqkvl + 2 * EMBED * EMBED, EMBED, EMBED);
    transpose_split<<<dim3(EMBED / 32, EMBED / 32), t256>>>(Wo, woh, wol, EMBED, EMBED);
    transpose_split<<<dim3(FFDIM / 32, EMBED / 32), t256>>>(W1, w1h, w1l, EMBED, FFDIM);
    transpose_split<<<dim3(EMBED / 32, FFDIM / 32), t256>>>(W2, w2h, w2l, FFDIM, EMBED);
    concat_bias<<<4, t256>>>(bq, bk, bv);

    // LN1
    ln_kernel<<<ROWS, t256>>>(x, g1, beta1, phh, phl);

    // fused QKV projection (N=3072) straight into attention layouts
    dim3 gqkv(3 * EMBED / 128, ROWS / 128);
    gemm_mma<0, 4><<<gqkv, t256, GEMM_SMEM>>>(phh, phl, wqkvh, wqkvl, pbqkv, nullptr,
                                              nullptr, nullptr, nullptr, ROWS, 3 * EMBED, EMBED);

    // tensor-core flash attention
    attn_mma<<<dim3(SEQ / 128, BATCH * HEADS), t256, ATTN_SMEM>>>();

    // x1 = x + y @ Wo + bo
    dim3 g1024(EMBED / 128, ROWS / 128);
    gemm_mma<1, 0><<<g1024, t256, GEMM_SMEM>>>(pyh, pyl, woh, wol, bo, x, px1, nullptr, nullptr, ROWS, EMBED, EMBED);
    // LN2
    ln_kernel<<<ROWS, t256>>>(px1, g2, beta2, ph2h, ph2l);
    // f = gelu(h2 @ W1 + b1)
    dim3 gff(FFDIM / 128, ROWS / 128);
    gemm_mma<2, 1><<<gff, t256, GEMM_SMEM>>>(ph2h, ph2l, w1h, w1l, b1, nullptr, nullptr, pfh, pfl, ROWS, FFDIM, EMBED);
    // out = x1 + f @ W2 + b2
    gemm_mma<1, 0><<<g1024, t256, GEMM_SMEM>>>(pfh, pfl, w2h, w2l, b2, px1, out, nullptr, nullptr, ROWS, EMBED, FFDIM);
}

// round 12
// speedup vs baseline: 6.3355x; 1.0039x over previous
#include <cuda_runtime.h>
#include <cuda_bf16.h>
#include <math.h>
#include <stdint.h>

#define EMBED 1024
#define HEADS 16
#define HEAD_DIM 64
#define BATCH 4
#define SEQ 2048
#define FFDIM 4096
#define ROWS (BATCH * SEQ) /* 8192 */

// ---------------- scratch (device globals; allocation-free) ----------------
__device__ float g_x1[ROWS * EMBED];
__device__ __nv_bfloat16 g_h_hi[ROWS * EMBED],  g_h_lo[ROWS * EMBED];
__device__ __nv_bfloat16 g_y_hi[ROWS * EMBED],  g_y_lo[ROWS * EMBED];
__device__ __nv_bfloat16 g_h2_hi[ROWS * EMBED], g_h2_lo[ROWS * EMBED];
__device__ __nv_bfloat16 g_f_hi[ROWS * FFDIM],  g_f_lo[ROWS * FFDIM];
// attention operands: Q,K head-major [b,h,s,d]; V transposed [b,h,d,s]
__device__ __nv_bfloat16 g_att_qh[ROWS * EMBED], g_att_ql[ROWS * EMBED];
__device__ __nv_bfloat16 g_att_kh[ROWS * EMBED], g_att_kl[ROWS * EMBED];
__device__ __nv_bfloat16 g_att_vh[ROWS * EMBED], g_att_vl[ROWS * EMBED];
// pre-transposed weights [N,K] bf16 hi/lo
__device__ __nv_bfloat16 g_wqkv_hi[3 * EMBED * EMBED], g_wqkv_lo[3 * EMBED * EMBED];
__device__ float         g_bqkv[3 * EMBED];
__device__ __nv_bfloat16 g_wo_hi[EMBED * EMBED], g_wo_lo[EMBED * EMBED];
__device__ __nv_bfloat16 g_w1_hi[EMBED * FFDIM], g_w1_lo[EMBED * FFDIM];
__device__ __nv_bfloat16 g_w2_hi[FFDIM * EMBED], g_w2_lo[FFDIM * EMBED];

// ---------------- helpers ----------------
__device__ __forceinline__ uint32_t smem_u32(const void* p) {
    uint32_t a;
    asm("{ .reg .u64 t; cvta.to.shared.u64 t, %1; cvt.u32.u64 %0, t; }" : "=r"(a) : "l"(p));
    return a;
}
__device__ __forceinline__ void split_bf16(float x, __nv_bfloat16& h, __nv_bfloat16& l) {
    h = __float2bfloat16(x);
    l = __float2bfloat16(x - __bfloat162float(h));
}
__device__ __forceinline__ void split2_pack(float a, float b, uint32_t& hi, uint32_t& lo) {
    __nv_bfloat16 ah, al, bh, bl;
    split_bf16(a, ah, al); split_bf16(b, bh, bl);
    __nv_bfloat162 H; H.x = ah; H.y = bh;
    __nv_bfloat162 L; L.x = al; L.y = bl;
    hi = *reinterpret_cast<uint32_t*>(&H);
    lo = *reinterpret_cast<uint32_t*>(&L);
}
__device__ __forceinline__ float gelu_exact(float x) {
    return 0.5f * x * (1.0f + erff(x * 0.70710678118654752f));
}

#define CP_ASYNC16(dst, src) \
    asm volatile("cp.async.cg.shared.global [%0], [%1], 16;" :: "r"(dst), "l"(src))
#define CP_COMMIT()  asm volatile("cp.async.commit_group;" ::: "memory")
#define CP_WAIT(n)   asm volatile("cp.async.wait_group %0;" :: "n"(n) : "memory")

__device__ __forceinline__ void mma_bf16(float* c, const uint32_t* a, const uint32_t* b) {
    asm volatile(
        "mma.sync.aligned.m16n8k16.row.col.f32.bf16.bf16.f32 "
        "{%0,%1,%2,%3},{%4,%5,%6,%7},{%8,%9},{%0,%1,%2,%3};"
        : "+f"(c[0]), "+f"(c[1]), "+f"(c[2]), "+f"(c[3])
        : "r"(a[0]), "r"(a[1]), "r"(a[2]), "r"(a[3]), "r"(b[0]), "r"(b[1]));
}
#define LDSM_X4(r, addr) \
    asm volatile("ldmatrix.sync.aligned.m8n8.x4.shared.b16 {%0,%1,%2,%3}, [%4];" \
                 : "=r"((r)[0]), "=r"((r)[1]), "=r"((r)[2]), "=r"((r)[3]) : "r"(addr))

// ---------------- weight transpose + split ----------------
__global__ void __launch_bounds__(256) transpose_split(const float* __restrict__ W,
                                                       __nv_bfloat16* __restrict__ Th,
                                                       __nv_bfloat16* __restrict__ Tl,
                                                       int K, int N) {
    __shared__ float t[32][33];
    int n0 = blockIdx.x * 32, k0 = blockIdx.y * 32;
    int tx = threadIdx.x & 31, ty = threadIdx.x >> 5;
#pragma unroll
    for (int i = 0; i < 4; i++) {
        int k = ty + i * 8;
        t[k][tx] = W[(size_t)(k0 + k) * N + n0 + tx];
    }
    __syncthreads();
#pragma unroll
    for (int i = 0; i < 4; i++) {
        int r = ty + i * 8;
        float v = t[tx][r];
        __nv_bfloat16 h, l;
        split_bf16(v, h, l);
        Th[(size_t)(n0 + r) * K + k0 + tx] = h;
        Tl[(size_t)(n0 + r) * K + k0 + tx] = l;
    }
}

__global__ void __launch_bounds__(256) concat_bias(const float* __restrict__ bq,
                                                   const float* __restrict__ bk,
                                                   const float* __restrict__ bv) {
    int i = blockIdx.x * 256 + threadIdx.x;  // 0..1023
    g_bqkv[i]        = bq[i];
    g_bqkv[i + 1024] = bk[i];
    g_bqkv[i + 2048] = bv[i];
}

// ---------------- LayerNorm ----------------
__global__ void __launch_bounds__(256) ln_kernel(const float* __restrict__ X,
                                                 const float* __restrict__ gam,
                                                 const float* __restrict__ bet,
                                                 __nv_bfloat16* __restrict__ Yh,
                                                 __nv_bfloat16* __restrict__ Yl) {
    int row = blockIdx.x;
    int tid = threadIdx.x;
    const float* xr = X + (size_t)row * EMBED;
    float4 v = *reinterpret_cast<const float4*>(&xr[tid * 4]);
    float s  = v.x + v.y + v.z + v.w;
    float sq = v.x * v.x + v.y * v.y + v.z * v.z + v.w * v.w;
#pragma unroll
    for (int o = 16; o; o >>= 1) {
        s  += __shfl_xor_sync(0xffffffffu, s, o);
        sq += __shfl_xor_sync(0xffffffffu, sq, o);
    }
    __shared__ float ss[8], sqs[8];
    int w = tid >> 5;
    if ((tid & 31) == 0) { ss[w] = s; sqs[w] = sq; }
    __syncthreads();
    s = 0.f; sq = 0.f;
#pragma unroll
    for (int i = 0; i < 8; i++) { s += ss[i]; sq += sqs[i]; }
    float mu  = s * (1.0f / EMBED);
    float var = sq * (1.0f / EMBED) - mu * mu;
    float inv = rsqrtf(var + 1e-5f);
    float4 gv = *reinterpret_cast<const float4*>(&gam[tid * 4]);
    float4 bv = *reinterpret_cast<const float4*>(&bet[tid * 4]);
    float o0 = (v.x - mu) * inv * gv.x + bv.x;
    float o1 = (v.y - mu) * inv * gv.y + bv.y;
    float o2 = (v.z - mu) * inv * gv.z + bv.z;
    float o3 = (v.w - mu) * inv * gv.w + bv.w;
    size_t base = (size_t)row * EMBED + tid * 4;
    uint32_t h0, l0, h1, l1;
    split2_pack(o0, o1, h0, l0);
    split2_pack(o2, o3, h1, l1);
    *reinterpret_cast<uint32_t*>(&Yh[base])     = h0;
    *reinterpret_cast<uint32_t*>(&Yh[base + 2]) = h1;
    *reinterpret_cast<uint32_t*>(&Yl[base])     = l0;
    *reinterpret_cast<uint32_t*>(&Yl[base + 2]) = l1;
}

// ---------------- mma.sync GEMM (split-bf16 fp32 emulation) ----------------
// EPI: 0=bias  1=bias+residual  2=bias+GELU
// OUT: 0=fp32 row-major  1=bf16 hi/lo row-major  4=fused QKV (c<1024 Q[b,h,s,d],
//      <2048 K[b,h,s,d], else V[b,h,d,s]) via device globals.
static constexpr int GEMM_SMEM = 81920;

template <int EPI, int OUT>
__device__ __forceinline__ void epi_store(float v0, float v1, int r, int c,
                                          const float* R, float* C,
                                          __nv_bfloat16* Ch, __nv_bfloat16* Cl, int N) {
    if (OUT == 4) {
        int kind = c >> 10;
        int c1   = c & 1023;
        if (kind < 2) {
            size_t o2 = (((size_t)(r >> 11) * HEADS + (c1 >> 6)) * SEQ + (r & 2047)) * 64 + (c1 & 63);
            uint32_t hi, lo;
            split2_pack(v0, v1, hi, lo);
            if (kind == 0) {
                *reinterpret_cast<uint32_t*>(&g_att_qh[o2]) = hi;
                *reinterpret_cast<uint32_t*>(&g_att_ql[o2]) = lo;
            } else {
                *reinterpret_cast<uint32_t*>(&g_att_kh[o2]) = hi;
                *reinterpret_cast<uint32_t*>(&g_att_kl[o2]) = lo;
            }
        } else {
            size_t o3 = (((size_t)(r >> 11) * HEADS + (c1 >> 6)) * 64 + (c1 & 63)) * SEQ + (r & 2047);
            __nv_bfloat16 h0, l0, h1, l1;
            split_bf16(v0, h0, l0); split_bf16(v1, h1, l1);
            g_att_vh[o3] = h0; g_att_vl[o3] = l0;
            g_att_vh[o3 + SEQ] = h1; g_att_vl[o3 + SEQ] = l1;
        }
        return;
    }
    size_t off = (size_t)r * N + c;
    if (EPI == 1) { float2 rr = *reinterpret_cast<const float2*>(&R[off]); v0 += rr.x; v1 += rr.y; }
    if (EPI == 2) { v0 = gelu_exact(v0); v1 = gelu_exact(v1); }
    if (OUT == 0) {
        float2 o; o.x = v0; o.y = v1;
        *reinterpret_cast<float2*>(&C[off]) = o;
    } else {
        uint32_t hi, lo;
        split2_pack(v0, v1, hi, lo);
        *reinterpret_cast<uint32_t*>(&Ch[off]) = hi;
        *reinterpret_cast<uint32_t*>(&Cl[off]) = lo;
    }
}

__device__ __forceinline__ void gemm_load_stage(
    uint32_t smem_base, int stage,
    const __nv_bfloat16* Ah, const __nv_bfloat16* Al,
    const __nv_bfloat16* Bh, const __nv_bfloat16* Bl,
    int row0, int col0, int K, int k0, int tid) {
    uint32_t sb = smem_base + (uint32_t)stage * 40960u;
#pragma unroll
    for (int i = 0; i < 8; i++) {
        int idx = i * 256 + tid;
        int arr = idx >> 9;
        int pos = idx & 511;
        int r   = pos >> 2;
        int c8  = pos & 3;
        uint32_t dst = sb + (uint32_t)(arr * 10240 + r * 80 + c8 * 16);
        const __nv_bfloat16* src;
        if (arr == 0)      src = &Ah[(size_t)(row0 + r) * K + k0 + c8 * 8];
        else if (arr == 1) src = &Al[(size_t)(row0 + r) * K + k0 + c8 * 8];
        else if (arr == 2) src = &Bh[(size_t)(col0 + r) * K + k0 + c8 * 8];
        else               src = &Bl[(size_t)(col0 + r) * K + k0 + c8 * 8];
        CP_ASYNC16(dst, src);
    }
}

template <int EPI, int OUT>
__global__ void __launch_bounds__(256, 2) gemm_mma(
    const __nv_bfloat16* __restrict__ Ah, const __nv_bfloat16* __restrict__ Al,
    const __nv_bfloat16* __restrict__ Bh, const __nv_bfloat16* __restrict__ Bl,
    const float* __restrict__ bias, const float* __restrict__ R,
    float* __restrict__ C, __nv_bfloat16* __restrict__ Ch, __nv_bfloat16* __restrict__ Cl,
    int M, int N, int K) {
    extern __shared__ char dsm[];
    const int tid  = threadIdx.x;
    const int lane = tid & 31;
    const int wid  = tid >> 5;
    const int wm   = wid & 1;
    const int wn   = wid >> 1;
    const int row0 = blockIdx.y * 128;
    const int col0 = blockIdx.x * 128;
    const uint32_t smem_base = smem_u32(dsm);

    float acc[4][4][4];
#pragma unroll
    for (int i = 0; i < 4; i++)
#pragma unroll
        for (int j = 0; j < 4; j++)
#pragma unroll
            for (int k = 0; k < 4; k++) acc[i][j][k] = 0.f;

    const int nchunks = K >> 5;
    gemm_load_stage(smem_base, 0, Ah, Al, Bh, Bl, row0, col0, K, 0, tid);
    CP_COMMIT();

    // x4 B-fragment addressing: tile t = lane>>3; rows (t>>1)*8 + lane&7, k (t&1)*8
    const int tb      = lane >> 3;
    const int rb4_off = ((tb >> 1) << 3) + (lane & 7);
    const int kb4_off = (tb & 1) << 3;
    const int ra_off  = (lane & 7) + ((lane >> 3) & 1) * 8;

    for (int c = 0; c < nchunks; c++) {
        if (c + 1 < nchunks) {
            gemm_load_stage(smem_base, (c + 1) & 1, Ah, Al, Bh, Bl, row0, col0, K, (c + 1) << 5, tid);
            CP_COMMIT();
            CP_WAIT(1);
        } else {
            CP_WAIT(0);
        }
        __syncthreads();

        uint32_t sb = smem_base + (uint32_t)(c & 1) * 40960u;
#pragma unroll
        for (int ks = 0; ks < 32; ks += 16) {
            uint32_t bh[4][2], bl[4][2];
#pragma unroll
            for (int np = 0; np < 2; np++) {   // nt pair (2np, 2np+1)
                int rowb = wn * 32 + np * 16 + rb4_off;
                uint32_t ab = sb + 20480u + (uint32_t)(rowb * 80 + (ks + kb4_off) * 2);
                uint32_t r4[4];
                LDSM_X4(r4, ab);
                bh[np * 2][0] = r4[0]; bh[np * 2][1] = r4[1];
                bh[np * 2 + 1][0] = r4[2]; bh[np * 2 + 1][1] = r4[3];
                LDSM_X4(r4, ab + 10240u);
                bl[np * 2][0] = r4[0]; bl[np * 2][1] = r4[1];
                bl[np * 2 + 1][0] = r4[2]; bl[np * 2 + 1][1] = r4[3];
            }
            int ka_off = ks + ((lane >> 4) << 3);
#pragma unroll
            for (int mt = 0; mt < 4; mt++) {
                int rowa = wm * 64 + mt * 16 + ra_off;
                uint32_t aa = sb + (uint32_t)(rowa * 80 + ka_off * 2);
                uint32_t ah[4], al[4];
                LDSM_X4(ah, aa);
                LDSM_X4(al, aa + 10240u);
#pragma unroll
                for (int nt = 0; nt < 4; nt++) {
                    mma_bf16(acc[mt][nt], ah, bh[nt]);
                    mma_bf16(acc[mt][nt], ah, bl[nt]);
                    mma_bf16(acc[mt][nt], al, bh[nt]);
                }
            }
        }
        __syncthreads();
    }

#pragma unroll
    for (int mt = 0; mt < 4; mt++) {
#pragma unroll
        for (int nt = 0; nt < 4; nt++) {
            int rg = row0 + wm * 64 + mt * 16 + (lane >> 2);
            int cg = col0 + wn * 32 + nt * 8 + (lane & 3) * 2;
            float2 b2 = *reinterpret_cast<const float2*>(&bias[cg]);
            epi_store<EPI, OUT>(acc[mt][nt][0] + b2.x, acc[mt][nt][1] + b2.y,
                                rg, cg, R, C, Ch, Cl, N);
            epi_store<EPI, OUT>(acc[mt][nt][2] + b2.x, acc[mt][nt][3] + b2.y,
                                rg + 8, cg, R, C, Ch, Cl, N);
        }
    }
}

// ---------------- tensor-core causal flash attention -----------------------
// CTA: one (b,h) x one 128-row q tile (descending order). 8 warps x 16 q rows.
// K-tiles of 64 keys. K smem: [64 keys][64 d] hi/lo, row stride 144B.
// Vt smem: [64 d][64 keys] hi/lo.  Softmax in log2 domain (exp2f).
static constexpr int AT_KLO   = 18432;
static constexpr int AT_VHI   = 36864;
static constexpr int AT_STAGE = 55296;
static constexpr int ATTN_SMEM = 110592;
#define ATTN_SCALE 0.18033688011112042f  /* (1/8) * log2(e) */

__device__ __forceinline__ void attn_load_kv(uint32_t sb, int stage, int bh, int k0, int tid) {
    uint32_t st = sb + (uint32_t)stage * AT_STAGE;
#pragma unroll
    for (int i = 0; i < 4; i++) {
        int idx = i * 256 + tid;
        int arr = idx >> 9;
        int pos = idx & 511;
        int r   = pos >> 3;
        int c8  = pos & 7;
        uint32_t dst = st + (uint32_t)(arr * AT_KLO + r * 144 + c8 * 16);
        const __nv_bfloat16* src = (arr ? g_att_kl : g_att_kh)
            + ((size_t)bh * SEQ + k0 + r) * 64 + c8 * 8;
        CP_ASYNC16(dst, src);
    }
#pragma unroll
    for (int i = 0; i < 4; i++) {
        int idx = i * 256 + tid;
        int arr = idx >> 9;
        int pos = idx & 511;
        int r   = pos >> 3;
        int c8  = pos & 7;
        uint32_t dst = st + (uint32_t)(AT_VHI + arr * 9216 + r * 144 + c8 * 16);
        const __nv_bfloat16* src = (arr ? g_att_vl : g_att_vh)
            + ((size_t)bh * 64 + r) * SEQ + k0 + c8 * 8;
        CP_ASYNC16(dst, src);
    }
}

__global__ void __launch_bounds__(256, 2) attn_mma() {
    extern __shared__ char smbuf[];
    const int qt  = gridDim.x - 1 - blockIdx.x;   // descending work size first
    const int bh  = blockIdx.y;
    const int q0  = qt * 128;
    const int tid = threadIdx.x;
    const int lane = tid & 31;
    const int w    = tid >> 5;
    const uint32_t sb = smem_u32(smbuf);

    // ---- stage Q tile [128 x 64] hi/lo into stage-0 K region, extract frags
#pragma unroll
    for (int i = 0; i < 8; i++) {
        int idx = i * 256 + tid;
        int arr = idx >> 10;
        int pos = idx & 1023;
        int r   = pos >> 3;
        int c8  = pos & 7;
        uint32_t dst = sb + (uint32_t)(arr * AT_KLO + r * 144 + c8 * 16);
        const __nv_bfloat16* src = (arr ? g_att_ql : g_att_qh)
            + ((size_t)bh * SEQ + q0 + r) * 64 + c8 * 8;
        CP_ASYNC16(dst, src);
    }
    CP_COMMIT(); CP_WAIT(0); __syncthreads();

    uint32_t qh[4][4], ql[4][4];
    {
        int ra = (lane & 7) + ((lane >> 3) & 1) * 8;
#pragma unroll
        for (int kc = 0; kc < 4; kc++) {
            int ka = kc * 16 + ((lane >> 4) << 3);
            uint32_t addr = sb + (uint32_t)((w * 16 + ra) * 144 + ka * 2);
            LDSM_X4(qh[kc], addr);
            LDSM_X4(ql[kc], addr + AT_KLO);
        }
    }
    __syncthreads();

    float m0 = -1e30f, m1 = -1e30f, l0 = 0.f, l1 = 0.f;
    float o[8][4];
#pragma unroll
    for (int nt = 0; nt < 8; nt++)
#pragma unroll
        for (int j = 0; j < 4; j++) o[nt][j] = 0.f;

    const int nkt = 2 * qt + 2;
    attn_load_kv(sb, 0, bh, 0, tid);
    CP_COMMIT();

    // x4 fragment addressing for K/V (row-pair tiles)
    const int tb      = lane >> 3;
    const int rk4_off = ((tb >> 1) << 3) + (lane & 7);
    const int kk4_off = (tb & 1) << 3;
    const int wrow_max = q0 + w * 16 + 15;   // highest q row this warp owns

    for (int kt = 0; kt < nkt; kt++) {
        if (kt + 1 < nkt) {
            attn_load_kv(sb, (kt + 1) & 1, bh, (kt + 1) * 64, tid);
            CP_COMMIT();
            CP_WAIT(1);
        } else {
            CP_WAIT(0);
        }
        __syncthreads();

        uint32_t st = sb + (uint32_t)(kt & 1) * AT_STAGE;
        const int k0 = kt * 64;

        // warp fully above the causal boundary for this tile -> exact no-op
        if (k0 <= wrow_max) {
            // ---- scores S = Q K^T (3-term split), skipping fully-masked key pairs
            float s[8][4];
#pragma unroll
            for (int nt = 0; nt < 8; nt++)
#pragma unroll
                for (int j = 0; j < 4; j++) s[nt][j] = 0.f;
#pragma unroll
            for (int kc = 0; kc < 4; kc++) {
#pragma unroll
                for (int np = 0; np < 4; np++) {  // key-tile pair (2np, 2np+1)
                    if (k0 + np * 16 > wrow_max) continue;  // all keys masked -> P=0 exact
                    uint32_t kaddr = st + (uint32_t)((np * 16 + rk4_off) * 144 + (kc * 16 + kk4_off) * 2);
                    uint32_t kfh[4], kfl[4];
                    LDSM_X4(kfh, kaddr);
                    LDSM_X4(kfl, kaddr + AT_KLO);
                    mma_bf16(s[np * 2],     qh[kc], kfh);
                    mma_bf16(s[np * 2],     ql[kc], kfh);
                    mma_bf16(s[np * 2],     qh[kc], kfl);
                    mma_bf16(s[np * 2 + 1], qh[kc], kfh + 2);
                    mma_bf16(s[np * 2 + 1], ql[kc], kfh + 2);
                    mma_bf16(s[np * 2 + 1], qh[kc], kfl + 2);
                }
            }

            // ---- scale (log2 domain) + causal mask
            const int r0 = q0 + w * 16 + (lane >> 2);
#pragma unroll
            for (int nt = 0; nt < 8; nt++)
#pragma unroll
                for (int j = 0; j < 4; j++) s[nt][j] *= ATTN_SCALE;
            if (k0 + 63 > q0 + w * 16) {
#pragma unroll
                for (int nt = 0; nt < 8; nt++)
#pragma unroll
                    for (int j = 0; j < 4; j++) {
                        int col = k0 + nt * 8 + (lane & 3) * 2 + (j & 1);
                        int row = r0 + ((j >> 1) << 3);
                        if (col > row) s[nt][j] = -1e30f;
                    }
            }

            // ---- online softmax in log2 domain (rows r0 and r0+8)
            float mx0 = -1e30f, mx1 = -1e30f;
#pragma unroll
            for (int nt = 0; nt < 8; nt++) {
                mx0 = fmaxf(mx0, fmaxf(s[nt][0], s[nt][1]));
                mx1 = fmaxf(mx1, fmaxf(s[nt][2], s[nt][3]));
            }
            mx0 = fmaxf(mx0, __shfl_xor_sync(0xffffffffu, mx0, 1));
            mx0 = fmaxf(mx0, __shfl_xor_sync(0xffffffffu, mx0, 2));
            mx1 = fmaxf(mx1, __shfl_xor_sync(0xffffffffu, mx1, 1));
            mx1 = fmaxf(mx1, __shfl_xor_sync(0xffffffffu, mx1, 2));
            float mn0 = fmaxf(m0, mx0), mn1 = fmaxf(m1, mx1);
            float a0 = exp2f(m0 - mn0), a1 = exp2f(m1 - mn1);
            float rl0 = 0.f, rl1 = 0.f;
#pragma unroll
            for (int nt = 0; nt < 8; nt++) {
                s[nt][0] = exp2f(s[nt][0] - mn0); rl0 += s[nt][0];
                s[nt][1] = exp2f(s[nt][1] - mn0); rl0 += s[nt][1];
                s[nt][2] = exp2f(s[nt][2] - mn1); rl1 += s[nt][2];
                s[nt][3] = exp2f(s[nt][3] - mn1); rl1 += s[nt][3];
            }
            rl0 += __shfl_xor_sync(0xffffffffu, rl0, 1);
            rl0 += __shfl_xor_sync(0xffffffffu, rl0, 2);
            rl1 += __shfl_xor_sync(0xffffffffu, rl1, 1);
            rl1 += __shfl_xor_sync(0xffffffffu, rl1, 2);
            l0 = l0 * a0 + rl0;
            l1 = l1 * a1 + rl1;
            m0 = mn0; m1 = mn1;
#pragma unroll
            for (int nt = 0; nt < 8; nt++) {
                o[nt][0] *= a0; o[nt][1] *= a0;
                o[nt][2] *= a1; o[nt][3] *= a1;
            }

            // ---- O += P V (3-term split), skipping fully-masked key chunks
#pragma unroll
            for (int kc = 0; kc < 4; kc++) {
                if (k0 + kc * 16 > wrow_max) continue;  // P block identically 0
                uint32_t pah[4], pal[4];
                split2_pack(s[2 * kc][0],     s[2 * kc][1],     pah[0], pal[0]);
                split2_pack(s[2 * kc][2],     s[2 * kc][3],     pah[1], pal[1]);
                split2_pack(s[2 * kc + 1][0], s[2 * kc + 1][1], pah[2], pal[2]);
                split2_pack(s[2 * kc + 1][2], s[2 * kc + 1][3], pah[3], pal[3]);
#pragma unroll
                for (int np = 0; np < 4; np++) {  // d-tile pair (2np, 2np+1)
                    uint32_t vaddr = st + (uint32_t)(AT_VHI + (np * 16 + rk4_off) * 144 + (kc * 16 + kk4_off) * 2);
                    uint32_t vfh[4], vfl[4];
                    LDSM_X4(vfh, vaddr);
                    LDSM_X4(vfl, vaddr + 9216);
                    mma_bf16(o[np * 2],     pah, vfh);
                    mma_bf16(o[np * 2],     pal, vfh);
                    mma_bf16(o[np * 2],     pah, vfl);
                    mma_bf16(o[np * 2 + 1], pah, vfh + 2);
                    mma_bf16(o[np * 2 + 1], pal, vfh + 2);
                    mma_bf16(o[np * 2 + 1], pah, vfl + 2);
                }
            }
        }
        __syncthreads();
    }

    // ---- write y (row-major [ROWS][EMBED] bf16 hi/lo)
    const float i0 = 1.f / l0, i1 = 1.f / l1;
    const int b = bh >> 4, h = bh & 15;
    const int rowg = b * SEQ + q0 + w * 16 + (lane >> 2);
#pragma unroll
    for (int nt = 0; nt < 8; nt++) {
        int colg = h * 64 + nt * 8 + (lane & 3) * 2;
        size_t off0 = (size_t)rowg * EMBED + colg;
        size_t off1 = off0 + (size_t)8 * EMBED;
        uint32_t hi, lo;
        split2_pack(o[nt][0] * i0, o[nt][1] * i0, hi, lo);
        *reinterpret_cast<uint32_t*>(&g_y_hi[off0]) = hi;
        *reinterpret_cast<uint32_t*>(&g_y_lo[off0]) = lo;
        split2_pack(o[nt][2] * i1, o[nt][3] * i1, hi, lo);
        *reinterpret_cast<uint32_t*>(&g_y_hi[off1]) = hi;
        *reinterpret_cast<uint32_t*>(&g_y_lo[off1]) = lo;
    }
}

// ---------------- launch ---------------------------------------------------
extern "C" void kernel_launch(void* const* d_in, const int* in_sizes, int n_in,
                              void* d_out, int out_size) {
    const float* x     = (const float*)d_in[0];
    const float* Wq    = (const float*)d_in[1];
    const float* bq    = (const float*)d_in[2];
    const float* Wk    = (const float*)d_in[3];
    const float* bk    = (const float*)d_in[4];
    const float* Wv    = (const float*)d_in[5];
    const float* bv    = (const float*)d_in[6];
    const float* Wo    = (const float*)d_in[7];
    const float* bo    = (const float*)d_in[8];
    const float* g1    = (const float*)d_in[9];
    const float* beta1 = (const float*)d_in[10];
    const float* g2    = (const float*)d_in[11];
    const float* beta2 = (const float*)d_in[12];
    const float* W1    = (const float*)d_in[13];
    const float* b1    = (const float*)d_in[14];
    const float* W2    = (const float*)d_in[15];
    const float* b2    = (const float*)d_in[16];
    float* out = (float*)d_out;

    float* px1;
    cudaGetSymbolAddress((void**)&px1, g_x1);
    __nv_bfloat16 *phh, *phl, *pyh, *pyl, *ph2h, *ph2l, *pfh, *pfl;
    cudaGetSymbolAddress((void**)&phh,  g_h_hi);  cudaGetSymbolAddress((void**)&phl,  g_h_lo);
    cudaGetSymbolAddress((void**)&pyh,  g_y_hi);  cudaGetSymbolAddress((void**)&pyl,  g_y_lo);
    cudaGetSymbolAddress((void**)&ph2h, g_h2_hi); cudaGetSymbolAddress((void**)&ph2l, g_h2_lo);
    cudaGetSymbolAddress((void**)&pfh,  g_f_hi);  cudaGetSymbolAddress((void**)&pfl,  g_f_lo);
    __nv_bfloat16 *wqkvh, *wqkvl, *woh, *wol, *w1h, *w1l, *w2h, *w2l;
    float* pbqkv;
    cudaGetSymbolAddress((void**)&wqkvh, g_wqkv_hi); cudaGetSymbolAddress((void**)&wqkvl, g_wqkv_lo);
    cudaGetSymbolAddress((void**)&pbqkv, g_bqkv);
    cudaGetSymbolAddress((void**)&woh, g_wo_hi); cudaGetSymbolAddress((void**)&wol, g_wo_lo);
    cudaGetSymbolAddress((void**)&w1h, g_w1_hi); cudaGetSymbolAddress((void**)&w1l, g_w1_lo);
    cudaGetSymbolAddress((void**)&w2h, g_w2_hi); cudaGetSymbolAddress((void**)&w2l, g_w2_lo);

    cudaFuncSetAttribute(gemm_mma<0, 4>, cudaFuncAttributeMaxDynamicSharedMemorySize, GEMM_SMEM);
    cudaFuncSetAttribute(gemm_mma<1, 0>, cudaFuncAttributeMaxDynamicSharedMemorySize, GEMM_SMEM);
    cudaFuncSetAttribute(gemm_mma<2, 1>, cudaFuncAttributeMaxDynamicSharedMemorySize, GEMM_SMEM);
    cudaFuncSetAttribute(attn_mma, cudaFuncAttributeMaxDynamicSharedMemorySize, ATTN_SMEM);

    dim3 t256(256);

    // ---- side stream: Wo/W1/W2 prep overlaps the LN1→QKV→attention chain ----
    cudaStream_t s2;
    cudaStreamCreateWithFlags(&s2, cudaStreamNonBlocking);
    cudaEvent_t eFork, eJoin;
    cudaEventCreateWithFlags(&eFork, cudaEventDisableTiming);
    cudaEventCreateWithFlags(&eJoin, cudaEventDisableTiming);
    cudaEventRecord(eFork, 0);
    cudaStreamWaitEvent(s2, eFork, 0);
    transpose_split<<<dim3(EMBED / 32, EMBED / 32), t256, 0, s2>>>(Wo, woh, wol, EMBED, EMBED);
    transpose_split<<<dim3(FFDIM / 32, EMBED / 32), t256, 0, s2>>>(W1, w1h, w1l, EMBED, FFDIM);
    transpose_split<<<dim3(EMBED / 32, FFDIM / 32), t256, 0, s2>>>(W2, w2h, w2l, FFDIM, EMBED);
    cudaEventRecord(eJoin, s2);

    // ---- main stream: QKV prep + LN1 ----
    transpose_split<<<dim3(EMBED / 32, EMBED / 32), t256>>>(Wq, wqkvh, wqkvl, EMBED, EMBED);
    transpose_split<<<dim3(EMBED / 32, EMBED / 32), t256>>>(Wk, wqkvh + EMBED * EMBED, wqkvl + EMBED * EMBED, EMBED, EMBED);
    transpose_split<<<dim3(EMBED / 32, EMBED / 32), t256>>>(Wv, wqkvh + 2 * EMBED * EMBED, wqkvl + 2 * EMBED * EMBED, EMBED, EMBED);
    concat_bias<<<4, t256>>>(bq, bk, bv);
    ln_kernel<<<ROWS, t256>>>(x, g1, beta1, phh, phl);

    // fused QKV projection (N=3072) straight into attention layouts
    dim3 gqkv(3 * EMBED / 128, ROWS / 128);
    gemm_mma<0, 4><<<gqkv, t256, GEMM_SMEM>>>(phh, phl, wqkvh, wqkvl, pbqkv, nullptr,
                                              nullptr, nullptr, nullptr, ROWS, 3 * EMBED, EMBED);

    // tensor-core flash attention
    attn_mma<<<dim3(SEQ / 128, BATCH * HEADS), t256, ATTN_SMEM>>>();

    // join side-stream prep before Wo GEMM
    cudaStreamWaitEvent(0, eJoin, 0);

    // x1 = x + y @ Wo + bo
    dim3 g1024(EMBED / 128, ROWS / 128);
    gemm_mma<1, 0><<<g1024, t256, GEMM_SMEM>>>(pyh, pyl, woh, wol, bo, x, px1, nullptr, nullptr, ROWS, EMBED, EMBED);
    // LN2
    ln_kernel<<<ROWS, t256>>>(px1, g2, beta2, ph2h, ph2l);
    // f = gelu(h2 @ W1 + b1)
    dim3 gff(FFDIM / 128, ROWS / 128);
    gemm_mma<2, 1><<<gff, t256, GEMM_SMEM>>>(ph2h, ph2l, w1h, w1l, b1, nullptr, nullptr, pfh, pfl, ROWS, FFDIM, EMBED);
    // out = x1 + f @ W2 + b2
    gemm_mma<1, 0><<<g1024, t256, GEMM_SMEM>>>(pfh, pfl, w2h, w2l, b2, px1, out, nullptr, nullptr, ROWS, EMBED, FFDIM);
}

// round 13
// speedup vs baseline: 8.9021x; 1.4051x over previous
#include <cuda_runtime.h>
#include <cuda_fp16.h>
#include <math.h>
#include <stdint.h>

#define EMBED 1024
#define HEADS 16
#define HEAD_DIM 64
#define BATCH 4
#define SEQ 2048
#define FFDIM 4096
#define ROWS (BATCH * SEQ) /* 8192 */

// ---------------- scratch (device globals; allocation-free) ----------------
__device__ float g_x1[ROWS * EMBED];
__device__ __half g_h_hi[ROWS * EMBED],  g_h_lo[ROWS * EMBED];
__device__ __half g_y_hi[ROWS * EMBED],  g_y_lo[ROWS * EMBED];
__device__ __half g_h2_hi[ROWS * EMBED], g_h2_lo[ROWS * EMBED];
__device__ __half g_f_hi[ROWS * FFDIM],  g_f_lo[ROWS * FFDIM];
// attention operands: Q hi/lo, K hi, V hi (transposed [b,h,d,s])
__device__ __half g_att_qh[ROWS * EMBED], g_att_ql[ROWS * EMBED];
__device__ __half g_att_kh[ROWS * EMBED];
__device__ __half g_att_vh[ROWS * EMBED];
// pre-transposed weights [N,K] fp16 hi only
__device__ __half g_wqkv_hi[3 * EMBED * EMBED];
__device__ float  g_bqkv[3 * EMBED];
__device__ __half g_wo_hi[EMBED * EMBED];
__device__ __half g_w1_hi[EMBED * FFDIM];
__device__ __half g_w2_hi[FFDIM * EMBED];

// ---------------- helpers ----------------
__device__ __forceinline__ uint32_t smem_u32(const void* p) {
    uint32_t a;
    asm("{ .reg .u64 t; cvta.to.shared.u64 t, %1; cvt.u32.u64 %0, t; }" : "=r"(a) : "l"(p));
    return a;
}
__device__ __forceinline__ void split_h(float x, __half& h, __half& l) {
    h = __float2half_rn(x);
    l = __float2half_rn(x - __half2float(h));
}
__device__ __forceinline__ void split2_pack(float a, float b, uint32_t& hi, uint32_t& lo) {
    __half ah, al, bh, bl;
    split_h(a, ah, al); split_h(b, bh, bl);
    __half2 H; H.x = ah; H.y = bh;
    __half2 L; L.x = al; L.y = bl;
    hi = *reinterpret_cast<uint32_t*>(&H);
    lo = *reinterpret_cast<uint32_t*>(&L);
}
__device__ __forceinline__ uint32_t pack2_h(float a, float b) {
    __half2 H; H.x = __float2half_rn(a); H.y = __float2half_rn(b);
    return *reinterpret_cast<uint32_t*>(&H);
}
__device__ __forceinline__ float gelu_exact(float x) {
    return 0.5f * x * (1.0f + erff(x * 0.70710678118654752f));
}

#define CP_ASYNC16(dst, src) \
    asm volatile("cp.async.cg.shared.global [%0], [%1], 16;" :: "r"(dst), "l"(src))
#define CP_COMMIT()  asm volatile("cp.async.commit_group;" ::: "memory")
#define CP_WAIT(n)   asm volatile("cp.async.wait_group %0;" :: "n"(n) : "memory")

__device__ __forceinline__ void mma_f16(float* c, const uint32_t* a, const uint32_t* b) {
    asm volatile(
        "mma.sync.aligned.m16n8k16.row.col.f32.f16.f16.f32 "
        "{%0,%1,%2,%3},{%4,%5,%6,%7},{%8,%9},{%0,%1,%2,%3};"
        : "+f"(c[0]), "+f"(c[1]), "+f"(c[2]), "+f"(c[3])
        : "r"(a[0]), "r"(a[1]), "r"(a[2]), "r"(a[3]), "r"(b[0]), "r"(b[1]));
}
#define LDSM_X4(r, addr) \
    asm volatile("ldmatrix.sync.aligned.m8n8.x4.shared.b16 {%0,%1,%2,%3}, [%4];" \
                 : "=r"((r)[0]), "=r"((r)[1]), "=r"((r)[2]), "=r"((r)[3]) : "r"(addr))

// ---------------- weight transpose (fp16 hi only) ----------------
__global__ void __launch_bounds__(256) transpose_h(const float* __restrict__ W,
                                                   __half* __restrict__ Th,
                                                   int K, int N) {
    __shared__ float t[32][33];
    int n0 = blockIdx.x * 32, k0 = blockIdx.y * 32;
    int tx = threadIdx.x & 31, ty = threadIdx.x >> 5;
#pragma unroll
    for (int i = 0; i < 4; i++) {
        int k = ty + i * 8;
        t[k][tx] = W[(size_t)(k0 + k) * N + n0 + tx];
    }
    __syncthreads();
#pragma unroll
    for (int i = 0; i < 4; i++) {
        int r = ty + i * 8;
        Th[(size_t)(n0 + r) * K + k0 + tx] = __float2half_rn(t[tx][r]);
    }
}

__global__ void __launch_bounds__(256) concat_bias(const float* __restrict__ bq,
                                                   const float* __restrict__ bk,
                                                   const float* __restrict__ bv) {
    int i = blockIdx.x * 256 + threadIdx.x;  // 0..1023
    g_bqkv[i]        = bq[i];
    g_bqkv[i + 1024] = bk[i];
    g_bqkv[i + 2048] = bv[i];
}

// ---------------- LayerNorm (fp16 hi/lo output) ----------------
__global__ void __launch_bounds__(256) ln_kernel(const float* __restrict__ X,
                                                 const float* __restrict__ gam,
                                                 const float* __restrict__ bet,
                                                 __half* __restrict__ Yh,
                                                 __half* __restrict__ Yl) {
    int row = blockIdx.x;
    int tid = threadIdx.x;
    const float* xr = X + (size_t)row * EMBED;
    float4 v = *reinterpret_cast<const float4*>(&xr[tid * 4]);
    float s  = v.x + v.y + v.z + v.w;
    float sq = v.x * v.x + v.y * v.y + v.z * v.z + v.w * v.w;
#pragma unroll
    for (int o = 16; o; o >>= 1) {
        s  += __shfl_xor_sync(0xffffffffu, s, o);
        sq += __shfl_xor_sync(0xffffffffu, sq, o);
    }
    __shared__ float ss[8], sqs[8];
    int w = tid >> 5;
    if ((tid & 31) == 0) { ss[w] = s; sqs[w] = sq; }
    __syncthreads();
    s = 0.f; sq = 0.f;
#pragma unroll
    for (int i = 0; i < 8; i++) { s += ss[i]; sq += sqs[i]; }
    float mu  = s * (1.0f / EMBED);
    float var = sq * (1.0f / EMBED) - mu * mu;
    float inv = rsqrtf(var + 1e-5f);
    float4 gv = *reinterpret_cast<const float4*>(&gam[tid * 4]);
    float4 bv = *reinterpret_cast<const float4*>(&bet[tid * 4]);
    float o0 = (v.x - mu) * inv * gv.x + bv.x;
    float o1 = (v.y - mu) * inv * gv.y + bv.y;
    float o2 = (v.z - mu) * inv * gv.z + bv.z;
    float o3 = (v.w - mu) * inv * gv.w + bv.w;
    size_t base = (size_t)row * EMBED + tid * 4;
    uint32_t h0, l0, h1, l1;
    split2_pack(o0, o1, h0, l0);
    split2_pack(o2, o3, h1, l1);
    *reinterpret_cast<uint32_t*>(&Yh[base])     = h0;
    *reinterpret_cast<uint32_t*>(&Yh[base + 2]) = h1;
    *reinterpret_cast<uint32_t*>(&Yl[base])     = l0;
    *reinterpret_cast<uint32_t*>(&Yl[base + 2]) = l1;
}

// ---------------- mma.sync GEMM (2-term fp16 split) ----------------
// C = (Ah+Al) @ Bh^T : A activations hi/lo [M,K], B weights hi [N,K].
// EPI: 0=bias  1=bias+residual  2=bias+GELU
// OUT: 0=fp32 row-major  1=fp16 hi/lo row-major  4=fused QKV
// smem per stage: Ah(0) Al(10240) Bh(20480), row stride 80B. 2 stages.
static constexpr int GEMM_STAGE = 30720;
static constexpr int GEMM_SMEM  = 61440;

template <int EPI, int OUT>
__device__ __forceinline__ void epi_store(float v0, float v1, int r, int c,
                                          const float* R, float* C,
                                          __half* Ch, __half* Cl, int N) {
    if (OUT == 4) {
        int kind = c >> 10;
        int c1   = c & 1023;
        if (kind == 0) {        // Q [b,h,s,d] hi+lo
            size_t o2 = (((size_t)(r >> 11) * HEADS + (c1 >> 6)) * SEQ + (r & 2047)) * 64 + (c1 & 63);
            uint32_t hi, lo;
            split2_pack(v0, v1, hi, lo);
            *reinterpret_cast<uint32_t*>(&g_att_qh[o2]) = hi;
            *reinterpret_cast<uint32_t*>(&g_att_ql[o2]) = lo;
        } else if (kind == 1) { // K [b,h,s,d] hi only
            size_t o2 = (((size_t)(r >> 11) * HEADS + (c1 >> 6)) * SEQ + (r & 2047)) * 64 + (c1 & 63);
            *reinterpret_cast<uint32_t*>(&g_att_kh[o2]) = pack2_h(v0, v1);
        } else {                // V [b,h,d,s] hi only
            size_t o3 = (((size_t)(r >> 11) * HEADS + (c1 >> 6)) * 64 + (c1 & 63)) * SEQ + (r & 2047);
            g_att_vh[o3]       = __float2half_rn(v0);
            g_att_vh[o3 + SEQ] = __float2half_rn(v1);
        }
        return;
    }
    size_t off = (size_t)r * N + c;
    if (EPI == 1) { float2 rr = *reinterpret_cast<const float2*>(&R[off]); v0 += rr.x; v1 += rr.y; }
    if (EPI == 2) { v0 = gelu_exact(v0); v1 = gelu_exact(v1); }
    if (OUT == 0) {
        float2 o; o.x = v0; o.y = v1;
        *reinterpret_cast<float2*>(&C[off]) = o;
    } else {
        uint32_t hi, lo;
        split2_pack(v0, v1, hi, lo);
        *reinterpret_cast<uint32_t*>(&Ch[off]) = hi;
        *reinterpret_cast<uint32_t*>(&Cl[off]) = lo;
    }
}

__device__ __forceinline__ void gemm_load_stage(
    uint32_t smem_base, int stage,
    const __half* Ah, const __half* Al, const __half* Bh,
    int row0, int col0, int K, int k0, int tid) {
    uint32_t sb = smem_base + (uint32_t)stage * (uint32_t)GEMM_STAGE;
#pragma unroll
    for (int i = 0; i < 6; i++) {
        int idx = i * 256 + tid;       // 0..1535
        int arr = idx >> 9;            // 0 Ah, 1 Al, 2 Bh
        int pos = idx & 511;
        int r   = pos >> 2;
        int c8  = pos & 3;
        uint32_t dst = sb + (uint32_t)(arr * 10240 + r * 80 + c8 * 16);
        const __half* src;
        if (arr == 0)      src = &Ah[(size_t)(row0 + r) * K + k0 + c8 * 8];
        else if (arr == 1) src = &Al[(size_t)(row0 + r) * K + k0 + c8 * 8];
        else               src = &Bh[(size_t)(col0 + r) * K + k0 + c8 * 8];
        CP_ASYNC16(dst, src);
    }
}

template <int EPI, int OUT>
__global__ void __launch_bounds__(256, 2) gemm_mma(
    const __half* __restrict__ Ah, const __half* __restrict__ Al,
    const __half* __restrict__ Bh,
    const float* __restrict__ bias, const float* __restrict__ R,
    float* __restrict__ C, __half* __restrict__ Ch, __half* __restrict__ Cl,
    int M, int N, int K) {
    extern __shared__ char dsm[];
    const int tid  = threadIdx.x;
    const int lane = tid & 31;
    const int wid  = tid >> 5;
    const int wm   = wid & 1;
    const int wn   = wid >> 1;
    const int row0 = blockIdx.y * 128;
    const int col0 = blockIdx.x * 128;
    const uint32_t smem_base = smem_u32(dsm);

    float acc[4][4][4];
#pragma unroll
    for (int i = 0; i < 4; i++)
#pragma unroll
        for (int j = 0; j < 4; j++)
#pragma unroll
            for (int k = 0; k < 4; k++) acc[i][j][k] = 0.f;

    const int nchunks = K >> 5;
    gemm_load_stage(smem_base, 0, Ah, Al, Bh, row0, col0, K, 0, tid);
    CP_COMMIT();

    const int tb      = lane >> 3;
    const int rb4_off = ((tb >> 1) << 3) + (lane & 7);
    const int kb4_off = (tb & 1) << 3;
    const int ra_off  = (lane & 7) + ((lane >> 3) & 1) * 8;

    for (int c = 0; c < nchunks; c++) {
        if (c + 1 < nchunks) {
            gemm_load_stage(smem_base, (c + 1) & 1, Ah, Al, Bh, row0, col0, K, (c + 1) << 5, tid);
            CP_COMMIT();
            CP_WAIT(1);
        } else {
            CP_WAIT(0);
        }
        __syncthreads();

        uint32_t sb = smem_base + (uint32_t)(c & 1) * (uint32_t)GEMM_STAGE;
#pragma unroll
        for (int ks = 0; ks < 32; ks += 16) {
            uint32_t bh[4][2];
#pragma unroll
            for (int np = 0; np < 2; np++) {
                int rowb = wn * 32 + np * 16 + rb4_off;
                uint32_t ab = sb + 20480u + (uint32_t)(rowb * 80 + (ks + kb4_off) * 2);
                uint32_t r4[4];
                LDSM_X4(r4, ab);
                bh[np * 2][0] = r4[0]; bh[np * 2][1] = r4[1];
                bh[np * 2 + 1][0] = r4[2]; bh[np * 2 + 1][1] = r4[3];
            }
            int ka_off = ks + ((lane >> 4) << 3);
#pragma unroll
            for (int mt = 0; mt < 4; mt++) {
                int rowa = wm * 64 + mt * 16 + ra_off;
                uint32_t aa = sb + (uint32_t)(rowa * 80 + ka_off * 2);
                uint32_t ah[4], al[4];
                LDSM_X4(ah, aa);
                LDSM_X4(al, aa + 10240u);
#pragma unroll
                for (int nt = 0; nt < 4; nt++) {
                    mma_f16(acc[mt][nt], ah, bh[nt]);
                    mma_f16(acc[mt][nt], al, bh[nt]);
                }
            }
        }
        __syncthreads();
    }

#pragma unroll
    for (int mt = 0; mt < 4; mt++) {
#pragma unroll
        for (int nt = 0; nt < 4; nt++) {
            int rg = row0 + wm * 64 + mt * 16 + (lane >> 2);
            int cg = col0 + wn * 32 + nt * 8 + (lane & 3) * 2;
            float2 b2 = *reinterpret_cast<const float2*>(&bias[cg]);
            epi_store<EPI, OUT>(acc[mt][nt][0] + b2.x, acc[mt][nt][1] + b2.y,
                                rg, cg, R, C, Ch, Cl, N);
            epi_store<EPI, OUT>(acc[mt][nt][2] + b2.x, acc[mt][nt][3] + b2.y,
                                rg + 8, cg, R, C, Ch, Cl, N);
        }
    }
}

// ---------------- tensor-core causal flash attention (2-term fp16) --------
// Q hi/lo compensated; K,V hi-only. K smem [64 keys][64 d], Vt smem [64 d][64 keys],
// row stride 144B. Q staged across both stage regions, extracted before KV loads.
static constexpr int AT_VOFF  = 9216;
static constexpr int AT_STAGE = 18432;
static constexpr int ATTN_SMEM = 36864;
#define ATTN_SCALE 0.18033688011112042f  /* (1/8) * log2(e) */

__device__ __forceinline__ void attn_load_kv(uint32_t sb, int stage, int bh, int k0, int tid) {
    uint32_t st = sb + (uint32_t)stage * (uint32_t)AT_STAGE;
#pragma unroll
    for (int i = 0; i < 2; i++) {
        int idx = i * 256 + tid;      // 0..511
        int r   = idx >> 3;
        int c8  = idx & 7;
        uint32_t dst = st + (uint32_t)(r * 144 + c8 * 16);
        const __half* src = g_att_kh + ((size_t)bh * SEQ + k0 + r) * 64 + c8 * 8;
        CP_ASYNC16(dst, src);
    }
#pragma unroll
    for (int i = 0; i < 2; i++) {
        int idx = i * 256 + tid;
        int r   = idx >> 3;
        int c8  = idx & 7;
        uint32_t dst = st + (uint32_t)(AT_VOFF + r * 144 + c8 * 16);
        const __half* src = g_att_vh + ((size_t)bh * 64 + r) * SEQ + k0 + c8 * 8;
        CP_ASYNC16(dst, src);
    }
}

__global__ void __launch_bounds__(256, 2) attn_mma() {
    extern __shared__ char smbuf[];
    const int qt  = gridDim.x - 1 - blockIdx.x;   // descending work size first
    const int bh  = blockIdx.y;
    const int q0  = qt * 128;
    const int tid = threadIdx.x;
    const int lane = tid & 31;
    const int w    = tid >> 5;
    const uint32_t sb = smem_u32(smbuf);

    // ---- stage Q tile [128 x 64] hi/lo, extract frags
#pragma unroll
    for (int i = 0; i < 8; i++) {
        int idx = i * 256 + tid;      // 0..2047
        int arr = idx >> 10;          // 0 hi, 1 lo
        int pos = idx & 1023;
        int r   = pos >> 3;
        int c8  = pos & 7;
        uint32_t dst = sb + (uint32_t)(arr * AT_STAGE + r * 144 + c8 * 16);
        const __half* src = (arr ? g_att_ql : g_att_qh)
            + ((size_t)bh * SEQ + q0 + r) * 64 + c8 * 8;
        CP_ASYNC16(dst, src);
    }
    CP_COMMIT(); CP_WAIT(0); __syncthreads();

    uint32_t qh[4][4], ql[4][4];
    {
        int ra = (lane & 7) + ((lane >> 3) & 1) * 8;
#pragma unroll
        for (int kc = 0; kc < 4; kc++) {
            int ka = kc * 16 + ((lane >> 4) << 3);
            uint32_t addr = sb + (uint32_t)((w * 16 + ra) * 144 + ka * 2);
            LDSM_X4(qh[kc], addr);
            LDSM_X4(ql[kc], addr + AT_STAGE);
        }
    }
    __syncthreads();

    float m0 = -1e30f, m1 = -1e30f, l0 = 0.f, l1 = 0.f;
    float o[8][4];
#pragma unroll
    for (int nt = 0; nt < 8; nt++)
#pragma unroll
        for (int j = 0; j < 4; j++) o[nt][j] = 0.f;

    const int nkt = 2 * qt + 2;
    attn_load_kv(sb, 0, bh, 0, tid);
    CP_COMMIT();

    const int tb      = lane >> 3;
    const int rk4_off = ((tb >> 1) << 3) + (lane & 7);
    const int kk4_off = (tb & 1) << 3;
    const int wrow_max = q0 + w * 16 + 15;

    for (int kt = 0; kt < nkt; kt++) {
        if (kt + 1 < nkt) {
            attn_load_kv(sb, (kt + 1) & 1, bh, (kt + 1) * 64, tid);
            CP_COMMIT();
            CP_WAIT(1);
        } else {
            CP_WAIT(0);
        }
        __syncthreads();

        uint32_t st = sb + (uint32_t)(kt & 1) * (uint32_t)AT_STAGE;
        const int k0 = kt * 64;

        if (k0 <= wrow_max) {
            // ---- S = (Qh+Ql) Kh^T
            float s[8][4];
#pragma unroll
            for (int nt = 0; nt < 8; nt++)
#pragma unroll
                for (int j = 0; j < 4; j++) s[nt][j] = 0.f;
#pragma unroll
            for (int kc = 0; kc < 4; kc++) {
#pragma unroll
                for (int np = 0; np < 4; np++) {
                    if (k0 + np * 16 > wrow_max) continue;  // fully masked -> exact skip
                    uint32_t kaddr = st + (uint32_t)((np * 16 + rk4_off) * 144 + (kc * 16 + kk4_off) * 2);
                    uint32_t kfh[4];
                    LDSM_X4(kfh, kaddr);
                    mma_f16(s[np * 2],     qh[kc], kfh);
                    mma_f16(s[np * 2],     ql[kc], kfh);
                    mma_f16(s[np * 2 + 1], qh[kc], kfh + 2);
                    mma_f16(s[np * 2 + 1], ql[kc], kfh + 2);
                }
            }

            // ---- scale (log2 domain) + causal mask
            const int r0 = q0 + w * 16 + (lane >> 2);
#pragma unroll
            for (int nt = 0; nt < 8; nt++)
#pragma unroll
                for (int j = 0; j < 4; j++) s[nt][j] *= ATTN_SCALE;
            if (k0 + 63 > q0 + w * 16) {
#pragma unroll
                for (int nt = 0; nt < 8; nt++)
#pragma unroll
                    for (int j = 0; j < 4; j++) {
                        int col = k0 + nt * 8 + (lane & 3) * 2 + (j & 1);
                        int row = r0 + ((j >> 1) << 3);
                        if (col > row) s[nt][j] = -1e30f;
                    }
            }

            // ---- online softmax in log2 domain
            float mx0 = -1e30f, mx1 = -1e30f;
#pragma unroll
            for (int nt = 0; nt < 8; nt++) {
                mx0 = fmaxf(mx0, fmaxf(s[nt][0], s[nt][1]));
                mx1 = fmaxf(mx1, fmaxf(s[nt][2], s[nt][3]));
            }
            mx0 = fmaxf(mx0, __shfl_xor_sync(0xffffffffu, mx0, 1));
            mx0 = fmaxf(mx0, __shfl_xor_sync(0xffffffffu, mx0, 2));
            mx1 = fmaxf(mx1, __shfl_xor_sync(0xffffffffu, mx1, 1));
            mx1 = fmaxf(mx1, __shfl_xor_sync(0xffffffffu, mx1, 2));
            float mn0 = fmaxf(m0, mx0), mn1 = fmaxf(m1, mx1);
            float a0 = exp2f(m0 - mn0), a1 = exp2f(m1 - mn1);
            float rl0 = 0.f, rl1 = 0.f;
#pragma unroll
            for (int nt = 0; nt < 8; nt++) {
                s[nt][0] = exp2f(s[nt][0] - mn0); rl0 += s[nt][0];
                s[nt][1] = exp2f(s[nt][1] - mn0); rl0 += s[nt][1];
                s[nt][2] = exp2f(s[nt][2] - mn1); rl1 += s[nt][2];
                s[nt][3] = exp2f(s[nt][3] - mn1); rl1 += s[nt][3];
            }
            rl0 += __shfl_xor_sync(0xffffffffu, rl0, 1);
            rl0 += __shfl_xor_sync(0xffffffffu, rl0, 2);
            rl1 += __shfl_xor_sync(0xffffffffu, rl1, 1);
            rl1 += __shfl_xor_sync(0xffffffffu, rl1, 2);
            l0 = l0 * a0 + rl0;
            l1 = l1 * a1 + rl1;
            m0 = mn0; m1 = mn1;
#pragma unroll
            for (int nt = 0; nt < 8; nt++) {
                o[nt][0] *= a0; o[nt][1] *= a0;
                o[nt][2] *= a1; o[nt][3] *= a1;
            }

            // ---- O += (Ph+Pl) Vh
#pragma unroll
            for (int kc = 0; kc < 4; kc++) {
                if (k0 + kc * 16 > wrow_max) continue;  // P block identically 0
                uint32_t pah[4], pal[4];
                split2_pack(s[2 * kc][0],     s[2 * kc][1],     pah[0], pal[0]);
                split2_pack(s[2 * kc][2],     s[2 * kc][3],     pah[1], pal[1]);
                split2_pack(s[2 * kc + 1][0], s[2 * kc + 1][1], pah[2], pal[2]);
                split2_pack(s[2 * kc + 1][2], s[2 * kc + 1][3], pah[3], pal[3]);
#pragma unroll
                for (int np = 0; np < 4; np++) {
                    uint32_t vaddr = st + (uint32_t)(AT_VOFF + (np * 16 + rk4_off) * 144 + (kc * 16 + kk4_off) * 2);
                    uint32_t vfh[4];
                    LDSM_X4(vfh, vaddr);
                    mma_f16(o[np * 2],     pah, vfh);
                    mma_f16(o[np * 2],     pal, vfh);
                    mma_f16(o[np * 2 + 1], pah, vfh + 2);
                    mma_f16(o[np * 2 + 1], pal, vfh + 2);
                }
            }
        }
        __syncthreads();
    }

    // ---- write y (row-major [ROWS][EMBED] fp16 hi/lo)
    const float i0 = 1.f / l0, i1 = 1.f / l1;
    const int b = bh >> 4, h = bh & 15;
    const int rowg = b * SEQ + q0 + w * 16 + (lane >> 2);
#pragma unroll
    for (int nt = 0; nt < 8; nt++) {
        int colg = h * 64 + nt * 8 + (lane & 3) * 2;
        size_t off0 = (size_t)rowg * EMBED + colg;
        size_t off1 = off0 + (size_t)8 * EMBED;
        uint32_t hi, lo;
        split2_pack(o[nt][0] * i0, o[nt][1] * i0, hi, lo);
        *reinterpret_cast<uint32_t*>(&g_y_hi[off0]) = hi;
        *reinterpret_cast<uint32_t*>(&g_y_lo[off0]) = lo;
        split2_pack(o[nt][2] * i1, o[nt][3] * i1, hi, lo);
        *reinterpret_cast<uint32_t*>(&g_y_hi[off1]) = hi;
        *reinterpret_cast<uint32_t*>(&g_y_lo[off1]) = lo;
    }
}

// ---------------- launch ---------------------------------------------------
extern "C" void kernel_launch(void* const* d_in, const int* in_sizes, int n_in,
                              void* d_out, int out_size) {
    const float* x     = (const float*)d_in[0];
    const float* Wq    = (const float*)d_in[1];
    const float* bq    = (const float*)d_in[2];
    const float* Wk    = (const float*)d_in[3];
    const float* bk    = (const float*)d_in[4];
    const float* Wv    = (const float*)d_in[5];
    const float* bv    = (const float*)d_in[6];
    const float* Wo    = (const float*)d_in[7];
    const float* bo    = (const float*)d_in[8];
    const float* g1    = (const float*)d_in[9];
    const float* beta1 = (const float*)d_in[10];
    const float* g2    = (const float*)d_in[11];
    const float* beta2 = (const float*)d_in[12];
    const float* W1    = (const float*)d_in[13];
    const float* b1    = (const float*)d_in[14];
    const float* W2    = (const float*)d_in[15];
    const float* b2    = (const float*)d_in[16];
    float* out = (float*)d_out;

    float* px1;
    cudaGetSymbolAddress((void**)&px1, g_x1);
    __half *phh, *phl, *pyh, *pyl, *ph2h, *ph2l, *pfh, *pfl;
    cudaGetSymbolAddress((void**)&phh,  g_h_hi);  cudaGetSymbolAddress((void**)&phl,  g_h_lo);
    cudaGetSymbolAddress((void**)&pyh,  g_y_hi);  cudaGetSymbolAddress((void**)&pyl,  g_y_lo);
    cudaGetSymbolAddress((void**)&ph2h, g_h2_hi); cudaGetSymbolAddress((void**)&ph2l, g_h2_lo);
    cudaGetSymbolAddress((void**)&pfh,  g_f_hi);  cudaGetSymbolAddress((void**)&pfl,  g_f_lo);
    __half *wqkvh, *woh, *w1h, *w2h;
    float* pbqkv;
    cudaGetSymbolAddress((void**)&wqkvh, g_wqkv_hi);
    cudaGetSymbolAddress((void**)&pbqkv, g_bqkv);
    cudaGetSymbolAddress((void**)&woh, g_wo_hi);
    cudaGetSymbolAddress((void**)&w1h, g_w1_hi);
    cudaGetSymbolAddress((void**)&w2h, g_w2_hi);

    cudaFuncSetAttribute(gemm_mma<0, 4>, cudaFuncAttributeMaxDynamicSharedMemorySize, GEMM_SMEM);
    cudaFuncSetAttribute(gemm_mma<1, 0>, cudaFuncAttributeMaxDynamicSharedMemorySize, GEMM_SMEM);
    cudaFuncSetAttribute(gemm_mma<2, 1>, cudaFuncAttributeMaxDynamicSharedMemorySize, GEMM_SMEM);
    cudaFuncSetAttribute(attn_mma, cudaFuncAttributeMaxDynamicSharedMemorySize, ATTN_SMEM);

    dim3 t256(256);

    // ---- side stream: Wo/W1/W2 prep overlaps the LN1→QKV→attention chain ----
    cudaStream_t s2;
    cudaStreamCreateWithFlags(&s2, cudaStreamNonBlocking);
    cudaEvent_t eFork, eJoin;
    cudaEventCreateWithFlags(&eFork, cudaEventDisableTiming);
    cudaEventCreateWithFlags(&eJoin, cudaEventDisableTiming);
    cudaEventRecord(eFork, 0);
    cudaStreamWaitEvent(s2, eFork, 0);
    transpose_h<<<dim3(EMBED / 32, EMBED / 32), t256, 0, s2>>>(Wo, woh, EMBED, EMBED);
    transpose_h<<<dim3(FFDIM / 32, EMBED / 32), t256, 0, s2>>>(W1, w1h, EMBED, FFDIM);
    transpose_h<<<dim3(EMBED / 32, FFDIM / 32), t256, 0, s2>>>(W2, w2h, FFDIM, EMBED);
    cudaEventRecord(eJoin, s2);

    // ---- main stream: QKV prep + LN1 ----
    transpose_h<<<dim3(EMBED / 32, EMBED / 32), t256>>>(Wq, wqkvh, EMBED, EMBED);
    transpose_h<<<dim3(EMBED / 32, EMBED / 32), t256>>>(Wk, wqkvh + EMBED * EMBED, EMBED, EMBED);
    transpose_h<<<dim3(EMBED / 32, EMBED / 32), t256>>>(Wv, wqkvh + 2 * EMBED * EMBED, EMBED, EMBED);
    concat_bias<<<4, t256>>>(bq, bk, bv);
    ln_kernel<<<ROWS, t256>>>(x, g1, beta1, phh, phl);

    // fused QKV projection (N=3072) straight into attention layouts
    dim3 gqkv(3 * EMBED / 128, ROWS / 128);
    gemm_mma<0, 4><<<gqkv, t256, GEMM_SMEM>>>(phh, phl, wqkvh, pbqkv, nullptr,
                                              nullptr, nullptr, nullptr, ROWS, 3 * EMBED, EMBED);

    // tensor-core flash attention
    attn_mma<<<dim3(SEQ / 128, BATCH * HEADS), t256, ATTN_SMEM>>>();

    // join side-stream prep before Wo GEMM
    cudaStreamWaitEvent(0, eJoin, 0);

    // x1 = x + y @ Wo + bo
    dim3 g1024(EMBED / 128, ROWS / 128);
    gemm_mma<1, 0><<<g1024, t256, GEMM_SMEM>>>(pyh, pyl, woh, bo, x, px1, nullptr, nullptr, ROWS, EMBED, EMBED);
    // LN2
    ln_kernel<<<ROWS, t256>>>(px1, g2, beta2, ph2h, ph2l);
    // f = gelu(h2 @ W1 + b1)
    dim3 gff(FFDIM / 128, ROWS / 128);
    gemm_mma<2, 1><<<gff, t256, GEMM_SMEM>>>(ph2h, ph2l, w1h, b1, nullptr, nullptr, pfh, pfl, ROWS, FFDIM, EMBED);
    // out = x1 + f @ W2 + b2
    gemm_mma<1, 0><<<g1024, t256, GEMM_SMEM>>>(pfh, pfl, w2h, b2, px1, out, nullptr, nullptr, ROWS, EMBED, FFDIM);
}

// round 14
// speedup vs baseline: 14.5827x; 1.6381x over previous
#include <cuda_runtime.h>
#include <cuda_fp16.h>
#include <math.h>
#include <stdint.h>

#define EMBED 1024
#define HEADS 16
#define HEAD_DIM 64
#define BATCH 4
#define SEQ 2048
#define FFDIM 4096
#define ROWS (BATCH * SEQ) /* 8192 */

// ---------------- scratch (device globals; allocation-free) ----------------
__device__ float g_x1[ROWS * EMBED];
__device__ __half g_h[ROWS * EMBED];     // LN1 out
__device__ __half g_y[ROWS * EMBED];     // attention out
__device__ __half g_h2[ROWS * EMBED];    // LN2 out
__device__ __half g_f[ROWS * FFDIM];     // gelu(FF1)
// attention operands: Q,K [b,h,s,d]; V transposed [b,h,d,s]
__device__ __half g_att_q[ROWS * EMBED];
__device__ __half g_att_k[ROWS * EMBED];
__device__ __half g_att_v[ROWS * EMBED];
// pre-transposed weights [N,K] fp16
__device__ __half g_wqkv[3 * EMBED * EMBED];
__device__ float  g_bqkv[3 * EMBED];
__device__ __half g_wo[EMBED * EMBED];
__device__ __half g_w1[EMBED * FFDIM];
__device__ __half g_w2[FFDIM * EMBED];

// ---------------- helpers ----------------
__device__ __forceinline__ uint32_t smem_u32(const void* p) {
    uint32_t a;
    asm("{ .reg .u64 t; cvta.to.shared.u64 t, %1; cvt.u32.u64 %0, t; }" : "=r"(a) : "l"(p));
    return a;
}
__device__ __forceinline__ uint32_t pack2_h(float a, float b) {
    __half2 H; H.x = __float2half_rn(a); H.y = __float2half_rn(b);
    return *reinterpret_cast<uint32_t*>(&H);
}
__device__ __forceinline__ float gelu_exact(float x) {
    return 0.5f * x * (1.0f + erff(x * 0.70710678118654752f));
}

#define CP_ASYNC16(dst, src) \
    asm volatile("cp.async.cg.shared.global [%0], [%1], 16;" :: "r"(dst), "l"(src))
#define CP_COMMIT()  asm volatile("cp.async.commit_group;" ::: "memory")
#define CP_WAIT(n)   asm volatile("cp.async.wait_group %0;" :: "n"(n) : "memory")

__device__ __forceinline__ void mma_f16(float* c, const uint32_t* a, const uint32_t* b) {
    asm volatile(
        "mma.sync.aligned.m16n8k16.row.col.f32.f16.f16.f32 "
        "{%0,%1,%2,%3},{%4,%5,%6,%7},{%8,%9},{%0,%1,%2,%3};"
        : "+f"(c[0]), "+f"(c[1]), "+f"(c[2]), "+f"(c[3])
        : "r"(a[0]), "r"(a[1]), "r"(a[2]), "r"(a[3]), "r"(b[0]), "r"(b[1]));
}
#define LDSM_X4(r, addr) \
    asm volatile("ldmatrix.sync.aligned.m8n8.x4.shared.b16 {%0,%1,%2,%3}, [%4];" \
                 : "=r"((r)[0]), "=r"((r)[1]), "=r"((r)[2]), "=r"((r)[3]) : "r"(addr))

// ---------------- weight transpose (fp16) ----------------
__global__ void __launch_bounds__(256) transpose_h(const float* __restrict__ W,
                                                   __half* __restrict__ Th,
                                                   int K, int N) {
    __shared__ float t[32][33];
    int n0 = blockIdx.x * 32, k0 = blockIdx.y * 32;
    int tx = threadIdx.x & 31, ty = threadIdx.x >> 5;
#pragma unroll
    for (int i = 0; i < 4; i++) {
        int k = ty + i * 8;
        t[k][tx] = W[(size_t)(k0 + k) * N + n0 + tx];
    }
    __syncthreads();
#pragma unroll
    for (int i = 0; i < 4; i++) {
        int r = ty + i * 8;
        Th[(size_t)(n0 + r) * K + k0 + tx] = __float2half_rn(t[tx][r]);
    }
}

__global__ void __launch_bounds__(256) concat_bias(const float* __restrict__ bq,
                                                   const float* __restrict__ bk,
                                                   const float* __restrict__ bv) {
    int i = blockIdx.x * 256 + threadIdx.x;  // 0..1023
    g_bqkv[i]        = bq[i];
    g_bqkv[i + 1024] = bk[i];
    g_bqkv[i + 2048] = bv[i];
}

// ---------------- LayerNorm (fp16 output) ----------------
__global__ void __launch_bounds__(256) ln_kernel(const float* __restrict__ X,
                                                 const float* __restrict__ gam,
                                                 const float* __restrict__ bet,
                                                 __half* __restrict__ Y) {
    int row = blockIdx.x;
    int tid = threadIdx.x;
    const float* xr = X + (size_t)row * EMBED;
    float4 v = *reinterpret_cast<const float4*>(&xr[tid * 4]);
    float s  = v.x + v.y + v.z + v.w;
    float sq = v.x * v.x + v.y * v.y + v.z * v.z + v.w * v.w;
#pragma unroll
    for (int o = 16; o; o >>= 1) {
        s  += __shfl_xor_sync(0xffffffffu, s, o);
        sq += __shfl_xor_sync(0xffffffffu, sq, o);
    }
    __shared__ float ss[8], sqs[8];
    int w = tid >> 5;
    if ((tid & 31) == 0) { ss[w] = s; sqs[w] = sq; }
    __syncthreads();
    s = 0.f; sq = 0.f;
#pragma unroll
    for (int i = 0; i < 8; i++) { s += ss[i]; sq += sqs[i]; }
    float mu  = s * (1.0f / EMBED);
    float var = sq * (1.0f / EMBED) - mu * mu;
    float inv = rsqrtf(var + 1e-5f);
    float4 gv = *reinterpret_cast<const float4*>(&gam[tid * 4]);
    float4 bv = *reinterpret_cast<const float4*>(&bet[tid * 4]);
    float o0 = (v.x - mu) * inv * gv.x + bv.x;
    float o1 = (v.y - mu) * inv * gv.y + bv.y;
    float o2 = (v.z - mu) * inv * gv.z + bv.z;
    float o3 = (v.w - mu) * inv * gv.w + bv.w;
    size_t base = (size_t)row * EMBED + tid * 4;
    *reinterpret_cast<uint32_t*>(&Y[base])     = pack2_h(o0, o1);
    *reinterpret_cast<uint32_t*>(&Y[base + 2]) = pack2_h(o2, o3);
}

// ---------------- mma.sync GEMM (pure fp16 in, fp32 acc) ----------------
// C = A @ B^T : A [M,K] fp16, B weights [N,K] fp16.
// EPI: 0=bias  1=bias+residual  2=bias+GELU
// OUT: 0=fp32 row-major  1=fp16 row-major  4=fused QKV
// smem per stage: A(0) B(10240), row stride 80B. 2 stages.
static constexpr int GEMM_STAGE = 20480;
static constexpr int GEMM_SMEM  = 40960;

template <int EPI, int OUT>
__device__ __forceinline__ void epi_store(float v0, float v1, int r, int c,
                                          const float* R, float* C,
                                          __half* Ch, int N) {
    if (OUT == 4) {
        int kind = c >> 10;
        int c1   = c & 1023;
        if (kind < 2) {         // Q or K [b,h,s,d]
            size_t o2 = (((size_t)(r >> 11) * HEADS + (c1 >> 6)) * SEQ + (r & 2047)) * 64 + (c1 & 63);
            __half* dst = (kind == 0) ? g_att_q : g_att_k;
            *reinterpret_cast<uint32_t*>(&dst[o2]) = pack2_h(v0, v1);
        } else {                // V [b,h,d,s]
            size_t o3 = (((size_t)(r >> 11) * HEADS + (c1 >> 6)) * 64 + (c1 & 63)) * SEQ + (r & 2047);
            g_att_v[o3]       = __float2half_rn(v0);
            g_att_v[o3 + SEQ] = __float2half_rn(v1);
        }
        return;
    }
    size_t off = (size_t)r * N + c;
    if (EPI == 1) { float2 rr = *reinterpret_cast<const float2*>(&R[off]); v0 += rr.x; v1 += rr.y; }
    if (EPI == 2) { v0 = gelu_exact(v0); v1 = gelu_exact(v1); }
    if (OUT == 0) {
        float2 o; o.x = v0; o.y = v1;
        *reinterpret_cast<float2*>(&C[off]) = o;
    } else {
        *reinterpret_cast<uint32_t*>(&Ch[off]) = pack2_h(v0, v1);
    }
}

__device__ __forceinline__ void gemm_load_stage(
    uint32_t smem_base, int stage,
    const __half* A, const __half* B,
    int row0, int col0, int K, int k0, int tid) {
    uint32_t sb = smem_base + (uint32_t)stage * (uint32_t)GEMM_STAGE;
#pragma unroll
    for (int i = 0; i < 4; i++) {
        int idx = i * 256 + tid;       // 0..1023
        int arr = idx >> 9;            // 0 A, 1 B
        int pos = idx & 511;
        int r   = pos >> 2;
        int c8  = pos & 3;
        uint32_t dst = sb + (uint32_t)(arr * 10240 + r * 80 + c8 * 16);
        const __half* src = (arr == 0)
            ? &A[(size_t)(row0 + r) * K + k0 + c8 * 8]
            : &B[(size_t)(col0 + r) * K + k0 + c8 * 8];
        CP_ASYNC16(dst, src);
    }
}

template <int EPI, int OUT>
__global__ void __launch_bounds__(256, 2) gemm_mma(
    const __half* __restrict__ A, const __half* __restrict__ B,
    const float* __restrict__ bias, const float* __restrict__ R,
    float* __restrict__ C, __half* __restrict__ Ch,
    int M, int N, int K) {
    extern __shared__ char dsm[];
    const int tid  = threadIdx.x;
    const int lane = tid & 31;
    const int wid  = tid >> 5;
    const int wm   = wid & 1;
    const int wn   = wid >> 1;
    const int row0 = blockIdx.y * 128;
    const int col0 = blockIdx.x * 128;
    const uint32_t smem_base = smem_u32(dsm);

    float acc[4][4][4];
#pragma unroll
    for (int i = 0; i < 4; i++)
#pragma unroll
        for (int j = 0; j < 4; j++)
#pragma unroll
            for (int k = 0; k < 4; k++) acc[i][j][k] = 0.f;

    const int nchunks = K >> 5;
    gemm_load_stage(smem_base, 0, A, B, row0, col0, K, 0, tid);
    CP_COMMIT();

    const int tb      = lane >> 3;
    const int rb4_off = ((tb >> 1) << 3) + (lane & 7);
    const int kb4_off = (tb & 1) << 3;
    const int ra_off  = (lane & 7) + ((lane >> 3) & 1) * 8;

    for (int c = 0; c < nchunks; c++) {
        if (c + 1 < nchunks) {
            gemm_load_stage(smem_base, (c + 1) & 1, A, B, row0, col0, K, (c + 1) << 5, tid);
            CP_COMMIT();
            CP_WAIT(1);
        } else {
            CP_WAIT(0);
        }
        __syncthreads();

        uint32_t sb = smem_base + (uint32_t)(c & 1) * (uint32_t)GEMM_STAGE;
#pragma unroll
        for (int ks = 0; ks < 32; ks += 16) {
            uint32_t bh[4][2];
#pragma unroll
            for (int np = 0; np < 2; np++) {
                int rowb = wn * 32 + np * 16 + rb4_off;
                uint32_t ab = sb + 10240u + (uint32_t)(rowb * 80 + (ks + kb4_off) * 2);
                uint32_t r4[4];
                LDSM_X4(r4, ab);
                bh[np * 2][0] = r4[0]; bh[np * 2][1] = r4[1];
                bh[np * 2 + 1][0] = r4[2]; bh[np * 2 + 1][1] = r4[3];
            }
            int ka_off = ks + ((lane >> 4) << 3);
#pragma unroll
            for (int mt = 0; mt < 4; mt++) {
                int rowa = wm * 64 + mt * 16 + ra_off;
                uint32_t aa = sb + (uint32_t)(rowa * 80 + ka_off * 2);
                uint32_t ah[4];
                LDSM_X4(ah, aa);
#pragma unroll
                for (int nt = 0; nt < 4; nt++) {
                    mma_f16(acc[mt][nt], ah, bh[nt]);
                }
            }
        }
        __syncthreads();
    }

#pragma unroll
    for (int mt = 0; mt < 4; mt++) {
#pragma unroll
        for (int nt = 0; nt < 4; nt++) {
            int rg = row0 + wm * 64 + mt * 16 + (lane >> 2);
            int cg = col0 + wn * 32 + nt * 8 + (lane & 3) * 2;
            float2 b2 = *reinterpret_cast<const float2*>(&bias[cg]);
            epi_store<EPI, OUT>(acc[mt][nt][0] + b2.x, acc[mt][nt][1] + b2.y,
                                rg, cg, R, C, Ch, N);
            epi_store<EPI, OUT>(acc[mt][nt][2] + b2.x, acc[mt][nt][3] + b2.y,
                                rg + 8, cg, R, C, Ch, N);
        }
    }
}

// ---------------- tensor-core causal flash attention (pure fp16) ----------
// K smem [64 keys][64 d], Vt smem [64 d][64 keys], row stride 144B.
// Q staged in stage-0 region, extracted to regs before KV loads.
static constexpr int AT_VOFF  = 9216;
static constexpr int AT_STAGE = 18432;
static constexpr int ATTN_SMEM = 36864;
#define ATTN_SCALE 0.18033688011112042f  /* (1/8) * log2(e) */

__device__ __forceinline__ void attn_load_kv(uint32_t sb, int stage, int bh, int k0, int tid) {
    uint32_t st = sb + (uint32_t)stage * (uint32_t)AT_STAGE;
#pragma unroll
    for (int i = 0; i < 2; i++) {
        int idx = i * 256 + tid;      // 0..511
        int r   = idx >> 3;
        int c8  = idx & 7;
        uint32_t dst = st + (uint32_t)(r * 144 + c8 * 16);
        const __half* src = g_att_k + ((size_t)bh * SEQ + k0 + r) * 64 + c8 * 8;
        CP_ASYNC16(dst, src);
    }
#pragma unroll
    for (int i = 0; i < 2; i++) {
        int idx = i * 256 + tid;
        int r   = idx >> 3;
        int c8  = idx & 7;
        uint32_t dst = st + (uint32_t)(AT_VOFF + r * 144 + c8 * 16);
        const __half* src = g_att_v + ((size_t)bh * 64 + r) * SEQ + k0 + c8 * 8;
        CP_ASYNC16(dst, src);
    }
}

__global__ void __launch_bounds__(256, 2) attn_mma() {
    extern __shared__ char smbuf[];
    const int qt  = gridDim.x - 1 - blockIdx.x;   // descending work size first
    const int bh  = blockIdx.y;
    const int q0  = qt * 128;
    const int tid = threadIdx.x;
    const int lane = tid & 31;
    const int w    = tid >> 5;
    const uint32_t sb = smem_u32(smbuf);

    // ---- stage Q tile [128 x 64] into stage-0 region, extract frags
#pragma unroll
    for (int i = 0; i < 4; i++) {
        int idx = i * 256 + tid;      // 0..1023
        int r   = idx >> 3;
        int c8  = idx & 7;
        uint32_t dst = sb + (uint32_t)(r * 144 + c8 * 16);
        const __half* src = g_att_q + ((size_t)bh * SEQ + q0 + r) * 64 + c8 * 8;
        CP_ASYNC16(dst, src);
    }
    CP_COMMIT(); CP_WAIT(0); __syncthreads();

    uint32_t qh[4][4];
    {
        int ra = (lane & 7) + ((lane >> 3) & 1) * 8;
#pragma unroll
        for (int kc = 0; kc < 4; kc++) {
            int ka = kc * 16 + ((lane >> 4) << 3);
            uint32_t addr = sb + (uint32_t)((w * 16 + ra) * 144 + ka * 2);
            LDSM_X4(qh[kc], addr);
        }
    }
    __syncthreads();

    float m0 = -1e30f, m1 = -1e30f, l0 = 0.f, l1 = 0.f;
    float o[8][4];
#pragma unroll
    for (int nt = 0; nt < 8; nt++)
#pragma unroll
        for (int j = 0; j < 4; j++) o[nt][j] = 0.f;

    const int nkt = 2 * qt + 2;
    attn_load_kv(sb, 0, bh, 0, tid);
    CP_COMMIT();

    const int tb      = lane >> 3;
    const int rk4_off = ((tb >> 1) << 3) + (lane & 7);
    const int kk4_off = (tb & 1) << 3;
    const int wrow_max = q0 + w * 16 + 15;

    for (int kt = 0; kt < nkt; kt++) {
        if (kt + 1 < nkt) {
            attn_load_kv(sb, (kt + 1) & 1, bh, (kt + 1) * 64, tid);
            CP_COMMIT();
            CP_WAIT(1);
        } else {
            CP_WAIT(0);
        }
        __syncthreads();

        uint32_t st = sb + (uint32_t)(kt & 1) * (uint32_t)AT_STAGE;
        const int k0 = kt * 64;

        if (k0 <= wrow_max) {
            // ---- S = Q K^T
            float s[8][4];
#pragma unroll
            for (int nt = 0; nt < 8; nt++)
#pragma unroll
                for (int j = 0; j < 4; j++) s[nt][j] = 0.f;
#pragma unroll
            for (int kc = 0; kc < 4; kc++) {
#pragma unroll
                for (int np = 0; np < 4; np++) {
                    if (k0 + np * 16 > wrow_max) continue;  // fully masked -> exact skip
                    uint32_t kaddr = st + (uint32_t)((np * 16 + rk4_off) * 144 + (kc * 16 + kk4_off) * 2);
                    uint32_t kfh[4];
                    LDSM_X4(kfh, kaddr);
                    mma_f16(s[np * 2],     qh[kc], kfh);
                    mma_f16(s[np * 2 + 1], qh[kc], kfh + 2);
                }
            }

            // ---- scale (log2 domain) + causal mask
            const int r0 = q0 + w * 16 + (lane >> 2);
#pragma unroll
            for (int nt = 0; nt < 8; nt++)
#pragma unroll
                for (int j = 0; j < 4; j++) s[nt][j] *= ATTN_SCALE;
            if (k0 + 63 > q0 + w * 16) {
#pragma unroll
                for (int nt = 0; nt < 8; nt++)
#pragma unroll
                    for (int j = 0; j < 4; j++) {
                        int col = k0 + nt * 8 + (lane & 3) * 2 + (j & 1);
                        int row = r0 + ((j >> 1) << 3);
                        if (col > row) s[nt][j] = -1e30f;
                    }
            }

            // ---- online softmax in log2 domain
            float mx0 = -1e30f, mx1 = -1e30f;
#pragma unroll
            for (int nt = 0; nt < 8; nt++) {
                mx0 = fmaxf(mx0, fmaxf(s[nt][0], s[nt][1]));
                mx1 = fmaxf(mx1, fmaxf(s[nt][2], s[nt][3]));
            }
            mx0 = fmaxf(mx0, __shfl_xor_sync(0xffffffffu, mx0, 1));
            mx0 = fmaxf(mx0, __shfl_xor_sync(0xffffffffu, mx0, 2));
            mx1 = fmaxf(mx1, __shfl_xor_sync(0xffffffffu, mx1, 1));
            mx1 = fmaxf(mx1, __shfl_xor_sync(0xffffffffu, mx1, 2));
            float mn0 = fmaxf(m0, mx0), mn1 = fmaxf(m1, mx1);
            float a0 = exp2f(m0 - mn0), a1 = exp2f(m1 - mn1);
            float rl0 = 0.f, rl1 = 0.f;
#pragma unroll
            for (int nt = 0; nt < 8; nt++) {
                s[nt][0] = exp2f(s[nt][0] - mn0); rl0 += s[nt][0];
                s[nt][1] = exp2f(s[nt][1] - mn0); rl0 += s[nt][1];
                s[nt][2] = exp2f(s[nt][2] - mn1); rl1 += s[nt][2];
                s[nt][3] = exp2f(s[nt][3] - mn1); rl1 += s[nt][3];
            }
            rl0 += __shfl_xor_sync(0xffffffffu, rl0, 1);
            rl0 += __shfl_xor_sync(0xffffffffu, rl0, 2);
            rl1 += __shfl_xor_sync(0xffffffffu, rl1, 1);
            rl1 += __shfl_xor_sync(0xffffffffu, rl1, 2);
            l0 = l0 * a0 + rl0;
            l1 = l1 * a1 + rl1;
            m0 = mn0; m1 = mn1;
#pragma unroll
            for (int nt = 0; nt < 8; nt++) {
                o[nt][0] *= a0; o[nt][1] *= a0;
                o[nt][2] *= a1; o[nt][3] *= a1;
            }

            // ---- O += P V
#pragma unroll
            for (int kc = 0; kc < 4; kc++) {
                if (k0 + kc * 16 > wrow_max) continue;  // P block identically 0
                uint32_t pah[4];
                pah[0] = pack2_h(s[2 * kc][0],     s[2 * kc][1]);
                pah[1] = pack2_h(s[2 * kc][2],     s[2 * kc][3]);
                pah[2] = pack2_h(s[2 * kc + 1][0], s[2 * kc + 1][1]);
                pah[3] = pack2_h(s[2 * kc + 1][2], s[2 * kc + 1][3]);
#pragma unroll
                for (int np = 0; np < 4; np++) {
                    uint32_t vaddr = st + (uint32_t)(AT_VOFF + (np * 16 + rk4_off) * 144 + (kc * 16 + kk4_off) * 2);
                    uint32_t vfh[4];
                    LDSM_X4(vfh, vaddr);
                    mma_f16(o[np * 2],     pah, vfh);
                    mma_f16(o[np * 2 + 1], pah, vfh + 2);
                }
            }
        }
        __syncthreads();
    }

    // ---- write y (row-major [ROWS][EMBED] fp16)
    const float i0 = 1.f / l0, i1 = 1.f / l1;
    const int b = bh >> 4, h = bh & 15;
    const int rowg = b * SEQ + q0 + w * 16 + (lane >> 2);
#pragma unroll
    for (int nt = 0; nt < 8; nt++) {
        int colg = h * 64 + nt * 8 + (lane & 3) * 2;
        size_t off0 = (size_t)rowg * EMBED + colg;
        size_t off1 = off0 + (size_t)8 * EMBED;
        *reinterpret_cast<uint32_t*>(&g_y[off0]) = pack2_h(o[nt][0] * i0, o[nt][1] * i0);
        *reinterpret_cast<uint32_t*>(&g_y[off1]) = pack2_h(o[nt][2] * i1, o[nt][3] * i1);
    }
}

// ---------------- launch ---------------------------------------------------
extern "C" void kernel_launch(void* const* d_in, const int* in_sizes, int n_in,
                              void* d_out, int out_size) {
    const float* x     = (const float*)d_in[0];
    const float* Wq    = (const float*)d_in[1];
    const float* bq    = (const float*)d_in[2];
    const float* Wk    = (const float*)d_in[3];
    const float* bk    = (const float*)d_in[4];
    const float* Wv    = (const float*)d_in[5];
    const float* bv    = (const float*)d_in[6];
    const float* Wo    = (const float*)d_in[7];
    const float* bo    = (const float*)d_in[8];
    const float* g1    = (const float*)d_in[9];
    const float* beta1 = (const float*)d_in[10];
    const float* g2    = (const float*)d_in[11];
    const float* beta2 = (const float*)d_in[12];
    const float* W1    = (const float*)d_in[13];
    const float* b1    = (const float*)d_in[14];
    const float* W2    = (const float*)d_in[15];
    const float* b2    = (const float*)d_in[16];
    float* out = (float*)d_out;

    float* px1;
    cudaGetSymbolAddress((void**)&px1, g_x1);
    __half *ph, *py, *ph2, *pf;
    cudaGetSymbolAddress((void**)&ph,  g_h);
    cudaGetSymbolAddress((void**)&py,  g_y);
    cudaGetSymbolAddress((void**)&ph2, g_h2);
    cudaGetSymbolAddress((void**)&pf,  g_f);
    __half *wqkv, *pwo, *pw1, *pw2;
    float* pbqkv;
    cudaGetSymbolAddress((void**)&wqkv, g_wqkv);
    cudaGetSymbolAddress((void**)&pbqkv, g_bqkv);
    cudaGetSymbolAddress((void**)&pwo, g_wo);
    cudaGetSymbolAddress((void**)&pw1, g_w1);
    cudaGetSymbolAddress((void**)&pw2, g_w2);

    cudaFuncSetAttribute(gemm_mma<0, 4>, cudaFuncAttributeMaxDynamicSharedMemorySize, GEMM_SMEM);
    cudaFuncSetAttribute(gemm_mma<1, 0>, cudaFuncAttributeMaxDynamicSharedMemorySize, GEMM_SMEM);
    cudaFuncSetAttribute(gemm_mma<2, 1>, cudaFuncAttributeMaxDynamicSharedMemorySize, GEMM_SMEM);
    cudaFuncSetAttribute(attn_mma, cudaFuncAttributeMaxDynamicSharedMemorySize, ATTN_SMEM);

    dim3 t256(256);

    // ---- side stream: Wo/W1/W2 prep overlaps the LN1→QKV→attention chain ----
    cudaStream_t s2;
    cudaStreamCreateWithFlags(&s2, cudaStreamNonBlocking);
    cudaEvent_t eFork, eJoin;
    cudaEventCreateWithFlags(&eFork, cudaEventDisableTiming);
    cudaEventCreateWithFlags(&eJoin, cudaEventDisableTiming);
    cudaEventRecord(eFork, 0);
    cudaStreamWaitEvent(s2, eFork, 0);
    transpose_h<<<dim3(EMBED / 32, EMBED / 32), t256, 0, s2>>>(Wo, pwo, EMBED, EMBED);
    transpose_h<<<dim3(FFDIM / 32, EMBED / 32), t256, 0, s2>>>(W1, pw1, EMBED, FFDIM);
    transpose_h<<<dim3(EMBED / 32, FFDIM / 32), t256, 0, s2>>>(W2, pw2, FFDIM, EMBED);
    cudaEventRecord(eJoin, s2);

    // ---- main stream: QKV prep + LN1 ----
    transpose_h<<<dim3(EMBED / 32, EMBED / 32), t256>>>(Wq, wqkv, EMBED, EMBED);
    transpose_h<<<dim3(EMBED / 32, EMBED / 32), t256>>>(Wk, wqkv + EMBED * EMBED, EMBED, EMBED);
    transpose_h<<<dim3(EMBED / 32, EMBED / 32), t256>>>(Wv, wqkv + 2 * EMBED * EMBED, EMBED, EMBED);
    concat_bias<<<4, t256>>>(bq, bk, bv);
    ln_kernel<<<ROWS, t256>>>(x, g1, beta1, ph);

    // fused QKV projection (N=3072) straight into attention layouts
    dim3 gqkv(3 * EMBED / 128, ROWS / 128);
    gemm_mma<0, 4><<<gqkv, t256, GEMM_SMEM>>>(ph, wqkv, pbqkv, nullptr,
                                              nullptr, nullptr, ROWS, 3 * EMBED, EMBED);

    // tensor-core flash attention
    attn_mma<<<dim3(SEQ / 128, BATCH * HEADS), t256, ATTN_SMEM>>>();

    // join side-stream prep before Wo GEMM
    cudaStreamWaitEvent(0, eJoin, 0);

    // x1 = x + y @ Wo + bo
    dim3 g1024(EMBED / 128, ROWS / 128);
    gemm_mma<1, 0><<<g1024, t256, GEMM_SMEM>>>(py, pwo, bo, x, px1, nullptr, ROWS, EMBED, EMBED);
    // LN2
    ln_kernel<<<ROWS, t256>>>(px1, g2, beta2, ph2);
    // f = gelu(h2 @ W1 + b1)
    dim3 gff(FFDIM / 128, ROWS / 128);
    gemm_mma<2, 1><<<gff, t256, GEMM_SMEM>>>(ph2, pw1, b1, nullptr, nullptr, pf, ROWS, FFDIM, EMBED);
    // out = x1 + f @ W2 + b2
    gemm_mma<1, 0><<<g1024, t256, GEMM_SMEM>>>(pf, pw2, b2, px1, out, nullptr, ROWS, EMBED, FFDIM);
}

// round 15
// speedup vs baseline: 15.2636x; 1.0467x over previous
#include <cuda_runtime.h>
#include <cuda_fp16.h>
#include <math.h>
#include <stdint.h>

#define EMBED 1024
#define HEADS 16
#define HEAD_DIM 64
#define BATCH 4
#define SEQ 2048
#define FFDIM 4096
#define ROWS (BATCH * SEQ) /* 8192 */

// ---------------- scratch (device globals; allocation-free) ----------------
__device__ float g_x1[ROWS * EMBED];
__device__ __half g_h[ROWS * EMBED];     // LN1 out
__device__ __half g_y[ROWS * EMBED];     // attention out
__device__ __half g_h2[ROWS * EMBED];    // LN2 out
__device__ __half g_f[ROWS * FFDIM];     // gelu(FF1)
// attention operands: Q,K [b,h,s,d]; V transposed [b,h,d,s]
__device__ __half g_att_q[ROWS * EMBED];
__device__ __half g_att_k[ROWS * EMBED];
__device__ __half g_att_v[ROWS * EMBED];
// pre-transposed weights [N,K] fp16
__device__ __half g_wqkv[3 * EMBED * EMBED];
__device__ float  g_bqkv[3 * EMBED];
__device__ __half g_wo[EMBED * EMBED];
__device__ __half g_w1[EMBED * FFDIM];
__device__ __half g_w2[FFDIM * EMBED];

// ---------------- helpers ----------------
__device__ __forceinline__ uint32_t smem_u32(const void* p) {
    uint32_t a;
    asm("{ .reg .u64 t; cvta.to.shared.u64 t, %1; cvt.u32.u64 %0, t; }" : "=r"(a) : "l"(p));
    return a;
}
__device__ __forceinline__ uint32_t pack2_h(float a, float b) {
    __half2 H; H.x = __float2half_rn(a); H.y = __float2half_rn(b);
    return *reinterpret_cast<uint32_t*>(&H);
}
__device__ __forceinline__ float gelu_exact(float x) {
    return 0.5f * x * (1.0f + erff(x * 0.70710678118654752f));
}

#define CP_ASYNC16(dst, src) \
    asm volatile("cp.async.cg.shared.global [%0], [%1], 16;" :: "r"(dst), "l"(src))
#define CP_COMMIT()  asm volatile("cp.async.commit_group;" ::: "memory")
#define CP_WAIT(n)   asm volatile("cp.async.wait_group %0;" :: "n"(n) : "memory")

__device__ __forceinline__ void mma_f16(float* c, const uint32_t* a, const uint32_t* b) {
    asm volatile(
        "mma.sync.aligned.m16n8k16.row.col.f32.f16.f16.f32 "
        "{%0,%1,%2,%3},{%4,%5,%6,%7},{%8,%9},{%0,%1,%2,%3};"
        : "+f"(c[0]), "+f"(c[1]), "+f"(c[2]), "+f"(c[3])
        : "r"(a[0]), "r"(a[1]), "r"(a[2]), "r"(a[3]), "r"(b[0]), "r"(b[1]));
}
#define LDSM_X4(r, addr) \
    asm volatile("ldmatrix.sync.aligned.m8n8.x4.shared.b16 {%0,%1,%2,%3}, [%4];" \
                 : "=r"((r)[0]), "=r"((r)[1]), "=r"((r)[2]), "=r"((r)[3]) : "r"(addr))

// ---------------- weight transpose (fp16) ----------------
__global__ void __launch_bounds__(256) transpose_h(const float* __restrict__ W,
                                                   __half* __restrict__ Th,
                                                   int K, int N) {
    __shared__ float t[32][33];
    int n0 = blockIdx.x * 32, k0 = blockIdx.y * 32;
    int tx = threadIdx.x & 31, ty = threadIdx.x >> 5;
#pragma unroll
    for (int i = 0; i < 4; i++) {
        int k = ty + i * 8;
        t[k][tx] = W[(size_t)(k0 + k) * N + n0 + tx];
    }
    __syncthreads();
#pragma unroll
    for (int i = 0; i < 4; i++) {
        int r = ty + i * 8;
        Th[(size_t)(n0 + r) * K + k0 + tx] = __float2half_rn(t[tx][r]);
    }
}

// merged QKV transpose: z selects Wq/Wk/Wv -> g_wqkv slab
__global__ void __launch_bounds__(256) transpose_qkv(const float* __restrict__ Wq,
                                                     const float* __restrict__ Wk,
                                                     const float* __restrict__ Wv) {
    __shared__ float t[32][33];
    const float* W = (blockIdx.z == 0) ? Wq : (blockIdx.z == 1) ? Wk : Wv;
    __half* Th = g_wqkv + (size_t)blockIdx.z * EMBED * EMBED;
    int n0 = blockIdx.x * 32, k0 = blockIdx.y * 32;
    int tx = threadIdx.x & 31, ty = threadIdx.x >> 5;
#pragma unroll
    for (int i = 0; i < 4; i++) {
        int k = ty + i * 8;
        t[k][tx] = W[(size_t)(k0 + k) * EMBED + n0 + tx];
    }
    __syncthreads();
#pragma unroll
    for (int i = 0; i < 4; i++) {
        int r = ty + i * 8;
        Th[(size_t)(n0 + r) * EMBED + k0 + tx] = __float2half_rn(t[tx][r]);
    }
}

__global__ void __launch_bounds__(256) concat_bias(const float* __restrict__ bq,
                                                   const float* __restrict__ bk,
                                                   const float* __restrict__ bv) {
    int i = blockIdx.x * 256 + threadIdx.x;  // 0..1023
    g_bqkv[i]        = bq[i];
    g_bqkv[i + 1024] = bk[i];
    g_bqkv[i + 2048] = bv[i];
}

// ---------------- LayerNorm (fp16 output) ----------------
__global__ void __launch_bounds__(256) ln_kernel(const float* __restrict__ X,
                                                 const float* __restrict__ gam,
                                                 const float* __restrict__ bet,
                                                 __half* __restrict__ Y) {
    int row = blockIdx.x;
    int tid = threadIdx.x;
    const float* xr = X + (size_t)row * EMBED;
    float4 v = *reinterpret_cast<const float4*>(&xr[tid * 4]);
    float s  = v.x + v.y + v.z + v.w;
    float sq = v.x * v.x + v.y * v.y + v.z * v.z + v.w * v.w;
#pragma unroll
    for (int o = 16; o; o >>= 1) {
        s  += __shfl_xor_sync(0xffffffffu, s, o);
        sq += __shfl_xor_sync(0xffffffffu, sq, o);
    }
    __shared__ float ss[8], sqs[8];
    int w = tid >> 5;
    if ((tid & 31) == 0) { ss[w] = s; sqs[w] = sq; }
    __syncthreads();
    s = 0.f; sq = 0.f;
#pragma unroll
    for (int i = 0; i < 8; i++) { s += ss[i]; sq += sqs[i]; }
    float mu  = s * (1.0f / EMBED);
    float var = sq * (1.0f / EMBED) - mu * mu;
    float inv = rsqrtf(var + 1e-5f);
    float4 gv = *reinterpret_cast<const float4*>(&gam[tid * 4]);
    float4 bv = *reinterpret_cast<const float4*>(&bet[tid * 4]);
    float o0 = (v.x - mu) * inv * gv.x + bv.x;
    float o1 = (v.y - mu) * inv * gv.y + bv.y;
    float o2 = (v.z - mu) * inv * gv.z + bv.z;
    float o3 = (v.w - mu) * inv * gv.w + bv.w;
    size_t base = (size_t)row * EMBED + tid * 4;
    *reinterpret_cast<uint32_t*>(&Y[base])     = pack2_h(o0, o1);
    *reinterpret_cast<uint32_t*>(&Y[base + 2]) = pack2_h(o2, o3);
}

// ---------------- mma.sync GEMM (pure fp16 in, fp32 acc, 3-stage) ---------
// C = A @ B^T : A [M,K] fp16, B weights [N,K] fp16.
// EPI: 0=bias  1=bias+residual  2=bias+GELU
// OUT: 0=fp32 row-major  1=fp16 row-major  4=fused QKV
// smem per stage: A(0) B(10240), row stride 80B. 3 stages.
static constexpr int GEMM_STAGE = 20480;
static constexpr int GEMM_SMEM  = 61440;

template <int EPI, int OUT>
__device__ __forceinline__ void epi_store(float v0, float v1, int r, int c,
                                          const float* R, float* C,
                                          __half* Ch, int N) {
    if (OUT == 4) {
        int kind = c >> 10;
        int c1   = c & 1023;
        if (kind < 2) {         // Q or K [b,h,s,d]
            size_t o2 = (((size_t)(r >> 11) * HEADS + (c1 >> 6)) * SEQ + (r & 2047)) * 64 + (c1 & 63);
            __half* dst = (kind == 0) ? g_att_q : g_att_k;
            *reinterpret_cast<uint32_t*>(&dst[o2]) = pack2_h(v0, v1);
        } else {                // V [b,h,d,s]
            size_t o3 = (((size_t)(r >> 11) * HEADS + (c1 >> 6)) * 64 + (c1 & 63)) * SEQ + (r & 2047);
            g_att_v[o3]       = __float2half_rn(v0);
            g_att_v[o3 + SEQ] = __float2half_rn(v1);
        }
        return;
    }
    size_t off = (size_t)r * N + c;
    if (EPI == 1) { float2 rr = *reinterpret_cast<const float2*>(&R[off]); v0 += rr.x; v1 += rr.y; }
    if (EPI == 2) { v0 = gelu_exact(v0); v1 = gelu_exact(v1); }
    if (OUT == 0) {
        float2 o; o.x = v0; o.y = v1;
        *reinterpret_cast<float2*>(&C[off]) = o;
    } else {
        *reinterpret_cast<uint32_t*>(&Ch[off]) = pack2_h(v0, v1);
    }
}

__device__ __forceinline__ void gemm_load_stage(
    uint32_t smem_base, int stage,
    const __half* A, const __half* B,
    int row0, int col0, int K, int k0, int tid) {
    uint32_t sb = smem_base + (uint32_t)stage * (uint32_t)GEMM_STAGE;
#pragma unroll
    for (int i = 0; i < 4; i++) {
        int idx = i * 256 + tid;       // 0..1023
        int arr = idx >> 9;            // 0 A, 1 B
        int pos = idx & 511;
        int r   = pos >> 2;
        int c8  = pos & 3;
        uint32_t dst = sb + (uint32_t)(arr * 10240 + r * 80 + c8 * 16);
        const __half* src = (arr == 0)
            ? &A[(size_t)(row0 + r) * K + k0 + c8 * 8]
            : &B[(size_t)(col0 + r) * K + k0 + c8 * 8];
        CP_ASYNC16(dst, src);
    }
}

template <int EPI, int OUT>
__global__ void __launch_bounds__(256, 2) gemm_mma(
    const __half* __restrict__ A, const __half* __restrict__ B,
    const float* __restrict__ bias, const float* __restrict__ R,
    float* __restrict__ C, __half* __restrict__ Ch,
    int M, int N, int K) {
    extern __shared__ char dsm[];
    const int tid  = threadIdx.x;
    const int lane = tid & 31;
    const int wid  = tid >> 5;
    const int wm   = wid & 1;
    const int wn   = wid >> 1;
    const int row0 = blockIdx.y * 128;
    const int col0 = blockIdx.x * 128;
    const uint32_t smem_base = smem_u32(dsm);

    float acc[4][4][4];
#pragma unroll
    for (int i = 0; i < 4; i++)
#pragma unroll
        for (int j = 0; j < 4; j++)
#pragma unroll
            for (int k = 0; k < 4; k++) acc[i][j][k] = 0.f;

    const int nchunks = K >> 5;
    gemm_load_stage(smem_base, 0, A, B, row0, col0, K, 0, tid);
    CP_COMMIT();
    gemm_load_stage(smem_base, 1, A, B, row0, col0, K, 32, tid);
    CP_COMMIT();

    const int tb      = lane >> 3;
    const int rb4_off = ((tb >> 1) << 3) + (lane & 7);
    const int kb4_off = (tb & 1) << 3;
    const int ra_off  = (lane & 7) + ((lane >> 3) & 1) * 8;

    int sidx = 0;
    for (int c = 0; c < nchunks; c++) {
        CP_WAIT(1);
        __syncthreads();
        // issue loads for chunk c+2 into stage (sidx+2)%3 (its readers are all
        // past this barrier), then compute chunk c — maximal overlap, 1 BAR/chunk.
        if (c + 2 < nchunks) {
            int sn = sidx + 2; if (sn >= 3) sn -= 3;
            gemm_load_stage(smem_base, sn, A, B, row0, col0, K, (c + 2) << 5, tid);
        }
        CP_COMMIT();

        uint32_t sb = smem_base + (uint32_t)sidx * (uint32_t)GEMM_STAGE;
#pragma unroll
        for (int ks = 0; ks < 32; ks += 16) {
            uint32_t bh[4][2];
#pragma unroll
            for (int np = 0; np < 2; np++) {
                int rowb = wn * 32 + np * 16 + rb4_off;
                uint32_t ab = sb + 10240u + (uint32_t)(rowb * 80 + (ks + kb4_off) * 2);
                uint32_t r4[4];
                LDSM_X4(r4, ab);
                bh[np * 2][0] = r4[0]; bh[np * 2][1] = r4[1];
                bh[np * 2 + 1][0] = r4[2]; bh[np * 2 + 1][1] = r4[3];
            }
            int ka_off = ks + ((lane >> 4) << 3);
#pragma unroll
            for (int mt = 0; mt < 4; mt++) {
                int rowa = wm * 64 + mt * 16 + ra_off;
                uint32_t aa = sb + (uint32_t)(rowa * 80 + ka_off * 2);
                uint32_t ah[4];
                LDSM_X4(ah, aa);
#pragma unroll
                for (int nt = 0; nt < 4; nt++) {
                    mma_f16(acc[mt][nt], ah, bh[nt]);
                }
            }
        }
        sidx++; if (sidx == 3) sidx = 0;
    }

#pragma unroll
    for (int mt = 0; mt < 4; mt++) {
#pragma unroll
        for (int nt = 0; nt < 4; nt++) {
            int rg = row0 + wm * 64 + mt * 16 + (lane >> 2);
            int cg = col0 + wn * 32 + nt * 8 + (lane & 3) * 2;
            float2 b2 = *reinterpret_cast<const float2*>(&bias[cg]);
            epi_store<EPI, OUT>(acc[mt][nt][0] + b2.x, acc[mt][nt][1] + b2.y,
                                rg, cg, R, C, Ch, N);
            epi_store<EPI, OUT>(acc[mt][nt][2] + b2.x, acc[mt][nt][3] + b2.y,
                                rg + 8, cg, R, C, Ch, N);
        }
    }
}

// ---------------- tensor-core causal flash attention (fp16, 3-stage) ------
// K smem [64 keys][64 d], Vt smem [64 d][64 keys], row stride 144B.
// Q staged in stage-2 region (full 18432B), extracted to regs before mainloop.
static constexpr int AT_VOFF  = 9216;
static constexpr int AT_STAGE = 18432;
static constexpr int ATTN_SMEM = 55296;  // 3 stages
#define ATTN_SCALE 0.18033688011112042f  /* (1/8) * log2(e) */

__device__ __forceinline__ void attn_load_kv(uint32_t sb, int stage, int bh, int k0, int tid) {
    uint32_t st = sb + (uint32_t)stage * (uint32_t)AT_STAGE;
#pragma unroll
    for (int i = 0; i < 2; i++) {
        int idx = i * 256 + tid;      // 0..511
        int r   = idx >> 3;
        int c8  = idx & 7;
        uint32_t dst = st + (uint32_t)(r * 144 + c8 * 16);
        const __half* src = g_att_k + ((size_t)bh * SEQ + k0 + r) * 64 + c8 * 8;
        CP_ASYNC16(dst, src);
    }
#pragma unroll
    for (int i = 0; i < 2; i++) {
        int idx = i * 256 + tid;
        int r   = idx >> 3;
        int c8  = idx & 7;
        uint32_t dst = st + (uint32_t)(AT_VOFF + r * 144 + c8 * 16);
        const __half* src = g_att_v + ((size_t)bh * 64 + r) * SEQ + k0 + c8 * 8;
        CP_ASYNC16(dst, src);
    }
}

__global__ void __launch_bounds__(256, 2) attn_mma() {
    extern __shared__ char smbuf[];
    const int qt  = gridDim.x - 1 - blockIdx.x;   // descending work size first
    const int bh  = blockIdx.y;
    const int q0  = qt * 128;
    const int tid = threadIdx.x;
    const int lane = tid & 31;
    const int w    = tid >> 5;
    const uint32_t sb = smem_u32(smbuf);

    // ---- stage Q tile [128 x 64] into stage-2 region
#pragma unroll
    for (int i = 0; i < 4; i++) {
        int idx = i * 256 + tid;      // 0..1023
        int r   = idx >> 3;
        int c8  = idx & 7;
        uint32_t dst = sb + 2u * AT_STAGE + (uint32_t)(r * 144 + c8 * 16);
        const __half* src = g_att_q + ((size_t)bh * SEQ + q0 + r) * 64 + c8 * 8;
        CP_ASYNC16(dst, src);
    }
    CP_COMMIT();
    // ---- prologue KV loads: stages 0, 1
    attn_load_kv(sb, 0, bh, 0, tid);
    CP_COMMIT();
    const int nkt = 2 * qt + 2;
    attn_load_kv(sb, 1, bh, 64, tid);
    CP_COMMIT();

    CP_WAIT(2);                 // Q complete (KV0/KV1 may still be in flight)
    __syncthreads();
    uint32_t qh[4][4];
    {
        int ra = (lane & 7) + ((lane >> 3) & 1) * 8;
#pragma unroll
        for (int kc = 0; kc < 4; kc++) {
            int ka = kc * 16 + ((lane >> 4) << 3);
            uint32_t addr = sb + 2u * AT_STAGE + (uint32_t)((w * 16 + ra) * 144 + ka * 2);
            LDSM_X4(qh[kc], addr);
        }
    }

    float m0 = -1e30f, m1 = -1e30f, l0 = 0.f, l1 = 0.f;
    float o[8][4];
#pragma unroll
    for (int nt = 0; nt < 8; nt++)
#pragma unroll
        for (int j = 0; j < 4; j++) o[nt][j] = 0.f;

    const int tb      = lane >> 3;
    const int rk4_off = ((tb >> 1) << 3) + (lane & 7);
    const int kk4_off = (tb & 1) << 3;
    const int wrow_max = q0 + w * 16 + 15;

    int sidx = 0;
    for (int kt = 0; kt < nkt; kt++) {
        CP_WAIT(1);
        __syncthreads();
        // issue KV loads for kt+2 into stage (sidx+2)%3 (readers are past barrier;
        // stage 2 on kt=0 reuses the Q buffer — Q already extracted to registers)
        if (kt + 2 < nkt) {
            int sn = sidx + 2; if (sn >= 3) sn -= 3;
            attn_load_kv(sb, sn, bh, (kt + 2) * 64, tid);
        }
        CP_COMMIT();

        uint32_t st = sb + (uint32_t)sidx * (uint32_t)AT_STAGE;
        const int k0 = kt * 64;

        if (k0 <= wrow_max) {
            // ---- S = Q K^T
            float s[8][4];
#pragma unroll
            for (int nt = 0; nt < 8; nt++)
#pragma unroll
                for (int j = 0; j < 4; j++) s[nt][j] = 0.f;
#pragma unroll
            for (int kc = 0; kc < 4; kc++) {
#pragma unroll
                for (int np = 0; np < 4; np++) {
                    if (k0 + np * 16 > wrow_max) continue;  // fully masked -> exact skip
                    uint32_t kaddr = st + (uint32_t)((np * 16 + rk4_off) * 144 + (kc * 16 + kk4_off) * 2);
                    uint32_t kfh[4];
                    LDSM_X4(kfh, kaddr);
                    mma_f16(s[np * 2],     qh[kc], kfh);
                    mma_f16(s[np * 2 + 1], qh[kc], kfh + 2);
                }
            }

            // ---- scale (log2 domain) + causal mask
            const int r0 = q0 + w * 16 + (lane >> 2);
#pragma unroll
            for (int nt = 0; nt < 8; nt++)
#pragma unroll
                for (int j = 0; j < 4; j++) s[nt][j] *= ATTN_SCALE;
            if (k0 + 63 > q0 + w * 16) {
#pragma unroll
                for (int nt = 0; nt < 8; nt++)
#pragma unroll
                    for (int j = 0; j < 4; j++) {
                        int col = k0 + nt * 8 + (lane & 3) * 2 + (j & 1);
                        int row = r0 + ((j >> 1) << 3);
                        if (col > row) s[nt][j] = -1e30f;
                    }
            }

            // ---- online softmax in log2 domain
            float mx0 = -1e30f, mx1 = -1e30f;
#pragma unroll
            for (int nt = 0; nt < 8; nt++) {
                mx0 = fmaxf(mx0, fmaxf(s[nt][0], s[nt][1]));
                mx1 = fmaxf(mx1, fmaxf(s[nt][2], s[nt][3]));
            }
            mx0 = fmaxf(mx0, __shfl_xor_sync(0xffffffffu, mx0, 1));
            mx0 = fmaxf(mx0, __shfl_xor_sync(0xffffffffu, mx0, 2));
            mx1 = fmaxf(mx1, __shfl_xor_sync(0xffffffffu, mx1, 1));
            mx1 = fmaxf(mx1, __shfl_xor_sync(0xffffffffu, mx1, 2));
            float mn0 = fmaxf(m0, mx0), mn1 = fmaxf(m1, mx1);
            float a0 = exp2f(m0 - mn0), a1 = exp2f(m1 - mn1);
            float rl0 = 0.f, rl1 = 0.f;
#pragma unroll
            for (int nt = 0; nt < 8; nt++) {
                s[nt][0] = exp2f(s[nt][0] - mn0); rl0 += s[nt][0];
                s[nt][1] = exp2f(s[nt][1] - mn0); rl0 += s[nt][1];
                s[nt][2] = exp2f(s[nt][2] - mn1); rl1 += s[nt][2];
                s[nt][3] = exp2f(s[nt][3] - mn1); rl1 += s[nt][3];
            }
            rl0 += __shfl_xor_sync(0xffffffffu, rl0, 1);
            rl0 += __shfl_xor_sync(0xffffffffu, rl0, 2);
            rl1 += __shfl_xor_sync(0xffffffffu, rl1, 1);
            rl1 += __shfl_xor_sync(0xffffffffu, rl1, 2);
            l0 = l0 * a0 + rl0;
            l1 = l1 * a1 + rl1;
            m0 = mn0; m1 = mn1;
#pragma unroll
            for (int nt = 0; nt < 8; nt++) {
                o[nt][0] *= a0; o[nt][1] *= a0;
                o[nt][2] *= a1; o[nt][3] *= a1;
            }

            // ---- O += P V
#pragma unroll
            for (int kc = 0; kc < 4; kc++) {
                if (k0 + kc * 16 > wrow_max) continue;  // P block identically 0
                uint32_t pah[4];
                pah[0] = pack2_h(s[2 * kc][0],     s[2 * kc][1]);
                pah[1] = pack2_h(s[2 * kc][2],     s[2 * kc][3]);
                pah[2] = pack2_h(s[2 * kc + 1][0], s[2 * kc + 1][1]);
                pah[3] = pack2_h(s[2 * kc + 1][2], s[2 * kc + 1][3]);
#pragma unroll
                for (int np = 0; np < 4; np++) {
                    uint32_t vaddr = st + (uint32_t)(AT_VOFF + (np * 16 + rk4_off) * 144 + (kc * 16 + kk4_off) * 2);
                    uint32_t vfh[4];
                    LDSM_X4(vfh, vaddr);
                    mma_f16(o[np * 2],     pah, vfh);
                    mma_f16(o[np * 2 + 1], pah, vfh + 2);
                }
            }
        }
        sidx++; if (sidx == 3) sidx = 0;
    }

    // ---- write y (row-major [ROWS][EMBED] fp16)
    const float i0 = 1.f / l0, i1 = 1.f / l1;
    const int b = bh >> 4, h = bh & 15;
    const int rowg = b * SEQ + q0 + w * 16 + (lane >> 2);
#pragma unroll
    for (int nt = 0; nt < 8; nt++) {
        int colg = h * 64 + nt * 8 + (lane & 3) * 2;
        size_t off0 = (size_t)rowg * EMBED + colg;
        size_t off1 = off0 + (size_t)8 * EMBED;
        *reinterpret_cast<uint32_t*>(&g_y[off0]) = pack2_h(o[nt][0] * i0, o[nt][1] * i0);
        *reinterpret_cast<uint32_t*>(&g_y[off1]) = pack2_h(o[nt][2] * i1, o[nt][3] * i1);
    }
}

// ---------------- launch ---------------------------------------------------
extern "C" void kernel_launch(void* const* d_in, const int* in_sizes, int n_in,
                              void* d_out, int out_size) {
    const float* x     = (const float*)d_in[0];
    const float* Wq    = (const float*)d_in[1];
    const float* bq    = (const float*)d_in[2];
    const float* Wk    = (const float*)d_in[3];
    const float* bk    = (const float*)d_in[4];
    const float* Wv    = (const float*)d_in[5];
    const float* bv    = (const float*)d_in[6];
    const float* Wo    = (const float*)d_in[7];
    const float* bo    = (const float*)d_in[8];
    const float* g1    = (const float*)d_in[9];
    const float* beta1 = (const float*)d_in[10];
    const float* g2    = (const float*)d_in[11];
    const float* beta2 = (const float*)d_in[12];
    const float* W1    = (const float*)d_in[13];
    const float* b1    = (const float*)d_in[14];
    const float* W2    = (const float*)d_in[15];
    const float* b2    = (const float*)d_in[16];
    float* out = (float*)d_out;

    float* px1;
    cudaGetSymbolAddress((void**)&px1, g_x1);
    __half *ph, *py, *ph2, *pf;
    cudaGetSymbolAddress((void**)&ph,  g_h);
    cudaGetSymbolAddress((void**)&py,  g_y);
    cudaGetSymbolAddress((void**)&ph2, g_h2);
    cudaGetSymbolAddress((void**)&pf,  g_f);
    __half *wqkv, *pwo, *pw1, *pw2;
    float* pbqkv;
    cudaGetSymbolAddress((void**)&wqkv, g_wqkv);
    cudaGetSymbolAddress((void**)&pbqkv, g_bqkv);
    cudaGetSymbolAddress((void**)&pwo, g_wo);
    cudaGetSymbolAddress((void**)&pw1, g_w1);
    cudaGetSymbolAddress((void**)&pw2, g_w2);

    cudaFuncSetAttribute(gemm_mma<0, 4>, cudaFuncAttributeMaxDynamicSharedMemorySize, GEMM_SMEM);
    cudaFuncSetAttribute(gemm_mma<1, 0>, cudaFuncAttributeMaxDynamicSharedMemorySize, GEMM_SMEM);
    cudaFuncSetAttribute(gemm_mma<2, 1>, cudaFuncAttributeMaxDynamicSharedMemorySize, GEMM_SMEM);
    cudaFuncSetAttribute(attn_mma, cudaFuncAttributeMaxDynamicSharedMemorySize, ATTN_SMEM);

    dim3 t256(256);

    // ---- side stream: Wo/W1/W2 prep overlaps the LN1→QKV→attention chain ----
    cudaStream_t s2;
    cudaStreamCreateWithFlags(&s2, cudaStreamNonBlocking);
    cudaEvent_t eFork, eJoin;
    cudaEventCreateWithFlags(&eFork, cudaEventDisableTiming);
    cudaEventCreateWithFlags(&eJoin, cudaEventDisableTiming);
    cudaEventRecord(eFork, 0);
    cudaStreamWaitEvent(s2, eFork, 0);
    transpose_h<<<dim3(EMBED / 32, EMBED / 32), t256, 0, s2>>>(Wo, pwo, EMBED, EMBED);
    transpose_h<<<dim3(FFDIM / 32, EMBED / 32), t256, 0, s2>>>(W1, pw1, EMBED, FFDIM);
    transpose_h<<<dim3(EMBED / 32, FFDIM / 32), t256, 0, s2>>>(W2, pw2, FFDIM, EMBED);
    cudaEventRecord(eJoin, s2);

    // ---- main stream: QKV prep + LN1 ----
    transpose_qkv<<<dim3(EMBED / 32, EMBED / 32, 3), t256>>>(Wq, Wk, Wv);
    concat_bias<<<4, t256>>>(bq, bk, bv);
    ln_kernel<<<ROWS, t256>>>(x, g1, beta1, ph);

    // fused QKV projection (N=3072) straight into attention layouts
    dim3 gqkv(3 * EMBED / 128, ROWS / 128);
    gemm_mma<0, 4><<<gqkv, t256, GEMM_SMEM>>>(ph, wqkv, pbqkv, nullptr,
                                              nullptr, nullptr, ROWS, 3 * EMBED, EMBED);

    // tensor-core flash attention
    attn_mma<<<dim3(SEQ / 128, BATCH * HEADS), t256, ATTN_SMEM>>>();

    // join side-stream prep before Wo GEMM
    cudaStreamWaitEvent(0, eJoin, 0);

    // x1 = x + y @ Wo + bo
    dim3 g1024(EMBED / 128, ROWS / 128);
    gemm_mma<1, 0><<<g1024, t256, GEMM_SMEM>>>(py, pwo, bo, x, px1, nullptr, ROWS, EMBED, EMBED);
    // LN2
    ln_kernel<<<ROWS, t256>>>(px1, g2, beta2, ph2);
    // f = gelu(h2 @ W1 + b1)
    dim3 gff(FFDIM / 128, ROWS / 128);
    gemm_mma<2, 1><<<gff, t256, GEMM_SMEM>>>(ph2, pw1, b1, nullptr, nullptr, pf, ROWS, FFDIM, EMBED);
    // out = x1 + f @ W2 + b2
    gemm_mma<1, 0><<<g1024, t256, GEMM_SMEM>>>(pf, pw2, b2, px1, out, nullptr, ROWS, EMBED, FFDIM);
}